// round 9
// baseline (speedup 1.0000x reference)
#include <cuda_runtime.h>
#include <cuda_bf16.h>
#include <math.h>
#include <stdint.h>

// Problem constants (T=2048, H=2048, HQ=32, HKV=2, D=64, G=16, M<=32)
#define TMAX 2048
#define MMAX 32

// ---------------- scratch (no allocation allowed) ----------------
__device__ float    g_q[TMAX * 2048];      // [n, HQ*D]
__device__ float    g_kvg[TMAX * 352];     // [n, k(128) | v(128) | gate(96)]
__device__ float    g_ck[MMAX * 2 * 64];
__device__ float    g_cv[MMAX * 2 * 64];
__device__ float    g_comp[TMAX * 2048];
__device__ unsigned g_sel[TMAX * 2];

// bf16 split operands
__device__ __nv_bfloat16 g_xh[2048 * 2048], g_xl[2048 * 2048];
__device__ __nv_bfloat16 g_fh[2048 * 2048], g_fl[2048 * 2048];
__device__ __nv_bfloat16 g_wqt_h[2048 * 2048], g_wqt_l[2048 * 2048];   // Wq^T [N,K]
__device__ __nv_bfloat16 g_wot_h[2048 * 2048], g_wot_l[2048 * 2048];   // Wo^T
__device__ __nv_bfloat16 g_wkvgt_h[352 * 2048], g_wkvgt_l[352 * 2048]; // [Wk|Wv|Wg]^T
// attention K / V^T split-bf16
__device__ __nv_bfloat16 g_kbh[TMAX * 128], g_kbl[TMAX * 128];          // [n][h][64]
__device__ __nv_bfloat16 g_vth[2 * 64 * TMAX], g_vtl[2 * 64 * TMAX];    // [h][d][n]

__device__ __forceinline__ uint32_t smem_u32(const void* p) {
    uint32_t a;
    asm("{ .reg .u64 t; cvta.to.shared.u64 t, %1; cvt.u32.u64 %0, t; }" : "=r"(a) : "l"(p));
    return a;
}

// ---------------- packed f32x2 helpers ----------------
__device__ __forceinline__ unsigned long long pk2(float x, float y) {
    unsigned long long r;
    asm("mov.b64 %0, {%1,%2};" : "=l"(r) : "f"(x), "f"(y));
    return r;
}
__device__ __forceinline__ unsigned long long pk2f2(float2 v) { return pk2(v.x, v.y); }
__device__ __forceinline__ void upk2(unsigned long long r, float& x, float& y) {
    asm("mov.b64 {%0,%1}, %2;" : "=f"(x), "=f"(y) : "l"(r));
}
__device__ __forceinline__ unsigned long long fma2(unsigned long long a,
                                                   unsigned long long b,
                                                   unsigned long long c) {
    unsigned long long d;
    asm("fma.rn.f32x2 %0, %1, %2, %3;" : "=l"(d) : "l"(a), "l"(b), "l"(c));
    return d;
}

// ---------------- mma helpers ----------------
#define LDSM4(r, addr) \
    asm volatile("ldmatrix.sync.aligned.m8n8.x4.shared.b16 {%0,%1,%2,%3}, [%4];" \
                 : "=r"((r)[0]), "=r"((r)[1]), "=r"((r)[2]), "=r"((r)[3]) : "r"(addr))

__device__ __forceinline__ void hmma(float* c, const uint32_t* a, const uint32_t* b) {
    asm volatile("mma.sync.aligned.m16n8k16.row.col.f32.bf16.bf16.f32 "
                 "{%0,%1,%2,%3},{%4,%5,%6,%7},{%8,%9},{%0,%1,%2,%3};"
                 : "+f"(c[0]), "+f"(c[1]), "+f"(c[2]), "+f"(c[3])
                 : "r"(a[0]), "r"(a[1]), "r"(a[2]), "r"(a[3]), "r"(b[0]), "r"(b[1]));
}

__device__ __forceinline__ void bsplit(float v, unsigned short& hi, unsigned short& lo) {
    __nv_bfloat16 h = __float2bfloat16(v);
    __nv_bfloat16 l = __float2bfloat16(v - __bfloat162float(h));
    hi = *(unsigned short*)&h; lo = *(unsigned short*)&l;
}

// ================= prep kernels =================
__global__ void split_fp32(const float4* __restrict__ A,
                           __nv_bfloat16* __restrict__ Ah,
                           __nv_bfloat16* __restrict__ Al, int total4)
{
    int i = blockIdx.x * 256 + threadIdx.x;
    if (i < total4) {
        float4 v = A[i];
        ushort4 hh, ll;
        bsplit(v.x, hh.x, ll.x); bsplit(v.y, hh.y, ll.y);
        bsplit(v.z, hh.z, ll.z); bsplit(v.w, hh.w, ll.w);
        *(ushort4*)(Ah + 4 * (size_t)i) = hh;
        *(ushort4*)(Al + 4 * (size_t)i) = ll;
    }
}

__global__ void transpose_split(const float* __restrict__ W,
                                __nv_bfloat16* __restrict__ Th,
                                __nv_bfloat16* __restrict__ Tl, int K, int N)
{
    __shared__ float t[32][33];
    const int k0 = blockIdx.y * 32, n0 = blockIdx.x * 32;
    const int tx = threadIdx.x, ty = threadIdx.y;  // 32 x 8
    for (int i = ty; i < 32; i += 8) {
        int k = k0 + i, n = n0 + tx;
        t[i][tx] = (n < N && k < K) ? W[(size_t)k * N + n] : 0.f;
    }
    __syncthreads();
    for (int i = ty; i < 32; i += 8) {
        int n = n0 + i, k = k0 + tx;
        if (n < N && k < K) {
            unsigned short hi, lo;
            bsplit(t[tx][i], hi, lo);
            *(unsigned short*)(Th + (size_t)n * K + k) = hi;
            *(unsigned short*)(Tl + (size_t)n * K + k) = lo;
        }
    }
}

// K split + V transpose-split. grid (n/32, 2, 2), block (32,8)
__global__ void kv_prep(int ntok)
{
    __shared__ float t[32][33];
    const int n0 = blockIdx.x * 32, h = blockIdx.y, dh = blockIdx.z * 32;
    const int tx = threadIdx.x, ty = threadIdx.y;
    for (int i = ty; i < 32; i += 8) {
        const int n = n0 + i, d = dh + tx;
        float kv = g_kvg[n * 352 + h * 64 + d];
        unsigned short hi, lo;
        bsplit(kv, hi, lo);
        *(unsigned short*)(g_kbh + n * 128 + h * 64 + d) = hi;
        *(unsigned short*)(g_kbl + n * 128 + h * 64 + d) = lo;
        t[i][tx] = g_kvg[n * 352 + h * 64 + 128 + d];
    }
    __syncthreads();
    for (int i = ty; i < 32; i += 8) {
        const int d = dh + i, n = n0 + tx;
        unsigned short hi, lo;
        bsplit(t[tx][i], hi, lo);
        *(unsigned short*)(g_vth + (h * 64 + d) * TMAX + n) = hi;
        *(unsigned short*)(g_vtl + (h * 64 + d) * TMAX + n) = lo;
    }
}

// ================= split-bf16 GEMM on mma.sync, 128x256 tile, 512 threads =================
// A mats: 128 rows x 112B, B mats: 256 rows x 112B. Stage = 86016B, 2 stages = 172032B.
#define A_MAT 14336
#define B_MAT 28672
#define STAGE_BYTES 86016
#define SMEM_GEMM (2 * STAGE_BYTES)

__global__ void __launch_bounds__(512) mma_gemm(
    const __nv_bfloat16* __restrict__ Ah, const __nv_bfloat16* __restrict__ Al,
    const __nv_bfloat16* __restrict__ Bth, const __nv_bfloat16* __restrict__ Btl,
    float* __restrict__ C, int M, int N, int K)
{
    extern __shared__ char smem[];
    const uint32_t sb = smem_u32(smem);
    const int tid = threadIdx.x;
    const int lane = tid & 31, wid = tid >> 5;
    const int warp_m = wid & 1, warp_n = wid >> 1;   // 2 x 8 warps
    const int row0 = blockIdx.y * 128, col0 = blockIdx.x * 256;
    const int nchunk = K >> 5;

    float acc[4][4][4];
#pragma unroll
    for (int a = 0; a < 4; a++)
#pragma unroll
        for (int b = 0; b < 4; b++)
#pragma unroll
            for (int c = 0; c < 4; c++) acc[a][b][c] = 0.f;

    const int mt = lane >> 3, rin = lane & 7;
    const uint32_t a_off = (uint32_t)((warp_m * 64 + (mt & 1) * 8 + rin) * 112 + ((mt >> 1) * 8) * 2);
    const uint32_t b_off = (uint32_t)((warp_n * 32 + ((mt >= 2) ? 8 : 0) + rin) * 112 + ((mt & 1) * 8) * 2);

    auto load_chunk = [&](int c) {
        const int k0 = c * 32;
        const uint32_t st = sb + (uint32_t)(c & 1) * STAGE_BYTES;
        // 3072 16B-vectors: A-hi [0,512), A-lo [512,1024), B-hi [1024,2048), B-lo [2048,3072)
#pragma unroll
        for (int i = 0; i < 6; i++) {
            int v = tid + i * 512;
            uint32_t dst;
            const __nv_bfloat16* srcp;
            int sz = 16;
            if (v < 1024) {
                int mat = v >> 9, r = (v >> 2) & 127, c16 = v & 3;
                dst = st + mat * A_MAT + r * 112 + c16 * 16;
                srcp = (mat ? Al : Ah) + (size_t)(row0 + r) * K + k0 + c16 * 8;
            } else {
                int vb = v - 1024;
                int mat = vb >> 10, r = (vb >> 2) & 255, c16 = vb & 3;
                dst = st + 2 * A_MAT + mat * B_MAT + r * 112 + c16 * 16;
                int n = col0 + r;
                int nn = (n < N) ? n : 0;
                if (n >= N) sz = 0;
                srcp = (mat ? Btl : Bth) + (size_t)nn * K + k0 + c16 * 8;
            }
            asm volatile("cp.async.cg.shared.global [%0], [%1], 16, %2;"
                         :: "r"(dst), "l"(srcp), "r"(sz));
        }
        asm volatile("cp.async.commit_group;" ::: "memory");
    };

    load_chunk(0);

    for (int c = 0; c < nchunk; c++) {
        if (c + 1 < nchunk) {
            load_chunk(c + 1);
            asm volatile("cp.async.wait_group 1;" ::: "memory");
        } else {
            asm volatile("cp.async.wait_group 0;" ::: "memory");
        }
        __syncthreads();

        const uint32_t st = sb + (uint32_t)(c & 1) * STAGE_BYTES;
#pragma unroll
        for (int ks = 0; ks < 2; ks++) {
            uint32_t ah[4][4], al[4][4];
#pragma unroll
            for (int mi = 0; mi < 4; mi++) {
                uint32_t addr = st + a_off + mi * (16 * 112) + ks * 32;
                LDSM4(ah[mi], addr);
                LDSM4(al[mi], addr + A_MAT);
            }
#pragma unroll
            for (int b2 = 0; b2 < 2; b2++) {
                uint32_t bh[4], bl[4];
                uint32_t baddr = st + 2 * A_MAT + b_off + b2 * (16 * 112) + ks * 32;
                LDSM4(bh, baddr);
                LDSM4(bl, baddr + B_MAT);
#pragma unroll
                for (int p = 0; p < 3; p++) {
#pragma unroll
                    for (int mi = 0; mi < 4; mi++) {
#pragma unroll
                        for (int hf = 0; hf < 2; hf++) {
                            const int nt = b2 * 2 + hf;
                            const uint32_t* A_ = (p == 2) ? al[mi] : ah[mi];
                            const uint32_t* B_ = (p == 1) ? bl : bh;
                            hmma(acc[mi][nt], A_, B_ + hf * 2);
                        }
                    }
                }
            }
        }
        __syncthreads();
    }

    const int g = lane >> 2, c2 = lane & 3;
#pragma unroll
    for (int mi = 0; mi < 4; mi++) {
        const int r = row0 + warp_m * 64 + mi * 16 + g;
#pragma unroll
        for (int nt = 0; nt < 4; nt++) {
            const int col = col0 + warp_n * 32 + nt * 8 + c2 * 2;
            if (col < N) {
                *(float2*)(C + (size_t)r * N + col)       = make_float2(acc[mi][nt][0], acc[mi][nt][1]);
                *(float2*)(C + (size_t)(r + 8) * N + col) = make_float2(acc[mi][nt][2], acc[mi][nt][3]);
            }
        }
    }
}

// ---------------- compressed tokens ----------------
__global__ void compress_kernel(const float* __restrict__ wck,
                                const float* __restrict__ wcv,
                                const float* __restrict__ pe)
{
    const int m = blockIdx.x, h = blockIdx.y, d = threadIdx.x;  // 64 threads
    float a = 0.f, b = 0.f;
    for (int t = 0; t < 64; t++) {
        const float wk = wck[h * 64 + t];
        const float wv = wcv[h * 64 + t];
        const int row = m * 64 + t;
        a = fmaf(g_kvg[row * 352 + h * 64 + d] + pe[(h * 64 + t) * 64 + d], wk, a);
        b = fmaf(g_kvg[row * 352 + 128 + h * 64 + d], wv, b);
    }
    g_ck[(m * 2 + h) * 64 + d] = a;
    g_cv[(m * 2 + h) * 64 + d] = b;
}

// ---------------- compressed attention + top-k, 4 tokens per CTA ----------------
__global__ void __launch_bounds__(512) comp_attn_kernel(int ntok)
{
    const int n0 = blockIdx.x * 4, h = blockIdx.y;
    const int tid = threadIdx.x;
    const int tq = tid >> 7, ltid = tid & 127;
    const int M = ntok >> 6;
    __shared__ float  sq[4096];
    __shared__ float2 ckp[32 * 33];
    __shared__ float  scv[MMAX * 64];
    __shared__ float  lg[4 * 512];
    __shared__ float  ssum[4 * 32];

    for (int i = tid; i < 4096; i += 512) {
        int q = i >> 10;
        sq[i] = g_q[(n0 + q) * 2048 + h * 1024 + (i & 1023)] * 0.125f;
    }
    for (int i = tid; i < M * 32; i += 512) {
        int m = i >> 5, d2 = i & 31;
        ckp[d2 * 33 + m] = *(const float2*)&g_ck[(m * 2 + h) * 64 + 2 * d2];
    }
    for (int i = tid; i < M * 64; i += 512)
        scv[i] = g_cv[((i >> 6) * 2 + h) * 64 + (i & 63)];
    __syncthreads();

    const int n = n0 + tq;
    const int mvis = (n >= 63) ? (((n - 63) >> 6) + 1) : 0;

#pragma unroll
    for (int i = 0; i < 4; i++) {
        int e = ltid + i * 128;
        int g = e >> 5, m = e & 31;
        unsigned long long acc = 0ull;
#pragma unroll
        for (int d2 = 0; d2 < 32; d2++) {
            unsigned long long qp = pk2f2(*(const float2*)&sq[tq * 1024 + g * 64 + 2 * d2]);
            acc = fma2(qp, pk2f2(ckp[d2 * 33 + m]), acc);
        }
        float x, y; upk2(acc, x, y);
        lg[tq * 512 + g * 32 + m] = x + y;
    }
    __syncthreads();

    if (ltid < 16) {
        float* row = lg + tq * 512 + ltid * 32;
        if (mvis == 0) {
            for (int m = 0; m < M; m++) row[m] = 0.f;
        } else {
            float mx = -INFINITY;
            for (int m = 0; m < mvis; m++) mx = fmaxf(mx, row[m]);
            float s = 0.f;
            for (int m = 0; m < mvis; m++) {
                float p = __expf(row[m] - mx);
                row[m] = p; s += p;
            }
            const float inv = 1.f / s;
            for (int m = 0; m < mvis; m++) row[m] *= inv;
            for (int m = mvis; m < M; m++) row[m] = 0.f;
        }
    }
    __syncthreads();

#pragma unroll
    for (int i = 0; i < 4; i++) {
        int e2 = ltid + i * 128;
        int g = e2 >> 5, d2 = e2 & 31;
        unsigned long long acc = 0ull;
        for (int m = 0; m < mvis; m++) {
            float p = lg[tq * 512 + g * 32 + m];
            acc = fma2(pk2(p, p), pk2f2(*(const float2*)&scv[m * 64 + 2 * d2]), acc);
        }
        float x, y; upk2(acc, x, y);
        *(float2*)&g_comp[n * 2048 + h * 1024 + g * 64 + 2 * d2] = make_float2(x, y);
    }

    if (ltid < 32) {
        float s = 0.f;
        if (ltid < M)
            for (int g = 0; g < 16; g++) s += lg[tq * 512 + g * 32 + ltid];
        ssum[tq * 32 + ltid] = s;
    }
    __syncthreads();

    if (ltid == 0) {
        const int qblk = n >> 6;
        unsigned sel = 0;
        if (qblk + 1 <= 16) {
            sel = (1u << (qblk + 1)) - 1u;
        } else {
            float sc[32];
            for (int m = 0; m < 32; m++) {
                if (m > qblk)                                  sc[m] = -INFINITY;
                else if (m == 0 || m == qblk || m == qblk - 1) sc[m] = INFINITY;
                else                                           sc[m] = ssum[tq * 32 + m];
            }
            for (int t = 0; t < 16; t++) {
                int best = 0; float bv = -INFINITY;
                for (int m = 0; m < 32; m++) {
                    if ((sel >> m) & 1u) continue;
                    if (sc[m] > bv) { bv = sc[m]; best = m; }
                }
                sel |= 1u << best;
            }
        }
        g_sel[n * 2 + h] = sel;
    }
}

// ---------------- main attention on tensor cores ----------------
#define BST 72          // bf16 smem row stride (elements) = 144 bytes
#define SQH 0
#define SQL 9216
#define SKH 18432
#define SKL 27648
#define SVTH 36864
#define SVTL 46080
#define PSH 55296
#define PSL 64512
#define PWH 73728
#define PWL 82944
#define LG_OFF 92160    // float [64][66]
#define PM_OFF 109056   // float [512]
#define HMM_OFF 111104  // float [2][64]
#define HLL_OFF 111616
#define HRR_OFF 112128
#define ATTN_SMEM 112640

__global__ void __launch_bounds__(256, 2) main_attn_kernel(int ntok)
{
    extern __shared__ char dsm[];
    const uint32_t sb = smem_u32(dsm);
    float* lg  = (float*)(dsm + LG_OFF);
    float* pm  = (float*)(dsm + PM_OFF);
    float* hmm = (float*)(dsm + HMM_OFF);
    float* hll = (float*)(dsm + HLL_OFF);
    float* hrr = (float*)(dsm + HRR_OFF);

    const int n0 = blockIdx.x * 4, h = blockIdx.y;
    const int tid = threadIdx.x;
    const int lane = tid & 31, wid = tid >> 5;
    const int warp_m = wid & 1, warp_n = wid >> 1;
    const int g = lane >> 2, cq = lane & 3;

    for (int i = tid; i < 4096; i += 256) {
        int r = i >> 6, d = i & 63;
        float v = g_q[(n0 + (r >> 4)) * 2048 + h * 1024 + (r & 15) * 64 + d] * 0.125f;
        unsigned short hi, lo;
        bsplit(v, hi, lo);
        *(unsigned short*)(dsm + SQH + (r * BST + d) * 2) = hi;
        *(unsigned short*)(dsm + SQL + (r * BST + d) * 2) = lo;
    }
    if (tid < 128) { hmm[tid] = -INFINITY; hll[tid] = 0.f; }

    const unsigned sel0 = g_sel[n0 * 2 + h],       sel1 = g_sel[(n0 + 1) * 2 + h],
                   sel2 = g_sel[(n0 + 2) * 2 + h], sel3 = g_sel[(n0 + 3) * 2 + h];
    const unsigned selU = sel0 | sel1 | sel2 | sel3;
    const int qblk = n0 >> 6;

    const int mt = lane >> 3, rin = lane & 7;
    const uint32_t a_base = (uint32_t)(((mt & 1) * 8 + rin) * 144 + ((mt >> 1) * 8) * 2);
    const uint32_t b_base = (uint32_t)((warp_n * 16 + ((mt >= 2) ? 8 : 0) + rin) * 144 + ((mt & 1) * 8) * 2);

    float acc_s[2][2][4] = {}, acc_w[2][2][4] = {};

    __syncthreads();

    for (int c = 0; c <= qblk; c++) {
        const int base = n0 - c * 64;
        const bool anyw = (base - 512) <= 63;
        if (!((selU >> c) & 1u) && !anyw) continue;

        for (int i = tid; i < 2048; i += 256) {
            int mat = i >> 9, idx = i & 511;
            int row = idx >> 3, c16 = idx & 7;
            const __nv_bfloat16* src;
            if (mat == 0)      src = g_kbh + (size_t)(c * 64 + row) * 128 + h * 64 + c16 * 8;
            else if (mat == 1) src = g_kbl + (size_t)(c * 64 + row) * 128 + h * 64 + c16 * 8;
            else if (mat == 2) src = g_vth + (size_t)(h * 64 + row) * TMAX + c * 64 + c16 * 8;
            else               src = g_vtl + (size_t)(h * 64 + row) * TMAX + c * 64 + c16 * 8;
            *(uint4*)(dsm + SKH + mat * 9216 + row * 144 + c16 * 16) = *(const uint4*)src;
        }
        __syncthreads();

        // ---- S = Q K^T via HMMA (3-product) ----
        {
            float acc[2][2][4] = {};
#pragma unroll
            for (int ks = 0; ks < 4; ks++) {
                uint32_t kh[4], kl[4];
                LDSM4(kh, sb + SKH + b_base + ks * 32);
                LDSM4(kl, sb + SKL + b_base + ks * 32);
#pragma unroll
                for (int mi = 0; mi < 2; mi++) {
                    uint32_t qh[4], ql[4];
                    const uint32_t ao = (uint32_t)((warp_m * 32 + mi * 16) * 144) + a_base + ks * 32;
                    LDSM4(qh, sb + SQH + ao);
                    LDSM4(ql, sb + SQL + ao);
#pragma unroll
                    for (int hf = 0; hf < 2; hf++) {
                        hmma(acc[mi][hf], qh, kh + hf * 2);
                        hmma(acc[mi][hf], qh, kl + hf * 2);
                        hmma(acc[mi][hf], ql, kh + hf * 2);
                    }
                }
            }
#pragma unroll
            for (int mi = 0; mi < 2; mi++) {
                const int r0 = warp_m * 32 + mi * 16 + g;
#pragma unroll
                for (int hf = 0; hf < 2; hf++) {
                    const int col = warp_n * 16 + hf * 8 + cq * 2;
                    *(float2*)&lg[r0 * 66 + col]       = make_float2(acc[mi][hf][0], acc[mi][hf][1]);
                    *(float2*)&lg[(r0 + 8) * 66 + col] = make_float2(acc[mi][hf][2], acc[mi][hf][3]);
                }
            }
        }
        __syncthreads();

        // ---- segmented max ----
        {
            const int r = tid >> 2, seg = tid & 3;
            const int q = r >> 4;
            const int jn = min(63, base + q);
            const unsigned selq = (q == 0) ? sel0 : (q == 1) ? sel1 : (q == 2) ? sel2 : sel3;
            const int jw0 = base + q - 512;
            float ms = -INFINITY;
            if ((selq >> c) & 1u) {
                const int hi2 = min(seg * 16 + 15, jn);
                for (int j = seg * 16; j <= hi2; j++) ms = fmaxf(ms, lg[r * 66 + j]);
            }
            pm[tid] = ms;
            float mw = -INFINITY;
            if (jw0 <= 63) {
                const int lo2 = max(seg * 16, jw0);
                const int hi2 = min(seg * 16 + 15, jn);
                for (int j = lo2; j <= hi2; j++) mw = fmaxf(mw, lg[r * 66 + j]);
            }
            pm[256 + tid] = mw;
        }
        __syncthreads();
        if (tid < 128) {
            const int br = tid >> 6, r = tid & 63;
            const float* p = pm + br * 256 + r * 4;
            const float cm = fmaxf(fmaxf(p[0], p[1]), fmaxf(p[2], p[3]));
            const float om = hmm[br * 64 + r];
            const float nm = fmaxf(om, cm);
            hmm[br * 64 + r] = nm;
            hrr[br * 64 + r] = (cm == -INFINITY) ? 1.f : __expf(om - nm);
        }
        __syncthreads();

        // ---- exp + partial sums + split-bf16 P store ----
        {
            const int r = tid >> 2, seg = tid & 3;
            const int q = r >> 4;
            const unsigned selq = (q == 0) ? sel0 : (q == 1) ? sel1 : (q == 2) ? sel2 : sel3;
            const int jn = base + q;
            const int jw0 = base + q - 512;
            const bool sact = (selq >> c) & 1u;
            const float ms = hmm[r], mw = hmm[64 + r];
            float ss = 0.f, sw = 0.f;
            unsigned short eh[16], el[16], wh[16], wl[16];
#pragma unroll
            for (int jj = 0; jj < 16; jj++) {
                const int j = seg * 16 + jj;
                const float l = lg[r * 66 + j];
                const bool jc = (j <= jn);
                float es = (jc && sact)        ? __expf(l - ms) : 0.f;
                float ew = (jc && j >= jw0)    ? __expf(l - mw) : 0.f;
                ss += es; sw += ew;
                bsplit(es, eh[jj], el[jj]);
                bsplit(ew, wh[jj], wl[jj]);
            }
            pm[tid] = ss; pm[256 + tid] = sw;
            const uint32_t po = (uint32_t)((r * BST + seg * 16) * 2);
#pragma unroll
            for (int v4 = 0; v4 < 4; v4++) {
                *(ushort4*)(dsm + PSH + po + v4 * 8) = make_ushort4(eh[v4*4], eh[v4*4+1], eh[v4*4+2], eh[v4*4+3]);
                *(ushort4*)(dsm + PSL + po + v4 * 8) = make_ushort4(el[v4*4], el[v4*4+1], el[v4*4+2], el[v4*4+3]);
                *(ushort4*)(dsm + PWH + po + v4 * 8) = make_ushort4(wh[v4*4], wh[v4*4+1], wh[v4*4+2], wh[v4*4+3]);
                *(ushort4*)(dsm + PWL + po + v4 * 8) = make_ushort4(wl[v4*4], wl[v4*4+1], wl[v4*4+2], wl[v4*4+3]);
            }
        }
        __syncthreads();
        if (tid < 128) {
            const int br = tid >> 6, r = tid & 63;
            const float* p = pm + br * 256 + r * 4;
            hll[br * 64 + r] = hll[br * 64 + r] * hrr[br * 64 + r]
                             + (p[0] + p[1]) + (p[2] + p[3]);
        }

        // ---- PV via HMMA with flash rescale ----
#pragma unroll
        for (int mi = 0; mi < 2; mi++) {
            const int rb = warp_m * 32 + mi * 16 + g;
            const float rs0 = hrr[rb], rs1 = hrr[rb + 8];
            const float rw0 = hrr[64 + rb], rw1 = hrr[64 + rb + 8];
#pragma unroll
            for (int hf = 0; hf < 2; hf++) {
                acc_s[mi][hf][0] *= rs0; acc_s[mi][hf][1] *= rs0;
                acc_s[mi][hf][2] *= rs1; acc_s[mi][hf][3] *= rs1;
                acc_w[mi][hf][0] *= rw0; acc_w[mi][hf][1] *= rw0;
                acc_w[mi][hf][2] *= rw1; acc_w[mi][hf][3] *= rw1;
            }
        }
#pragma unroll
        for (int ks = 0; ks < 4; ks++) {
            uint32_t vh[4], vl[4];
            LDSM4(vh, sb + SVTH + b_base + ks * 32);
            LDSM4(vl, sb + SVTL + b_base + ks * 32);
#pragma unroll
            for (int mi = 0; mi < 2; mi++) {
                const uint32_t ao = (uint32_t)((warp_m * 32 + mi * 16) * 144) + a_base + ks * 32;
                uint32_t ph[4], pl[4];
                LDSM4(ph, sb + PSH + ao);
                LDSM4(pl, sb + PSL + ao);
#pragma unroll
                for (int hf = 0; hf < 2; hf++) {
                    hmma(acc_s[mi][hf], ph, vh + hf * 2);
                    hmma(acc_s[mi][hf], ph, vl + hf * 2);
                    hmma(acc_s[mi][hf], pl, vh + hf * 2);
                }
                LDSM4(ph, sb + PWH + ao);
                LDSM4(pl, sb + PWL + ao);
#pragma unroll
                for (int hf = 0; hf < 2; hf++) {
                    hmma(acc_w[mi][hf], ph, vh + hf * 2);
                    hmma(acc_w[mi][hf], ph, vl + hf * 2);
                    hmma(acc_w[mi][hf], pl, vh + hf * 2);
                }
            }
        }
        __syncthreads();
    }

    // ---- gated fusion epilogue ----
#pragma unroll
    for (int mi = 0; mi < 2; mi++) {
#pragma unroll
        for (int half = 0; half < 2; half++) {
            const int r = warp_m * 32 + mi * 16 + g + half * 8;
            const int nq = n0 + (r >> 4);
            const int head = r & 15;
            const int hq = h * 16 + head;
            const float gl0 = g_kvg[nq * 352 + 256 + hq * 3 + 0];
            const float gl1 = g_kvg[nq * 352 + 256 + hq * 3 + 1];
            const float gl2 = g_kvg[nq * 352 + 256 + hq * 3 + 2];
            const float g0 = 1.f / (1.f + __expf(-gl0));
            const float g1 = 1.f / (1.f + __expf(-gl1));
            const float g2 = 1.f / (1.f + __expf(-gl2));
            const float inv_s = 1.f / hll[r];
            const float inv_w = 1.f / hll[64 + r];
#pragma unroll
            for (int hf = 0; hf < 2; hf++) {
                const int col = warp_n * 16 + hf * 8 + cq * 2;
                const int oi = nq * 2048 + h * 1024 + head * 64 + col;
                const float2 cmp = *(const float2*)&g_comp[oi];
                const float o0 = g0 * cmp.x + g1 * acc_s[mi][hf][half * 2]     * inv_s
                                            + g2 * acc_w[mi][hf][half * 2]     * inv_w;
                const float o1 = g0 * cmp.y + g1 * acc_s[mi][hf][half * 2 + 1] * inv_s
                                            + g2 * acc_w[mi][hf][half * 2 + 1] * inv_w;
                ushort2 hh, ll;
                bsplit(o0, hh.x, ll.x);
                bsplit(o1, hh.y, ll.y);
                *(ushort2*)(g_fh + oi) = hh;
                *(ushort2*)(g_fl + oi) = ll;
            }
        }
    }
}

// ---------------- launch ----------------
extern "C" void kernel_launch(void* const* d_in, const int* in_sizes, int n_in,
                              void* d_out, int out_size)
{
    const float* x   = (const float*)d_in[0];
    const float* Wq  = (const float*)d_in[2];
    const float* Wk  = (const float*)d_in[3];
    const float* Wv  = (const float*)d_in[4];
    const float* Wo  = (const float*)d_in[5];
    const float* Wg  = (const float*)d_in[6];
    const float* wck = (const float*)d_in[7];
    const float* wcv = (const float*)d_in[8];
    const float* pe  = (const float*)d_in[9];
    float* out = (float*)d_out;

    const int ntok = in_sizes[0] / 2048;     // T = 2048
    const int M = ntok / 64;

    float *q, *kvg;
    cudaGetSymbolAddress((void**)&q,   g_q);
    cudaGetSymbolAddress((void**)&kvg, g_kvg);

    __nv_bfloat16 *xh, *xl, *fh, *fl, *wqh, *wql, *woh, *wol, *wkvgh, *wkvgl;
    cudaGetSymbolAddress((void**)&xh, g_xh);     cudaGetSymbolAddress((void**)&xl, g_xl);
    cudaGetSymbolAddress((void**)&fh, g_fh);     cudaGetSymbolAddress((void**)&fl, g_fl);
    cudaGetSymbolAddress((void**)&wqh, g_wqt_h); cudaGetSymbolAddress((void**)&wql, g_wqt_l);
    cudaGetSymbolAddress((void**)&woh, g_wot_h); cudaGetSymbolAddress((void**)&wol, g_wot_l);
    cudaGetSymbolAddress((void**)&wkvgh, g_wkvgt_h);
    cudaGetSymbolAddress((void**)&wkvgl, g_wkvgt_l);

    cudaFuncSetAttribute(mma_gemm, cudaFuncAttributeMaxDynamicSharedMemorySize, SMEM_GEMM);
    cudaFuncSetAttribute(main_attn_kernel, cudaFuncAttributeMaxDynamicSharedMemorySize, ATTN_SMEM);

    const int tot = ntok * 2048;
    dim3 tb(32, 8);

    split_fp32<<<(tot / 4 + 255) / 256, 256>>>((const float4*)x, xh, xl, tot / 4);                // 0
    transpose_split<<<dim3(64, 64), tb>>>(Wq, wqh, wql, 2048, 2048);                              // 1
    transpose_split<<<dim3(4,  64), tb>>>(Wk, wkvgh,              wkvgl,              2048, 128); // 2
    mma_gemm<<<dim3(8, ntok / 128), 512, SMEM_GEMM>>>(xh, xl, wqh, wql, q, ntok, 2048, 2048);     // 3 <- ncu
    transpose_split<<<dim3(4,  64), tb>>>(Wv, wkvgh + 128 * 2048, wkvgl + 128 * 2048, 2048, 128); // 4
    transpose_split<<<dim3(3,  64), tb>>>(Wg, wkvgh + 256 * 2048, wkvgl + 256 * 2048, 2048, 96);  // 5
    mma_gemm<<<dim3(2, ntok / 128), 512, SMEM_GEMM>>>(xh, xl, wkvgh, wkvgl, kvg, ntok, 352, 2048);

    kv_prep<<<dim3(ntok / 32, 2, 2), tb>>>(ntok);
    compress_kernel<<<dim3(M, 2), 64>>>(wck, wcv, pe);
    comp_attn_kernel<<<dim3(ntok / 4, 2), 512>>>(ntok);
    main_attn_kernel<<<dim3(ntok / 4, 2), 256, ATTN_SMEM>>>(ntok);

    transpose_split<<<dim3(64, 64), tb>>>(Wo, woh, wol, 2048, 2048);
    mma_gemm<<<dim3(8, ntok / 128), 512, SMEM_GEMM>>>(fh, fl, woh, wol, out, ntok, 2048, 2048);
}

// round 10
// speedup vs baseline: 1.0641x; 1.0641x over previous
#include <cuda_runtime.h>
#include <cuda_bf16.h>
#include <math.h>
#include <stdint.h>

// Problem constants (T=2048, H=2048, HQ=32, HKV=2, D=64, G=16, M<=32)
#define TMAX 2048
#define MMAX 32

// ---------------- scratch (no allocation allowed) ----------------
__device__ float    g_q[TMAX * 2048];      // [n, HQ*D]
__device__ float    g_kvg[TMAX * 352];     // [n, k(128) | v(128) | gate(96)]
__device__ float    g_ck[MMAX * 2 * 64];
__device__ float    g_cv[MMAX * 2 * 64];
__device__ float    g_comp[TMAX * 2048];
__device__ unsigned g_sel[TMAX * 2];

// bf16 split operands
__device__ __nv_bfloat16 g_xh[2048 * 2048], g_xl[2048 * 2048];
__device__ __nv_bfloat16 g_fh[2048 * 2048], g_fl[2048 * 2048];
__device__ __nv_bfloat16 g_wqt_h[2048 * 2048], g_wqt_l[2048 * 2048];   // Wq^T [N,K]
__device__ __nv_bfloat16 g_wot_h[2048 * 2048], g_wot_l[2048 * 2048];   // Wo^T
__device__ __nv_bfloat16 g_wkvgt_h[352 * 2048], g_wkvgt_l[352 * 2048]; // [Wk|Wv|Wg]^T
// attention K / V^T split-bf16
__device__ __nv_bfloat16 g_kbh[TMAX * 128], g_kbl[TMAX * 128];          // [n][h][64]
__device__ __nv_bfloat16 g_vth[2 * 64 * TMAX], g_vtl[2 * 64 * TMAX];    // [h][d][n]

__device__ __forceinline__ uint32_t smem_u32(const void* p) {
    uint32_t a;
    asm("{ .reg .u64 t; cvta.to.shared.u64 t, %1; cvt.u32.u64 %0, t; }" : "=r"(a) : "l"(p));
    return a;
}

// ---------------- packed f32x2 helpers ----------------
__device__ __forceinline__ unsigned long long pk2(float x, float y) {
    unsigned long long r;
    asm("mov.b64 %0, {%1,%2};" : "=l"(r) : "f"(x), "f"(y));
    return r;
}
__device__ __forceinline__ unsigned long long pk2f2(float2 v) { return pk2(v.x, v.y); }
__device__ __forceinline__ void upk2(unsigned long long r, float& x, float& y) {
    asm("mov.b64 {%0,%1}, %2;" : "=f"(x), "=f"(y) : "l"(r));
}
__device__ __forceinline__ unsigned long long fma2(unsigned long long a,
                                                   unsigned long long b,
                                                   unsigned long long c) {
    unsigned long long d;
    asm("fma.rn.f32x2 %0, %1, %2, %3;" : "=l"(d) : "l"(a), "l"(b), "l"(c));
    return d;
}

// ---------------- mma helpers ----------------
#define LDSM4(r, addr) \
    asm volatile("ldmatrix.sync.aligned.m8n8.x4.shared.b16 {%0,%1,%2,%3}, [%4];" \
                 : "=r"((r)[0]), "=r"((r)[1]), "=r"((r)[2]), "=r"((r)[3]) : "r"(addr))

__device__ __forceinline__ void hmma(float* c, const uint32_t* a, const uint32_t* b) {
    asm volatile("mma.sync.aligned.m16n8k16.row.col.f32.bf16.bf16.f32 "
                 "{%0,%1,%2,%3},{%4,%5,%6,%7},{%8,%9},{%0,%1,%2,%3};"
                 : "+f"(c[0]), "+f"(c[1]), "+f"(c[2]), "+f"(c[3])
                 : "r"(a[0]), "r"(a[1]), "r"(a[2]), "r"(a[3]), "r"(b[0]), "r"(b[1]));
}

__device__ __forceinline__ void bsplit(float v, unsigned short& hi, unsigned short& lo) {
    __nv_bfloat16 h = __float2bfloat16(v);
    __nv_bfloat16 l = __float2bfloat16(v - __bfloat162float(h));
    hi = *(unsigned short*)&h; lo = *(unsigned short*)&l;
}

// ================= prep kernels =================
__global__ void split_fp32(const float4* __restrict__ A,
                           __nv_bfloat16* __restrict__ Ah,
                           __nv_bfloat16* __restrict__ Al, int total4)
{
    int i = blockIdx.x * 256 + threadIdx.x;
    if (i < total4) {
        float4 v = A[i];
        ushort4 hh, ll;
        bsplit(v.x, hh.x, ll.x); bsplit(v.y, hh.y, ll.y);
        bsplit(v.z, hh.z, ll.z); bsplit(v.w, hh.w, ll.w);
        *(ushort4*)(Ah + 4 * (size_t)i) = hh;
        *(ushort4*)(Al + 4 * (size_t)i) = ll;
    }
}

__global__ void transpose_split(const float* __restrict__ W,
                                __nv_bfloat16* __restrict__ Th,
                                __nv_bfloat16* __restrict__ Tl, int K, int N)
{
    __shared__ float t[32][33];
    const int k0 = blockIdx.y * 32, n0 = blockIdx.x * 32;
    const int tx = threadIdx.x, ty = threadIdx.y;  // 32 x 8
    for (int i = ty; i < 32; i += 8) {
        int k = k0 + i, n = n0 + tx;
        t[i][tx] = (n < N && k < K) ? W[(size_t)k * N + n] : 0.f;
    }
    __syncthreads();
    for (int i = ty; i < 32; i += 8) {
        int n = n0 + i, k = k0 + tx;
        if (n < N && k < K) {
            unsigned short hi, lo;
            bsplit(t[tx][i], hi, lo);
            *(unsigned short*)(Th + (size_t)n * K + k) = hi;
            *(unsigned short*)(Tl + (size_t)n * K + k) = lo;
        }
    }
}

// K split + V transpose-split. grid (n/32, 2, 2), block (32,8)
__global__ void kv_prep(int ntok)
{
    __shared__ float t[32][33];
    const int n0 = blockIdx.x * 32, h = blockIdx.y, dh = blockIdx.z * 32;
    const int tx = threadIdx.x, ty = threadIdx.y;
    for (int i = ty; i < 32; i += 8) {
        const int n = n0 + i, d = dh + tx;
        float kv = g_kvg[n * 352 + h * 64 + d];
        unsigned short hi, lo;
        bsplit(kv, hi, lo);
        *(unsigned short*)(g_kbh + n * 128 + h * 64 + d) = hi;
        *(unsigned short*)(g_kbl + n * 128 + h * 64 + d) = lo;
        t[i][tx] = g_kvg[n * 352 + h * 64 + 128 + d];
    }
    __syncthreads();
    for (int i = ty; i < 32; i += 8) {
        const int d = dh + i, n = n0 + tx;
        unsigned short hi, lo;
        bsplit(t[tx][i], hi, lo);
        *(unsigned short*)(g_vth + (h * 64 + d) * TMAX + n) = hi;
        *(unsigned short*)(g_vtl + (h * 64 + d) * TMAX + n) = lo;
    }
}

// ================= split-bf16 GEMM, 128x256 tile, 512 threads (big GEMMs) =================
#define A_MAT 14336
#define B_MAT 28672
#define STAGE_BYTES 86016
#define SMEM_GEMM (2 * STAGE_BYTES)

__global__ void __launch_bounds__(512) mma_gemm(
    const __nv_bfloat16* __restrict__ Ah, const __nv_bfloat16* __restrict__ Al,
    const __nv_bfloat16* __restrict__ Bth, const __nv_bfloat16* __restrict__ Btl,
    float* __restrict__ C, int M, int N, int K)
{
    extern __shared__ char smem[];
    const uint32_t sb = smem_u32(smem);
    const int tid = threadIdx.x;
    const int lane = tid & 31, wid = tid >> 5;
    const int warp_m = wid & 1, warp_n = wid >> 1;   // 2 x 8 warps
    const int row0 = blockIdx.y * 128, col0 = blockIdx.x * 256;
    const int nchunk = K >> 5;

    float acc[4][4][4];
#pragma unroll
    for (int a = 0; a < 4; a++)
#pragma unroll
        for (int b = 0; b < 4; b++)
#pragma unroll
            for (int c = 0; c < 4; c++) acc[a][b][c] = 0.f;

    const int mt = lane >> 3, rin = lane & 7;
    const uint32_t a_off = (uint32_t)((warp_m * 64 + (mt & 1) * 8 + rin) * 112 + ((mt >> 1) * 8) * 2);
    const uint32_t b_off = (uint32_t)((warp_n * 32 + ((mt >= 2) ? 8 : 0) + rin) * 112 + ((mt & 1) * 8) * 2);

    auto load_chunk = [&](int c) {
        const int k0 = c * 32;
        const uint32_t st = sb + (uint32_t)(c & 1) * STAGE_BYTES;
#pragma unroll
        for (int i = 0; i < 6; i++) {
            int v = tid + i * 512;
            uint32_t dst;
            const __nv_bfloat16* srcp;
            int sz = 16;
            if (v < 1024) {
                int mat = v >> 9, r = (v >> 2) & 127, c16 = v & 3;
                dst = st + mat * A_MAT + r * 112 + c16 * 16;
                srcp = (mat ? Al : Ah) + (size_t)(row0 + r) * K + k0 + c16 * 8;
            } else {
                int vb = v - 1024;
                int mat = vb >> 10, r = (vb >> 2) & 255, c16 = vb & 3;
                dst = st + 2 * A_MAT + mat * B_MAT + r * 112 + c16 * 16;
                int n = col0 + r;
                int nn = (n < N) ? n : 0;
                if (n >= N) sz = 0;
                srcp = (mat ? Btl : Bth) + (size_t)nn * K + k0 + c16 * 8;
            }
            asm volatile("cp.async.cg.shared.global [%0], [%1], 16, %2;"
                         :: "r"(dst), "l"(srcp), "r"(sz));
        }
        asm volatile("cp.async.commit_group;" ::: "memory");
    };

    load_chunk(0);

    for (int c = 0; c < nchunk; c++) {
        if (c + 1 < nchunk) {
            load_chunk(c + 1);
            asm volatile("cp.async.wait_group 1;" ::: "memory");
        } else {
            asm volatile("cp.async.wait_group 0;" ::: "memory");
        }
        __syncthreads();

        const uint32_t st = sb + (uint32_t)(c & 1) * STAGE_BYTES;
#pragma unroll
        for (int ks = 0; ks < 2; ks++) {
            uint32_t ah[4][4], al[4][4];
#pragma unroll
            for (int mi = 0; mi < 4; mi++) {
                uint32_t addr = st + a_off + mi * (16 * 112) + ks * 32;
                LDSM4(ah[mi], addr);
                LDSM4(al[mi], addr + A_MAT);
            }
#pragma unroll
            for (int b2 = 0; b2 < 2; b2++) {
                uint32_t bh[4], bl[4];
                uint32_t baddr = st + 2 * A_MAT + b_off + b2 * (16 * 112) + ks * 32;
                LDSM4(bh, baddr);
                LDSM4(bl, baddr + B_MAT);
#pragma unroll
                for (int p = 0; p < 3; p++) {
#pragma unroll
                    for (int mi = 0; mi < 4; mi++) {
#pragma unroll
                        for (int hf = 0; hf < 2; hf++) {
                            const int nt = b2 * 2 + hf;
                            const uint32_t* A_ = (p == 2) ? al[mi] : ah[mi];
                            const uint32_t* B_ = (p == 1) ? bl : bh;
                            hmma(acc[mi][nt], A_, B_ + hf * 2);
                        }
                    }
                }
            }
        }
        __syncthreads();
    }

    const int g = lane >> 2, c2 = lane & 3;
#pragma unroll
    for (int mi = 0; mi < 4; mi++) {
        const int r = row0 + warp_m * 64 + mi * 16 + g;
#pragma unroll
        for (int nt = 0; nt < 4; nt++) {
            const int col = col0 + warp_n * 32 + nt * 8 + c2 * 2;
            if (col < N) {
                *(float2*)(C + (size_t)r * N + col)       = make_float2(acc[mi][nt][0], acc[mi][nt][1]);
                *(float2*)(C + (size_t)(r + 8) * N + col) = make_float2(acc[mi][nt][2], acc[mi][nt][3]);
            }
        }
    }
}

// ================= split-bf16 GEMM, 128x128 tile, 256 threads (narrow GEMMs) =================
#define MAT_BYTES8  (128 * 112)
#define STAGE8 (4 * MAT_BYTES8)
#define SMEM_GEMM8 (2 * STAGE8)

__global__ void __launch_bounds__(256) mma_gemm128(
    const __nv_bfloat16* __restrict__ Ah, const __nv_bfloat16* __restrict__ Al,
    const __nv_bfloat16* __restrict__ Bth, const __nv_bfloat16* __restrict__ Btl,
    float* __restrict__ C, int M, int N, int K)
{
    extern __shared__ char smem[];
    const uint32_t sb = smem_u32(smem);
    const int tid = threadIdx.x;
    const int lane = tid & 31, wid = tid >> 5;
    const int warp_m = wid & 1, warp_n = wid >> 1;
    const int row0 = blockIdx.y * 128, col0 = blockIdx.x * 128;
    const int nchunk = K >> 5;

    float acc[4][4][4];
#pragma unroll
    for (int a = 0; a < 4; a++)
#pragma unroll
        for (int b = 0; b < 4; b++)
#pragma unroll
            for (int c = 0; c < 4; c++) acc[a][b][c] = 0.f;

    const int mt = lane >> 3, rin = lane & 7;
    const uint32_t a_off = (uint32_t)((warp_m * 64 + (mt & 1) * 8 + rin) * 112 + ((mt >> 1) * 8) * 2);
    const uint32_t b_off = (uint32_t)((warp_n * 32 + ((mt >= 2) ? 8 : 0) + rin) * 112 + ((mt & 1) * 8) * 2);

    auto load_chunk = [&](int c) {
        const int k0 = c * 32;
        const uint32_t st = sb + (uint32_t)(c & 1) * STAGE8;
#pragma unroll
        for (int i = 0; i < 8; i++) {
            int v = tid + i * 256;
            int mat = v >> 9, r = (v >> 2) & 127, c16 = v & 3;
            uint32_t dst = st + mat * MAT_BYTES8 + r * 112 + c16 * 16;
            const __nv_bfloat16* srcp;
            int sz = 16;
            if (mat == 0)      srcp = Ah + (size_t)(row0 + r) * K + k0 + c16 * 8;
            else if (mat == 1) srcp = Al + (size_t)(row0 + r) * K + k0 + c16 * 8;
            else {
                int n = col0 + r;
                int nn = (n < N) ? n : 0;
                if (n >= N) sz = 0;
                srcp = (mat == 2 ? Bth : Btl) + (size_t)nn * K + k0 + c16 * 8;
            }
            asm volatile("cp.async.cg.shared.global [%0], [%1], 16, %2;"
                         :: "r"(dst), "l"(srcp), "r"(sz));
        }
        asm volatile("cp.async.commit_group;" ::: "memory");
    };

    load_chunk(0);

    for (int c = 0; c < nchunk; c++) {
        if (c + 1 < nchunk) {
            load_chunk(c + 1);
            asm volatile("cp.async.wait_group 1;" ::: "memory");
        } else {
            asm volatile("cp.async.wait_group 0;" ::: "memory");
        }
        __syncthreads();

        const uint32_t st = sb + (uint32_t)(c & 1) * STAGE8;
#pragma unroll
        for (int ks = 0; ks < 2; ks++) {
            uint32_t ah[4][4], al[4][4];
#pragma unroll
            for (int mi = 0; mi < 4; mi++) {
                uint32_t addr = st + a_off + mi * (16 * 112) + ks * 32;
                LDSM4(ah[mi], addr);
                LDSM4(al[mi], addr + MAT_BYTES8);
            }
#pragma unroll
            for (int b2 = 0; b2 < 2; b2++) {
                uint32_t bh[4], bl[4];
                uint32_t baddr = st + 2 * MAT_BYTES8 + b_off + b2 * (16 * 112) + ks * 32;
                LDSM4(bh, baddr);
                LDSM4(bl, baddr + MAT_BYTES8);
#pragma unroll
                for (int p = 0; p < 3; p++) {
#pragma unroll
                    for (int mi = 0; mi < 4; mi++) {
#pragma unroll
                        for (int hf = 0; hf < 2; hf++) {
                            const int nt = b2 * 2 + hf;
                            const uint32_t* A_ = (p == 2) ? al[mi] : ah[mi];
                            const uint32_t* B_ = (p == 1) ? bl : bh;
                            hmma(acc[mi][nt], A_, B_ + hf * 2);
                        }
                    }
                }
            }
        }
        __syncthreads();
    }

    const int g = lane >> 2, c2 = lane & 3;
#pragma unroll
    for (int mi = 0; mi < 4; mi++) {
        const int r = row0 + warp_m * 64 + mi * 16 + g;
#pragma unroll
        for (int nt = 0; nt < 4; nt++) {
            const int col = col0 + warp_n * 32 + nt * 8 + c2 * 2;
            if (col < N) {
                *(float2*)(C + (size_t)r * N + col)       = make_float2(acc[mi][nt][0], acc[mi][nt][1]);
                *(float2*)(C + (size_t)(r + 8) * N + col) = make_float2(acc[mi][nt][2], acc[mi][nt][3]);
            }
        }
    }
}

// ---------------- compressed tokens ----------------
__global__ void compress_kernel(const float* __restrict__ wck,
                                const float* __restrict__ wcv,
                                const float* __restrict__ pe)
{
    const int m = blockIdx.x, h = blockIdx.y, d = threadIdx.x;  // 64 threads
    float a = 0.f, b = 0.f;
    for (int t = 0; t < 64; t++) {
        const float wk = wck[h * 64 + t];
        const float wv = wcv[h * 64 + t];
        const int row = m * 64 + t;
        a = fmaf(g_kvg[row * 352 + h * 64 + d] + pe[(h * 64 + t) * 64 + d], wk, a);
        b = fmaf(g_kvg[row * 352 + 128 + h * 64 + d], wv, b);
    }
    g_ck[(m * 2 + h) * 64 + d] = a;
    g_cv[(m * 2 + h) * 64 + d] = b;
}

// ---------------- compressed attention + top-k, 4 tokens per CTA ----------------
__global__ void __launch_bounds__(512) comp_attn_kernel(int ntok)
{
    const int n0 = blockIdx.x * 4, h = blockIdx.y;
    const int tid = threadIdx.x;
    const int tq = tid >> 7, ltid = tid & 127;
    const int M = ntok >> 6;
    __shared__ float  sq[4096];
    __shared__ float2 ckp[32 * 33];
    __shared__ float  scv[MMAX * 64];
    __shared__ float  lg[4 * 512];
    __shared__ float  ssum[4 * 32];

    for (int i = tid; i < 4096; i += 512) {
        int q = i >> 10;
        sq[i] = g_q[(n0 + q) * 2048 + h * 1024 + (i & 1023)] * 0.125f;
    }
    for (int i = tid; i < M * 32; i += 512) {
        int m = i >> 5, d2 = i & 31;
        ckp[d2 * 33 + m] = *(const float2*)&g_ck[(m * 2 + h) * 64 + 2 * d2];
    }
    for (int i = tid; i < M * 64; i += 512)
        scv[i] = g_cv[((i >> 6) * 2 + h) * 64 + (i & 63)];
    __syncthreads();

    const int n = n0 + tq;
    const int mvis = (n >= 63) ? (((n - 63) >> 6) + 1) : 0;

#pragma unroll
    for (int i = 0; i < 4; i++) {
        int e = ltid + i * 128;
        int g = e >> 5, m = e & 31;
        unsigned long long acc = 0ull;
#pragma unroll
        for (int d2 = 0; d2 < 32; d2++) {
            unsigned long long qp = pk2f2(*(const float2*)&sq[tq * 1024 + g * 64 + 2 * d2]);
            acc = fma2(qp, pk2f2(ckp[d2 * 33 + m]), acc);
        }
        float x, y; upk2(acc, x, y);
        lg[tq * 512 + g * 32 + m] = x + y;
    }
    __syncthreads();

    if (ltid < 16) {
        float* row = lg + tq * 512 + ltid * 32;
        if (mvis == 0) {
            for (int m = 0; m < M; m++) row[m] = 0.f;
        } else {
            float mx = -INFINITY;
            for (int m = 0; m < mvis; m++) mx = fmaxf(mx, row[m]);
            float s = 0.f;
            for (int m = 0; m < mvis; m++) {
                float p = __expf(row[m] - mx);
                row[m] = p; s += p;
            }
            const float inv = 1.f / s;
            for (int m = 0; m < mvis; m++) row[m] *= inv;
            for (int m = mvis; m < M; m++) row[m] = 0.f;
        }
    }
    __syncthreads();

#pragma unroll
    for (int i = 0; i < 4; i++) {
        int e2 = ltid + i * 128;
        int g = e2 >> 5, d2 = e2 & 31;
        unsigned long long acc = 0ull;
        for (int m = 0; m < mvis; m++) {
            float p = lg[tq * 512 + g * 32 + m];
            acc = fma2(pk2(p, p), pk2f2(*(const float2*)&scv[m * 64 + 2 * d2]), acc);
        }
        float x, y; upk2(acc, x, y);
        *(float2*)&g_comp[n * 2048 + h * 1024 + g * 64 + 2 * d2] = make_float2(x, y);
    }

    if (ltid < 32) {
        float s = 0.f;
        if (ltid < M)
            for (int g = 0; g < 16; g++) s += lg[tq * 512 + g * 32 + ltid];
        ssum[tq * 32 + ltid] = s;
    }
    __syncthreads();

    if (ltid == 0) {
        const int qblk = n >> 6;
        unsigned sel = 0;
        if (qblk + 1 <= 16) {
            sel = (1u << (qblk + 1)) - 1u;
        } else {
            float sc[32];
            for (int m = 0; m < 32; m++) {
                if (m > qblk)                                  sc[m] = -INFINITY;
                else if (m == 0 || m == qblk || m == qblk - 1) sc[m] = INFINITY;
                else                                           sc[m] = ssum[tq * 32 + m];
            }
            for (int t = 0; t < 16; t++) {
                int best = 0; float bv = -INFINITY;
                for (int m = 0; m < 32; m++) {
                    if ((sel >> m) & 1u) continue;
                    if (sc[m] > bv) { bv = sc[m]; best = m; }
                }
                sel |= 1u << best;
            }
        }
        g_sel[n * 2 + h] = sel;
    }
}

// ---------------- main attention on tensor cores ----------------
#define BST 72          // bf16 smem row stride (elements) = 144 bytes
#define SQH 0
#define SQL 9216
#define SKH 18432
#define SKL 27648
#define SVTH 36864
#define SVTL 46080
#define PSH 55296
#define PSL 64512
#define PWH 73728
#define PWL 82944
#define LG_OFF 92160    // float [64][66]
#define PM_OFF 109056   // float [512]
#define HMM_OFF 111104  // float [2][64]
#define HLL_OFF 111616
#define HRR_OFF 112128
#define ATTN_SMEM 112640

__global__ void __launch_bounds__(256, 2) main_attn_kernel(int ntok)
{
    extern __shared__ char dsm[];
    const uint32_t sb = smem_u32(dsm);
    float* lg  = (float*)(dsm + LG_OFF);
    float* pm  = (float*)(dsm + PM_OFF);
    float* hmm = (float*)(dsm + HMM_OFF);
    float* hll = (float*)(dsm + HLL_OFF);
    float* hrr = (float*)(dsm + HRR_OFF);

    const int n0 = blockIdx.x * 4, h = blockIdx.y;
    const int tid = threadIdx.x;
    const int lane = tid & 31, wid = tid >> 5;
    const int warp_m = wid & 1, warp_n = wid >> 1;
    const int g = lane >> 2, cq = lane & 3;

    for (int i = tid; i < 4096; i += 256) {
        int r = i >> 6, d = i & 63;
        float v = g_q[(n0 + (r >> 4)) * 2048 + h * 1024 + (r & 15) * 64 + d] * 0.125f;
        unsigned short hi, lo;
        bsplit(v, hi, lo);
        *(unsigned short*)(dsm + SQH + (r * BST + d) * 2) = hi;
        *(unsigned short*)(dsm + SQL + (r * BST + d) * 2) = lo;
    }
    if (tid < 128) { hmm[tid] = -INFINITY; hll[tid] = 0.f; }

    const unsigned sel0 = g_sel[n0 * 2 + h],       sel1 = g_sel[(n0 + 1) * 2 + h],
                   sel2 = g_sel[(n0 + 2) * 2 + h], sel3 = g_sel[(n0 + 3) * 2 + h];
    const unsigned selU = sel0 | sel1 | sel2 | sel3;
    const int qblk = n0 >> 6;

    const int mt = lane >> 3, rin = lane & 7;
    const uint32_t a_base = (uint32_t)(((mt & 1) * 8 + rin) * 144 + ((mt >> 1) * 8) * 2);
    const uint32_t b_base = (uint32_t)((warp_n * 16 + ((mt >= 2) ? 8 : 0) + rin) * 144 + ((mt & 1) * 8) * 2);

    float acc_s[2][2][4] = {}, acc_w[2][2][4] = {};

    __syncthreads();

    for (int c = 0; c <= qblk; c++) {
        const int base = n0 - c * 64;
        const bool anyw = (base - 512) <= 63;
        if (!((selU >> c) & 1u) && !anyw) continue;

        for (int i = tid; i < 2048; i += 256) {
            int mat = i >> 9, idx = i & 511;
            int row = idx >> 3, c16 = idx & 7;
            const __nv_bfloat16* src;
            if (mat == 0)      src = g_kbh + (size_t)(c * 64 + row) * 128 + h * 64 + c16 * 8;
            else if (mat == 1) src = g_kbl + (size_t)(c * 64 + row) * 128 + h * 64 + c16 * 8;
            else if (mat == 2) src = g_vth + (size_t)(h * 64 + row) * TMAX + c * 64 + c16 * 8;
            else               src = g_vtl + (size_t)(h * 64 + row) * TMAX + c * 64 + c16 * 8;
            *(uint4*)(dsm + SKH + mat * 9216 + row * 144 + c16 * 16) = *(const uint4*)src;
        }
        __syncthreads();

        // ---- S = Q K^T via HMMA (3-product) ----
        {
            float acc[2][2][4] = {};
#pragma unroll
            for (int ks = 0; ks < 4; ks++) {
                uint32_t kh[4], kl[4];
                LDSM4(kh, sb + SKH + b_base + ks * 32);
                LDSM4(kl, sb + SKL + b_base + ks * 32);
#pragma unroll
                for (int mi = 0; mi < 2; mi++) {
                    uint32_t qh[4], ql[4];
                    const uint32_t ao = (uint32_t)((warp_m * 32 + mi * 16) * 144) + a_base + ks * 32;
                    LDSM4(qh, sb + SQH + ao);
                    LDSM4(ql, sb + SQL + ao);
#pragma unroll
                    for (int hf = 0; hf < 2; hf++) {
                        hmma(acc[mi][hf], qh, kh + hf * 2);
                        hmma(acc[mi][hf], qh, kl + hf * 2);
                        hmma(acc[mi][hf], ql, kh + hf * 2);
                    }
                }
            }
#pragma unroll
            for (int mi = 0; mi < 2; mi++) {
                const int r0 = warp_m * 32 + mi * 16 + g;
#pragma unroll
                for (int hf = 0; hf < 2; hf++) {
                    const int col = warp_n * 16 + hf * 8 + cq * 2;
                    *(float2*)&lg[r0 * 66 + col]       = make_float2(acc[mi][hf][0], acc[mi][hf][1]);
                    *(float2*)&lg[(r0 + 8) * 66 + col] = make_float2(acc[mi][hf][2], acc[mi][hf][3]);
                }
            }
        }
        __syncthreads();

        // ---- segmented max ----
        {
            const int r = tid >> 2, seg = tid & 3;
            const int q = r >> 4;
            const int jn = min(63, base + q);
            const unsigned selq = (q == 0) ? sel0 : (q == 1) ? sel1 : (q == 2) ? sel2 : sel3;
            const int jw0 = base + q - 512;
            float ms = -INFINITY;
            if ((selq >> c) & 1u) {
                const int hi2 = min(seg * 16 + 15, jn);
                for (int j = seg * 16; j <= hi2; j++) ms = fmaxf(ms, lg[r * 66 + j]);
            }
            pm[tid] = ms;
            float mw = -INFINITY;
            if (jw0 <= 63) {
                const int lo2 = max(seg * 16, jw0);
                const int hi2 = min(seg * 16 + 15, jn);
                for (int j = lo2; j <= hi2; j++) mw = fmaxf(mw, lg[r * 66 + j]);
            }
            pm[256 + tid] = mw;
        }
        __syncthreads();
        if (tid < 128) {
            const int br = tid >> 6, r = tid & 63;
            const float* p = pm + br * 256 + r * 4;
            const float cm = fmaxf(fmaxf(p[0], p[1]), fmaxf(p[2], p[3]));
            const float om = hmm[br * 64 + r];
            const float nm = fmaxf(om, cm);
            hmm[br * 64 + r] = nm;
            hrr[br * 64 + r] = (cm == -INFINITY) ? 1.f : __expf(om - nm);
        }
        __syncthreads();

        // ---- exp + partial sums + split-bf16 P store ----
        {
            const int r = tid >> 2, seg = tid & 3;
            const int q = r >> 4;
            const unsigned selq = (q == 0) ? sel0 : (q == 1) ? sel1 : (q == 2) ? sel2 : sel3;
            const int jn = base + q;
            const int jw0 = base + q - 512;
            const bool sact = (selq >> c) & 1u;
            const float ms = hmm[r], mw = hmm[64 + r];
            float ss = 0.f, sw = 0.f;
            unsigned short eh[16], el[16], wh[16], wl[16];
#pragma unroll
            for (int jj = 0; jj < 16; jj++) {
                const int j = seg * 16 + jj;
                const float l = lg[r * 66 + j];
                const bool jc = (j <= jn);
                float es = (jc && sact)        ? __expf(l - ms) : 0.f;
                float ew = (jc && j >= jw0)    ? __expf(l - mw) : 0.f;
                ss += es; sw += ew;
                bsplit(es, eh[jj], el[jj]);
                bsplit(ew, wh[jj], wl[jj]);
            }
            pm[tid] = ss; pm[256 + tid] = sw;
            const uint32_t po = (uint32_t)((r * BST + seg * 16) * 2);
#pragma unroll
            for (int v4 = 0; v4 < 4; v4++) {
                *(ushort4*)(dsm + PSH + po + v4 * 8) = make_ushort4(eh[v4*4], eh[v4*4+1], eh[v4*4+2], eh[v4*4+3]);
                *(ushort4*)(dsm + PSL + po + v4 * 8) = make_ushort4(el[v4*4], el[v4*4+1], el[v4*4+2], el[v4*4+3]);
                *(ushort4*)(dsm + PWH + po + v4 * 8) = make_ushort4(wh[v4*4], wh[v4*4+1], wh[v4*4+2], wh[v4*4+3]);
                *(ushort4*)(dsm + PWL + po + v4 * 8) = make_ushort4(wl[v4*4], wl[v4*4+1], wl[v4*4+2], wl[v4*4+3]);
            }
        }
        __syncthreads();
        if (tid < 128) {
            const int br = tid >> 6, r = tid & 63;
            const float* p = pm + br * 256 + r * 4;
            hll[br * 64 + r] = hll[br * 64 + r] * hrr[br * 64 + r]
                             + (p[0] + p[1]) + (p[2] + p[3]);
        }

        // ---- PV via HMMA with flash rescale ----
#pragma unroll
        for (int mi = 0; mi < 2; mi++) {
            const int rb = warp_m * 32 + mi * 16 + g;
            const float rs0 = hrr[rb], rs1 = hrr[rb + 8];
            const float rw0 = hrr[64 + rb], rw1 = hrr[64 + rb + 8];
#pragma unroll
            for (int hf = 0; hf < 2; hf++) {
                acc_s[mi][hf][0] *= rs0; acc_s[mi][hf][1] *= rs0;
                acc_s[mi][hf][2] *= rs1; acc_s[mi][hf][3] *= rs1;
                acc_w[mi][hf][0] *= rw0; acc_w[mi][hf][1] *= rw0;
                acc_w[mi][hf][2] *= rw1; acc_w[mi][hf][3] *= rw1;
            }
        }
#pragma unroll
        for (int ks = 0; ks < 4; ks++) {
            uint32_t vh[4], vl[4];
            LDSM4(vh, sb + SVTH + b_base + ks * 32);
            LDSM4(vl, sb + SVTL + b_base + ks * 32);
#pragma unroll
            for (int mi = 0; mi < 2; mi++) {
                const uint32_t ao = (uint32_t)((warp_m * 32 + mi * 16) * 144) + a_base + ks * 32;
                uint32_t ph[4], pl[4];
                LDSM4(ph, sb + PSH + ao);
                LDSM4(pl, sb + PSL + ao);
#pragma unroll
                for (int hf = 0; hf < 2; hf++) {
                    hmma(acc_s[mi][hf], ph, vh + hf * 2);
                    hmma(acc_s[mi][hf], ph, vl + hf * 2);
                    hmma(acc_s[mi][hf], pl, vh + hf * 2);
                }
                LDSM4(ph, sb + PWH + ao);
                LDSM4(pl, sb + PWL + ao);
#pragma unroll
                for (int hf = 0; hf < 2; hf++) {
                    hmma(acc_w[mi][hf], ph, vh + hf * 2);
                    hmma(acc_w[mi][hf], ph, vl + hf * 2);
                    hmma(acc_w[mi][hf], pl, vh + hf * 2);
                }
            }
        }
        __syncthreads();
    }

    // ---- gated fusion epilogue ----
#pragma unroll
    for (int mi = 0; mi < 2; mi++) {
#pragma unroll
        for (int half = 0; half < 2; half++) {
            const int r = warp_m * 32 + mi * 16 + g + half * 8;
            const int nq = n0 + (r >> 4);
            const int head = r & 15;
            const int hq = h * 16 + head;
            const float gl0 = g_kvg[nq * 352 + 256 + hq * 3 + 0];
            const float gl1 = g_kvg[nq * 352 + 256 + hq * 3 + 1];
            const float gl2 = g_kvg[nq * 352 + 256 + hq * 3 + 2];
            const float g0 = 1.f / (1.f + __expf(-gl0));
            const float g1 = 1.f / (1.f + __expf(-gl1));
            const float g2 = 1.f / (1.f + __expf(-gl2));
            const float inv_s = 1.f / hll[r];
            const float inv_w = 1.f / hll[64 + r];
#pragma unroll
            for (int hf = 0; hf < 2; hf++) {
                const int col = warp_n * 16 + hf * 8 + cq * 2;
                const int oi = nq * 2048 + h * 1024 + head * 64 + col;
                const float2 cmp = *(const float2*)&g_comp[oi];
                const float o0 = g0 * cmp.x + g1 * acc_s[mi][hf][half * 2]     * inv_s
                                            + g2 * acc_w[mi][hf][half * 2]     * inv_w;
                const float o1 = g0 * cmp.y + g1 * acc_s[mi][hf][half * 2 + 1] * inv_s
                                            + g2 * acc_w[mi][hf][half * 2 + 1] * inv_w;
                ushort2 hh, ll;
                bsplit(o0, hh.x, ll.x);
                bsplit(o1, hh.y, ll.y);
                *(ushort2*)(g_fh + oi) = hh;
                *(ushort2*)(g_fl + oi) = ll;
            }
        }
    }
}

// ---------------- launch ----------------
extern "C" void kernel_launch(void* const* d_in, const int* in_sizes, int n_in,
                              void* d_out, int out_size)
{
    const float* x   = (const float*)d_in[0];
    const float* Wq  = (const float*)d_in[2];
    const float* Wk  = (const float*)d_in[3];
    const float* Wv  = (const float*)d_in[4];
    const float* Wo  = (const float*)d_in[5];
    const float* Wg  = (const float*)d_in[6];
    const float* wck = (const float*)d_in[7];
    const float* wcv = (const float*)d_in[8];
    const float* pe  = (const float*)d_in[9];
    float* out = (float*)d_out;

    const int ntok = in_sizes[0] / 2048;     // T = 2048
    const int M = ntok / 64;

    float *q, *kvg;
    cudaGetSymbolAddress((void**)&q,   g_q);
    cudaGetSymbolAddress((void**)&kvg, g_kvg);

    __nv_bfloat16 *xh, *xl, *fh, *fl, *wqh, *wql, *woh, *wol, *wkvgh, *wkvgl;
    cudaGetSymbolAddress((void**)&xh, g_xh);     cudaGetSymbolAddress((void**)&xl, g_xl);
    cudaGetSymbolAddress((void**)&fh, g_fh);     cudaGetSymbolAddress((void**)&fl, g_fl);
    cudaGetSymbolAddress((void**)&wqh, g_wqt_h); cudaGetSymbolAddress((void**)&wql, g_wqt_l);
    cudaGetSymbolAddress((void**)&woh, g_wot_h); cudaGetSymbolAddress((void**)&wol, g_wot_l);
    cudaGetSymbolAddress((void**)&wkvgh, g_wkvgt_h);
    cudaGetSymbolAddress((void**)&wkvgl, g_wkvgt_l);

    cudaFuncSetAttribute(mma_gemm, cudaFuncAttributeMaxDynamicSharedMemorySize, SMEM_GEMM);
    cudaFuncSetAttribute(mma_gemm128, cudaFuncAttributeMaxDynamicSharedMemorySize, SMEM_GEMM8);
    cudaFuncSetAttribute(main_attn_kernel, cudaFuncAttributeMaxDynamicSharedMemorySize, ATTN_SMEM);

    const int tot = ntok * 2048;
    dim3 tb(32, 8);

    split_fp32<<<(tot / 4 + 255) / 256, 256>>>((const float4*)x, xh, xl, tot / 4);                // 0
    transpose_split<<<dim3(64, 64), tb>>>(Wq, wqh, wql, 2048, 2048);                              // 1
    transpose_split<<<dim3(4,  64), tb>>>(Wk, wkvgh,              wkvgl,              2048, 128); // 2
    mma_gemm<<<dim3(8, ntok / 128), 512, SMEM_GEMM>>>(xh, xl, wqh, wql, q, ntok, 2048, 2048);     // 3 <- ncu
    transpose_split<<<dim3(4,  64), tb>>>(Wv, wkvgh + 128 * 2048, wkvgl + 128 * 2048, 2048, 128); // 4
    transpose_split<<<dim3(3,  64), tb>>>(Wg, wkvgh + 256 * 2048, wkvgl + 256 * 2048, 2048, 96);  // 5
    mma_gemm128<<<dim3(3, ntok / 128), 256, SMEM_GEMM8>>>(xh, xl, wkvgh, wkvgl, kvg, ntok, 352, 2048);

    kv_prep<<<dim3(ntok / 32, 2, 2), tb>>>(ntok);
    compress_kernel<<<dim3(M, 2), 64>>>(wck, wcv, pe);
    comp_attn_kernel<<<dim3(ntok / 4, 2), 512>>>(ntok);
    main_attn_kernel<<<dim3(ntok / 4, 2), 256, ATTN_SMEM>>>(ntok);

    transpose_split<<<dim3(64, 64), tb>>>(Wo, woh, wol, 2048, 2048);
    mma_gemm<<<dim3(8, ntok / 128), 512, SMEM_GEMM>>>(fh, fl, woh, wol, out, ntok, 2048, 2048);
}

// round 11
// speedup vs baseline: 1.0992x; 1.0330x over previous
#include <cuda_runtime.h>
#include <cuda_bf16.h>
#include <math.h>
#include <stdint.h>

// Problem constants (T=2048, H=2048, HQ=32, HKV=2, D=64, G=16, M<=32)
#define TMAX 2048
#define MMAX 32

// ---------------- scratch (no allocation allowed) ----------------
__device__ float    g_q[TMAX * 2048];      // [n, HQ*D]
__device__ float    g_kvg[TMAX * 352];     // [n, k(128) | v(128) | gate(96)]
__device__ float    g_ck[MMAX * 2 * 64];
__device__ float    g_cv[MMAX * 2 * 64];
__device__ float    g_comp[TMAX * 2048];
__device__ unsigned g_sel[TMAX * 2];

// bf16 split operands
__device__ __nv_bfloat16 g_xh[2048 * 2048], g_xl[2048 * 2048];
__device__ __nv_bfloat16 g_fh[2048 * 2048], g_fl[2048 * 2048];
__device__ __nv_bfloat16 g_wqt_h[2048 * 2048], g_wqt_l[2048 * 2048];   // Wq^T [N,K]
__device__ __nv_bfloat16 g_wot_h[2048 * 2048], g_wot_l[2048 * 2048];   // Wo^T
__device__ __nv_bfloat16 g_wkvgt_h[352 * 2048], g_wkvgt_l[352 * 2048]; // [Wk|Wv|Wg]^T
// attention K / V^T split-bf16
__device__ __nv_bfloat16 g_kbh[TMAX * 128], g_kbl[TMAX * 128];          // [n][h][64]
__device__ __nv_bfloat16 g_vth[2 * 64 * TMAX], g_vtl[2 * 64 * TMAX];    // [h][d][n]

__device__ __forceinline__ uint32_t smem_u32(const void* p) {
    uint32_t a;
    asm("{ .reg .u64 t; cvta.to.shared.u64 t, %1; cvt.u32.u64 %0, t; }" : "=r"(a) : "l"(p));
    return a;
}

// ---------------- packed f32x2 helpers ----------------
__device__ __forceinline__ unsigned long long pk2(float x, float y) {
    unsigned long long r;
    asm("mov.b64 %0, {%1,%2};" : "=l"(r) : "f"(x), "f"(y));
    return r;
}
__device__ __forceinline__ unsigned long long pk2f2(float2 v) { return pk2(v.x, v.y); }
__device__ __forceinline__ void upk2(unsigned long long r, float& x, float& y) {
    asm("mov.b64 {%0,%1}, %2;" : "=f"(x), "=f"(y) : "l"(r));
}
__device__ __forceinline__ unsigned long long fma2(unsigned long long a,
                                                   unsigned long long b,
                                                   unsigned long long c) {
    unsigned long long d;
    asm("fma.rn.f32x2 %0, %1, %2, %3;" : "=l"(d) : "l"(a), "l"(b), "l"(c));
    return d;
}

// ---------------- mma helpers ----------------
#define LDSM4(r, addr) \
    asm volatile("ldmatrix.sync.aligned.m8n8.x4.shared.b16 {%0,%1,%2,%3}, [%4];" \
                 : "=r"((r)[0]), "=r"((r)[1]), "=r"((r)[2]), "=r"((r)[3]) : "r"(addr))

__device__ __forceinline__ void hmma(float* c, const uint32_t* a, const uint32_t* b) {
    asm volatile("mma.sync.aligned.m16n8k16.row.col.f32.bf16.bf16.f32 "
                 "{%0,%1,%2,%3},{%4,%5,%6,%7},{%8,%9},{%0,%1,%2,%3};"
                 : "+f"(c[0]), "+f"(c[1]), "+f"(c[2]), "+f"(c[3])
                 : "r"(a[0]), "r"(a[1]), "r"(a[2]), "r"(a[3]), "r"(b[0]), "r"(b[1]));
}

__device__ __forceinline__ void bsplit(float v, unsigned short& hi, unsigned short& lo) {
    __nv_bfloat16 h = __float2bfloat16(v);
    __nv_bfloat16 l = __float2bfloat16(v - __bfloat162float(h));
    hi = *(unsigned short*)&h; lo = *(unsigned short*)&l;
}

// ================= prep kernels =================
__global__ void split_fp32(const float4* __restrict__ A,
                           __nv_bfloat16* __restrict__ Ah,
                           __nv_bfloat16* __restrict__ Al, int total4)
{
    int i = blockIdx.x * 256 + threadIdx.x;
    if (i < total4) {
        float4 v = A[i];
        ushort4 hh, ll;
        bsplit(v.x, hh.x, ll.x); bsplit(v.y, hh.y, ll.y);
        bsplit(v.z, hh.z, ll.z); bsplit(v.w, hh.w, ll.w);
        *(ushort4*)(Ah + 4 * (size_t)i) = hh;
        *(ushort4*)(Al + 4 * (size_t)i) = ll;
    }
}

__global__ void transpose_split(const float* __restrict__ W,
                                __nv_bfloat16* __restrict__ Th,
                                __nv_bfloat16* __restrict__ Tl, int K, int N)
{
    __shared__ float t[32][33];
    const int k0 = blockIdx.y * 32, n0 = blockIdx.x * 32;
    const int tx = threadIdx.x, ty = threadIdx.y;  // 32 x 8
    for (int i = ty; i < 32; i += 8) {
        int k = k0 + i, n = n0 + tx;
        t[i][tx] = (n < N && k < K) ? W[(size_t)k * N + n] : 0.f;
    }
    __syncthreads();
    for (int i = ty; i < 32; i += 8) {
        int n = n0 + i, k = k0 + tx;
        if (n < N && k < K) {
            unsigned short hi, lo;
            bsplit(t[tx][i], hi, lo);
            *(unsigned short*)(Th + (size_t)n * K + k) = hi;
            *(unsigned short*)(Tl + (size_t)n * K + k) = lo;
        }
    }
}

// K split + V transpose-split. grid (n/32, 2, 2), block (32,8)
__global__ void kv_prep(int ntok)
{
    __shared__ float t[32][33];
    const int n0 = blockIdx.x * 32, h = blockIdx.y, dh = blockIdx.z * 32;
    const int tx = threadIdx.x, ty = threadIdx.y;
    for (int i = ty; i < 32; i += 8) {
        const int n = n0 + i, d = dh + tx;
        float kv = g_kvg[n * 352 + h * 64 + d];
        unsigned short hi, lo;
        bsplit(kv, hi, lo);
        *(unsigned short*)(g_kbh + n * 128 + h * 64 + d) = hi;
        *(unsigned short*)(g_kbl + n * 128 + h * 64 + d) = lo;
        t[i][tx] = g_kvg[n * 352 + h * 64 + 128 + d];
    }
    __syncthreads();
    for (int i = ty; i < 32; i += 8) {
        const int d = dh + i, n = n0 + tx;
        unsigned short hi, lo;
        bsplit(t[tx][i], hi, lo);
        *(unsigned short*)(g_vth + (h * 64 + d) * TMAX + n) = hi;
        *(unsigned short*)(g_vtl + (h * 64 + d) * TMAX + n) = lo;
    }
}

// ================= split-bf16 GEMM, 128x256 tile, 512 threads (big GEMMs) =================
#define A_MAT 14336
#define B_MAT 28672
#define STAGE_BYTES 86016
#define SMEM_GEMM (2 * STAGE_BYTES)

__global__ void __launch_bounds__(512) mma_gemm(
    const __nv_bfloat16* __restrict__ Ah, const __nv_bfloat16* __restrict__ Al,
    const __nv_bfloat16* __restrict__ Bth, const __nv_bfloat16* __restrict__ Btl,
    float* __restrict__ C, int M, int N, int K)
{
    extern __shared__ char smem[];
    const uint32_t sb = smem_u32(smem);
    const int tid = threadIdx.x;
    const int lane = tid & 31, wid = tid >> 5;
    const int warp_m = wid & 1, warp_n = wid >> 1;   // 2 x 8 warps
    const int row0 = blockIdx.y * 128, col0 = blockIdx.x * 256;
    const int nchunk = K >> 5;

    float acc[4][4][4];
#pragma unroll
    for (int a = 0; a < 4; a++)
#pragma unroll
        for (int b = 0; b < 4; b++)
#pragma unroll
            for (int c = 0; c < 4; c++) acc[a][b][c] = 0.f;

    const int mt = lane >> 3, rin = lane & 7;
    const uint32_t a_off = (uint32_t)((warp_m * 64 + (mt & 1) * 8 + rin) * 112 + ((mt >> 1) * 8) * 2);
    const uint32_t b_off = (uint32_t)((warp_n * 32 + ((mt >= 2) ? 8 : 0) + rin) * 112 + ((mt & 1) * 8) * 2);

    auto load_chunk = [&](int c) {
        const int k0 = c * 32;
        const uint32_t st = sb + (uint32_t)(c & 1) * STAGE_BYTES;
#pragma unroll
        for (int i = 0; i < 6; i++) {
            int v = tid + i * 512;
            uint32_t dst;
            const __nv_bfloat16* srcp;
            int sz = 16;
            if (v < 1024) {
                int mat = v >> 9, r = (v >> 2) & 127, c16 = v & 3;
                dst = st + mat * A_MAT + r * 112 + c16 * 16;
                srcp = (mat ? Al : Ah) + (size_t)(row0 + r) * K + k0 + c16 * 8;
            } else {
                int vb = v - 1024;
                int mat = vb >> 10, r = (vb >> 2) & 255, c16 = vb & 3;
                dst = st + 2 * A_MAT + mat * B_MAT + r * 112 + c16 * 16;
                int n = col0 + r;
                int nn = (n < N) ? n : 0;
                if (n >= N) sz = 0;
                srcp = (mat ? Btl : Bth) + (size_t)nn * K + k0 + c16 * 8;
            }
            asm volatile("cp.async.cg.shared.global [%0], [%1], 16, %2;"
                         :: "r"(dst), "l"(srcp), "r"(sz));
        }
        asm volatile("cp.async.commit_group;" ::: "memory");
    };

    load_chunk(0);

    for (int c = 0; c < nchunk; c++) {
        if (c + 1 < nchunk) {
            load_chunk(c + 1);
            asm volatile("cp.async.wait_group 1;" ::: "memory");
        } else {
            asm volatile("cp.async.wait_group 0;" ::: "memory");
        }
        __syncthreads();

        const uint32_t st = sb + (uint32_t)(c & 1) * STAGE_BYTES;
#pragma unroll
        for (int ks = 0; ks < 2; ks++) {
            uint32_t ah[4][4], al[4][4];
#pragma unroll
            for (int mi = 0; mi < 4; mi++) {
                uint32_t addr = st + a_off + mi * (16 * 112) + ks * 32;
                LDSM4(ah[mi], addr);
                LDSM4(al[mi], addr + A_MAT);
            }
#pragma unroll
            for (int b2 = 0; b2 < 2; b2++) {
                uint32_t bh[4], bl[4];
                uint32_t baddr = st + 2 * A_MAT + b_off + b2 * (16 * 112) + ks * 32;
                LDSM4(bh, baddr);
                LDSM4(bl, baddr + B_MAT);
#pragma unroll
                for (int p = 0; p < 3; p++) {
#pragma unroll
                    for (int mi = 0; mi < 4; mi++) {
#pragma unroll
                        for (int hf = 0; hf < 2; hf++) {
                            const int nt = b2 * 2 + hf;
                            const uint32_t* A_ = (p == 2) ? al[mi] : ah[mi];
                            const uint32_t* B_ = (p == 1) ? bl : bh;
                            hmma(acc[mi][nt], A_, B_ + hf * 2);
                        }
                    }
                }
            }
        }
        __syncthreads();
    }

    const int g = lane >> 2, c2 = lane & 3;
#pragma unroll
    for (int mi = 0; mi < 4; mi++) {
        const int r = row0 + warp_m * 64 + mi * 16 + g;
#pragma unroll
        for (int nt = 0; nt < 4; nt++) {
            const int col = col0 + warp_n * 32 + nt * 8 + c2 * 2;
            if (col < N) {
                *(float2*)(C + (size_t)r * N + col)       = make_float2(acc[mi][nt][0], acc[mi][nt][1]);
                *(float2*)(C + (size_t)(r + 8) * N + col) = make_float2(acc[mi][nt][2], acc[mi][nt][3]);
            }
        }
    }
}

// ================= split-bf16 GEMM, 128x128 tile, 256 threads (narrow GEMMs) =================
#define MAT_BYTES8  (128 * 112)
#define STAGE8 (4 * MAT_BYTES8)
#define SMEM_GEMM8 (2 * STAGE8)

__global__ void __launch_bounds__(256) mma_gemm128(
    const __nv_bfloat16* __restrict__ Ah, const __nv_bfloat16* __restrict__ Al,
    const __nv_bfloat16* __restrict__ Bth, const __nv_bfloat16* __restrict__ Btl,
    float* __restrict__ C, int M, int N, int K)
{
    extern __shared__ char smem[];
    const uint32_t sb = smem_u32(smem);
    const int tid = threadIdx.x;
    const int lane = tid & 31, wid = tid >> 5;
    const int warp_m = wid & 1, warp_n = wid >> 1;
    const int row0 = blockIdx.y * 128, col0 = blockIdx.x * 128;
    const int nchunk = K >> 5;

    float acc[4][4][4];
#pragma unroll
    for (int a = 0; a < 4; a++)
#pragma unroll
        for (int b = 0; b < 4; b++)
#pragma unroll
            for (int c = 0; c < 4; c++) acc[a][b][c] = 0.f;

    const int mt = lane >> 3, rin = lane & 7;
    const uint32_t a_off = (uint32_t)((warp_m * 64 + (mt & 1) * 8 + rin) * 112 + ((mt >> 1) * 8) * 2);
    const uint32_t b_off = (uint32_t)((warp_n * 32 + ((mt >= 2) ? 8 : 0) + rin) * 112 + ((mt & 1) * 8) * 2);

    auto load_chunk = [&](int c) {
        const int k0 = c * 32;
        const uint32_t st = sb + (uint32_t)(c & 1) * STAGE8;
#pragma unroll
        for (int i = 0; i < 8; i++) {
            int v = tid + i * 256;
            int mat = v >> 9, r = (v >> 2) & 127, c16 = v & 3;
            uint32_t dst = st + mat * MAT_BYTES8 + r * 112 + c16 * 16;
            const __nv_bfloat16* srcp;
            int sz = 16;
            if (mat == 0)      srcp = Ah + (size_t)(row0 + r) * K + k0 + c16 * 8;
            else if (mat == 1) srcp = Al + (size_t)(row0 + r) * K + k0 + c16 * 8;
            else {
                int n = col0 + r;
                int nn = (n < N) ? n : 0;
                if (n >= N) sz = 0;
                srcp = (mat == 2 ? Bth : Btl) + (size_t)nn * K + k0 + c16 * 8;
            }
            asm volatile("cp.async.cg.shared.global [%0], [%1], 16, %2;"
                         :: "r"(dst), "l"(srcp), "r"(sz));
        }
        asm volatile("cp.async.commit_group;" ::: "memory");
    };

    load_chunk(0);

    for (int c = 0; c < nchunk; c++) {
        if (c + 1 < nchunk) {
            load_chunk(c + 1);
            asm volatile("cp.async.wait_group 1;" ::: "memory");
        } else {
            asm volatile("cp.async.wait_group 0;" ::: "memory");
        }
        __syncthreads();

        const uint32_t st = sb + (uint32_t)(c & 1) * STAGE8;
#pragma unroll
        for (int ks = 0; ks < 2; ks++) {
            uint32_t ah[4][4], al[4][4];
#pragma unroll
            for (int mi = 0; mi < 4; mi++) {
                uint32_t addr = st + a_off + mi * (16 * 112) + ks * 32;
                LDSM4(ah[mi], addr);
                LDSM4(al[mi], addr + MAT_BYTES8);
            }
#pragma unroll
            for (int b2 = 0; b2 < 2; b2++) {
                uint32_t bh[4], bl[4];
                uint32_t baddr = st + 2 * MAT_BYTES8 + b_off + b2 * (16 * 112) + ks * 32;
                LDSM4(bh, baddr);
                LDSM4(bl, baddr + MAT_BYTES8);
#pragma unroll
                for (int p = 0; p < 3; p++) {
#pragma unroll
                    for (int mi = 0; mi < 4; mi++) {
#pragma unroll
                        for (int hf = 0; hf < 2; hf++) {
                            const int nt = b2 * 2 + hf;
                            const uint32_t* A_ = (p == 2) ? al[mi] : ah[mi];
                            const uint32_t* B_ = (p == 1) ? bl : bh;
                            hmma(acc[mi][nt], A_, B_ + hf * 2);
                        }
                    }
                }
            }
        }
        __syncthreads();
    }

    const int g = lane >> 2, c2 = lane & 3;
#pragma unroll
    for (int mi = 0; mi < 4; mi++) {
        const int r = row0 + warp_m * 64 + mi * 16 + g;
#pragma unroll
        for (int nt = 0; nt < 4; nt++) {
            const int col = col0 + warp_n * 32 + nt * 8 + c2 * 2;
            if (col < N) {
                *(float2*)(C + (size_t)r * N + col)       = make_float2(acc[mi][nt][0], acc[mi][nt][1]);
                *(float2*)(C + (size_t)(r + 8) * N + col) = make_float2(acc[mi][nt][2], acc[mi][nt][3]);
            }
        }
    }
}

// ---------------- compressed tokens ----------------
__global__ void compress_kernel(const float* __restrict__ wck,
                                const float* __restrict__ wcv,
                                const float* __restrict__ pe)
{
    const int m = blockIdx.x, h = blockIdx.y, d = threadIdx.x;  // 64 threads
    float a = 0.f, b = 0.f;
    for (int t = 0; t < 64; t++) {
        const float wk = wck[h * 64 + t];
        const float wv = wcv[h * 64 + t];
        const int row = m * 64 + t;
        a = fmaf(g_kvg[row * 352 + h * 64 + d] + pe[(h * 64 + t) * 64 + d], wk, a);
        b = fmaf(g_kvg[row * 352 + 128 + h * 64 + d], wv, b);
    }
    g_ck[(m * 2 + h) * 64 + d] = a;
    g_cv[(m * 2 + h) * 64 + d] = b;
}

// ---------------- compressed attention + top-k, 4 tokens per CTA ----------------
__global__ void __launch_bounds__(512) comp_attn_kernel(int ntok)
{
    const int n0 = blockIdx.x * 4, h = blockIdx.y;
    const int tid = threadIdx.x;
    const int tq = tid >> 7, ltid = tid & 127;
    const int M = ntok >> 6;
    __shared__ float  sq[4096];
    __shared__ float2 ckp[32 * 33];
    __shared__ float  scv[MMAX * 64];
    __shared__ float  lg[4 * 512];
    __shared__ float  ssum[4 * 32];

    for (int i = tid; i < 4096; i += 512) {
        int q = i >> 10;
        sq[i] = g_q[(n0 + q) * 2048 + h * 1024 + (i & 1023)] * 0.125f;
    }
    for (int i = tid; i < M * 32; i += 512) {
        int m = i >> 5, d2 = i & 31;
        ckp[d2 * 33 + m] = *(const float2*)&g_ck[(m * 2 + h) * 64 + 2 * d2];
    }
    for (int i = tid; i < M * 64; i += 512)
        scv[i] = g_cv[((i >> 6) * 2 + h) * 64 + (i & 63)];
    __syncthreads();

    const int n = n0 + tq;
    const int mvis = (n >= 63) ? (((n - 63) >> 6) + 1) : 0;

#pragma unroll
    for (int i = 0; i < 4; i++) {
        int e = ltid + i * 128;
        int g = e >> 5, m = e & 31;
        unsigned long long acc = 0ull;
#pragma unroll
        for (int d2 = 0; d2 < 32; d2++) {
            unsigned long long qp = pk2f2(*(const float2*)&sq[tq * 1024 + g * 64 + 2 * d2]);
            acc = fma2(qp, pk2f2(ckp[d2 * 33 + m]), acc);
        }
        float x, y; upk2(acc, x, y);
        lg[tq * 512 + g * 32 + m] = x + y;
    }
    __syncthreads();

    if (ltid < 16) {
        float* row = lg + tq * 512 + ltid * 32;
        if (mvis == 0) {
            for (int m = 0; m < M; m++) row[m] = 0.f;
        } else {
            float mx = -INFINITY;
            for (int m = 0; m < mvis; m++) mx = fmaxf(mx, row[m]);
            float s = 0.f;
            for (int m = 0; m < mvis; m++) {
                float p = __expf(row[m] - mx);
                row[m] = p; s += p;
            }
            const float inv = 1.f / s;
            for (int m = 0; m < mvis; m++) row[m] *= inv;
            for (int m = mvis; m < M; m++) row[m] = 0.f;
        }
    }
    __syncthreads();

#pragma unroll
    for (int i = 0; i < 4; i++) {
        int e2 = ltid + i * 128;
        int g = e2 >> 5, d2 = e2 & 31;
        unsigned long long acc = 0ull;
        for (int m = 0; m < mvis; m++) {
            float p = lg[tq * 512 + g * 32 + m];
            acc = fma2(pk2(p, p), pk2f2(*(const float2*)&scv[m * 64 + 2 * d2]), acc);
        }
        float x, y; upk2(acc, x, y);
        *(float2*)&g_comp[n * 2048 + h * 1024 + g * 64 + 2 * d2] = make_float2(x, y);
    }

    if (ltid < 32) {
        float s = 0.f;
        if (ltid < M)
            for (int g = 0; g < 16; g++) s += lg[tq * 512 + g * 32 + ltid];
        ssum[tq * 32 + ltid] = s;
    }
    __syncthreads();

    if (ltid == 0) {
        const int qblk = n >> 6;
        unsigned sel = 0;
        if (qblk + 1 <= 16) {
            sel = (1u << (qblk + 1)) - 1u;
        } else {
            float sc[32];
            for (int m = 0; m < 32; m++) {
                if (m > qblk)                                  sc[m] = -INFINITY;
                else if (m == 0 || m == qblk || m == qblk - 1) sc[m] = INFINITY;
                else                                           sc[m] = ssum[tq * 32 + m];
            }
            for (int t = 0; t < 16; t++) {
                int best = 0; float bv = -INFINITY;
                for (int m = 0; m < 32; m++) {
                    if ((sel >> m) & 1u) continue;
                    if (sc[m] > bv) { bv = sc[m]; best = m; }
                }
                sel |= 1u << best;
            }
        }
        g_sel[n * 2 + h] = sel;
    }
}

// ---------------- main attention on tensor cores (branch-activity skipping) ----------------
#define BST 72          // bf16 smem row stride (elements) = 144 bytes
#define SQH 0
#define SQL 9216
#define SKH 18432
#define SKL 27648
#define SVTH 36864
#define SVTL 46080
#define PSH 55296
#define PSL 64512
#define PWH 73728
#define PWL 82944
#define LG_OFF 92160    // float [64][66]
#define PM_OFF 109056   // float [512]
#define HMM_OFF 111104  // float [2][64]
#define HLL_OFF 111616
#define HRR_OFF 112128
#define ATTN_SMEM 112640

__global__ void __launch_bounds__(256, 2) main_attn_kernel(int ntok)
{
    extern __shared__ char dsm[];
    const uint32_t sb = smem_u32(dsm);
    float* lg  = (float*)(dsm + LG_OFF);
    float* pm  = (float*)(dsm + PM_OFF);
    float* hmm = (float*)(dsm + HMM_OFF);
    float* hll = (float*)(dsm + HLL_OFF);
    float* hrr = (float*)(dsm + HRR_OFF);

    const int n0 = blockIdx.x * 4, h = blockIdx.y;
    const int tid = threadIdx.x;
    const int lane = tid & 31, wid = tid >> 5;
    const int warp_m = wid & 1, warp_n = wid >> 1;
    const int g = lane >> 2, cq = lane & 3;

    for (int i = tid; i < 4096; i += 256) {
        int r = i >> 6, d = i & 63;
        float v = g_q[(n0 + (r >> 4)) * 2048 + h * 1024 + (r & 15) * 64 + d] * 0.125f;
        unsigned short hi, lo;
        bsplit(v, hi, lo);
        *(unsigned short*)(dsm + SQH + (r * BST + d) * 2) = hi;
        *(unsigned short*)(dsm + SQL + (r * BST + d) * 2) = lo;
    }
    if (tid < 128) { hmm[tid] = -INFINITY; hll[tid] = 0.f; }

    const unsigned sel0 = g_sel[n0 * 2 + h],       sel1 = g_sel[(n0 + 1) * 2 + h],
                   sel2 = g_sel[(n0 + 2) * 2 + h], sel3 = g_sel[(n0 + 3) * 2 + h];
    const unsigned selU = sel0 | sel1 | sel2 | sel3;
    const int qblk = n0 >> 6;

    const int mt = lane >> 3, rin = lane & 7;
    const uint32_t a_base = (uint32_t)(((mt & 1) * 8 + rin) * 144 + ((mt >> 1) * 8) * 2);
    const uint32_t b_base = (uint32_t)((warp_n * 16 + ((mt >= 2) ? 8 : 0) + rin) * 144 + ((mt & 1) * 8) * 2);

    float acc_s[2][2][4] = {}, acc_w[2][2][4] = {};

    __syncthreads();

    for (int c = 0; c <= qblk; c++) {
        const int base = n0 - c * 64;
        const bool wact = (base - 512) <= 63;          // window branch active (any token)
        const bool sact = (selU >> c) & 1u;            // sparse branch active (any token)
        if (!sact && !wact) continue;

        for (int i = tid; i < 2048; i += 256) {
            int mat = i >> 9, idx = i & 511;
            int row = idx >> 3, c16 = idx & 7;
            const __nv_bfloat16* src;
            if (mat == 0)      src = g_kbh + (size_t)(c * 64 + row) * 128 + h * 64 + c16 * 8;
            else if (mat == 1) src = g_kbl + (size_t)(c * 64 + row) * 128 + h * 64 + c16 * 8;
            else if (mat == 2) src = g_vth + (size_t)(h * 64 + row) * TMAX + c * 64 + c16 * 8;
            else               src = g_vtl + (size_t)(h * 64 + row) * TMAX + c * 64 + c16 * 8;
            *(uint4*)(dsm + SKH + mat * 9216 + row * 144 + c16 * 16) = *(const uint4*)src;
        }
        __syncthreads();

        // ---- S = Q K^T via HMMA (3-product) ----
        {
            float acc[2][2][4] = {};
#pragma unroll
            for (int ks = 0; ks < 4; ks++) {
                uint32_t kh[4], kl[4];
                LDSM4(kh, sb + SKH + b_base + ks * 32);
                LDSM4(kl, sb + SKL + b_base + ks * 32);
#pragma unroll
                for (int mi = 0; mi < 2; mi++) {
                    uint32_t qh[4], ql[4];
                    const uint32_t ao = (uint32_t)((warp_m * 32 + mi * 16) * 144) + a_base + ks * 32;
                    LDSM4(qh, sb + SQH + ao);
                    LDSM4(ql, sb + SQL + ao);
#pragma unroll
                    for (int hf = 0; hf < 2; hf++) {
                        hmma(acc[mi][hf], qh, kh + hf * 2);
                        hmma(acc[mi][hf], qh, kl + hf * 2);
                        hmma(acc[mi][hf], ql, kh + hf * 2);
                    }
                }
            }
#pragma unroll
            for (int mi = 0; mi < 2; mi++) {
                const int r0 = warp_m * 32 + mi * 16 + g;
#pragma unroll
                for (int hf = 0; hf < 2; hf++) {
                    const int col = warp_n * 16 + hf * 8 + cq * 2;
                    *(float2*)&lg[r0 * 66 + col]       = make_float2(acc[mi][hf][0], acc[mi][hf][1]);
                    *(float2*)&lg[(r0 + 8) * 66 + col] = make_float2(acc[mi][hf][2], acc[mi][hf][3]);
                }
            }
        }
        __syncthreads();

        // ---- segmented max (branch-guarded) ----
        {
            const int r = tid >> 2, seg = tid & 3;
            const int q = r >> 4;
            const int jn = min(63, base + q);
            if (sact) {
                const unsigned selq = (q == 0) ? sel0 : (q == 1) ? sel1 : (q == 2) ? sel2 : sel3;
                float ms = -INFINITY;
                if ((selq >> c) & 1u) {
                    const int hi2 = min(seg * 16 + 15, jn);
                    for (int j = seg * 16; j <= hi2; j++) ms = fmaxf(ms, lg[r * 66 + j]);
                }
                pm[tid] = ms;
            }
            if (wact) {
                const int jw0 = base + q - 512;
                float mw = -INFINITY;
                if (jw0 <= 63) {
                    const int lo2 = max(seg * 16, jw0);
                    const int hi2 = min(seg * 16 + 15, jn);
                    for (int j = lo2; j <= hi2; j++) mw = fmaxf(mw, lg[r * 66 + j]);
                }
                pm[256 + tid] = mw;
            }
        }
        __syncthreads();
        if (tid < 128) {
            const int br = tid >> 6, r = tid & 63;
            const bool act = br ? wact : sact;
            if (act) {
                const float* p = pm + br * 256 + r * 4;
                const float cm = fmaxf(fmaxf(p[0], p[1]), fmaxf(p[2], p[3]));
                const float om = hmm[br * 64 + r];
                const float nm = fmaxf(om, cm);
                hmm[br * 64 + r] = nm;
                hrr[br * 64 + r] = (cm == -INFINITY) ? 1.f : __expf(om - nm);
            } else {
                hrr[br * 64 + r] = 1.f;
            }
        }
        __syncthreads();

        // ---- exp + partial sums + split-bf16 P store (branch-guarded) ----
        {
            const int r = tid >> 2, seg = tid & 3;
            const int q = r >> 4;
            const int jn = base + q;
            const uint32_t po = (uint32_t)((r * BST + seg * 16) * 2);
            if (sact) {
                const unsigned selq = (q == 0) ? sel0 : (q == 1) ? sel1 : (q == 2) ? sel2 : sel3;
                const bool srow = (selq >> c) & 1u;
                const float ms = hmm[r];
                float ss = 0.f;
                unsigned short eh[16], el[16];
#pragma unroll
                for (int jj = 0; jj < 16; jj++) {
                    const int j = seg * 16 + jj;
                    float es = (srow && j <= jn) ? __expf(lg[r * 66 + j] - ms) : 0.f;
                    ss += es;
                    bsplit(es, eh[jj], el[jj]);
                }
                pm[tid] = ss;
#pragma unroll
                for (int v4 = 0; v4 < 4; v4++) {
                    *(ushort4*)(dsm + PSH + po + v4 * 8) = make_ushort4(eh[v4*4], eh[v4*4+1], eh[v4*4+2], eh[v4*4+3]);
                    *(ushort4*)(dsm + PSL + po + v4 * 8) = make_ushort4(el[v4*4], el[v4*4+1], el[v4*4+2], el[v4*4+3]);
                }
            }
            if (wact) {
                const int jw0 = base + q - 512;
                const float mw = hmm[64 + r];
                float sw = 0.f;
                unsigned short wh[16], wl[16];
#pragma unroll
                for (int jj = 0; jj < 16; jj++) {
                    const int j = seg * 16 + jj;
                    float ew = (j <= jn && j >= jw0) ? __expf(lg[r * 66 + j] - mw) : 0.f;
                    sw += ew;
                    bsplit(ew, wh[jj], wl[jj]);
                }
                pm[256 + tid] = sw;
#pragma unroll
                for (int v4 = 0; v4 < 4; v4++) {
                    *(ushort4*)(dsm + PWH + po + v4 * 8) = make_ushort4(wh[v4*4], wh[v4*4+1], wh[v4*4+2], wh[v4*4+3]);
                    *(ushort4*)(dsm + PWL + po + v4 * 8) = make_ushort4(wl[v4*4], wl[v4*4+1], wl[v4*4+2], wl[v4*4+3]);
                }
            }
        }
        __syncthreads();
        if (tid < 128) {
            const int br = tid >> 6, r = tid & 63;
            const bool act = br ? wact : sact;
            if (act) {
                const float* p = pm + br * 256 + r * 4;
                hll[br * 64 + r] = hll[br * 64 + r] * hrr[br * 64 + r]
                                 + (p[0] + p[1]) + (p[2] + p[3]);
            }
        }

        // ---- PV via HMMA with flash rescale (branch-guarded) ----
        if (sact) {
#pragma unroll
            for (int mi = 0; mi < 2; mi++) {
                const int rb = warp_m * 32 + mi * 16 + g;
                const float rs0 = hrr[rb], rs1 = hrr[rb + 8];
#pragma unroll
                for (int hf = 0; hf < 2; hf++) {
                    acc_s[mi][hf][0] *= rs0; acc_s[mi][hf][1] *= rs0;
                    acc_s[mi][hf][2] *= rs1; acc_s[mi][hf][3] *= rs1;
                }
            }
        }
        if (wact) {
#pragma unroll
            for (int mi = 0; mi < 2; mi++) {
                const int rb = warp_m * 32 + mi * 16 + g;
                const float rw0 = hrr[64 + rb], rw1 = hrr[64 + rb + 8];
#pragma unroll
                for (int hf = 0; hf < 2; hf++) {
                    acc_w[mi][hf][0] *= rw0; acc_w[mi][hf][1] *= rw0;
                    acc_w[mi][hf][2] *= rw1; acc_w[mi][hf][3] *= rw1;
                }
            }
        }
#pragma unroll
        for (int ks = 0; ks < 4; ks++) {
            uint32_t vh[4], vl[4];
            LDSM4(vh, sb + SVTH + b_base + ks * 32);
            LDSM4(vl, sb + SVTL + b_base + ks * 32);
#pragma unroll
            for (int mi = 0; mi < 2; mi++) {
                const uint32_t ao = (uint32_t)((warp_m * 32 + mi * 16) * 144) + a_base + ks * 32;
                if (sact) {
                    uint32_t ph[4], pl[4];
                    LDSM4(ph, sb + PSH + ao);
                    LDSM4(pl, sb + PSL + ao);
#pragma unroll
                    for (int hf = 0; hf < 2; hf++) {
                        hmma(acc_s[mi][hf], ph, vh + hf * 2);
                        hmma(acc_s[mi][hf], ph, vl + hf * 2);
                        hmma(acc_s[mi][hf], pl, vh + hf * 2);
                    }
                }
                if (wact) {
                    uint32_t ph[4], pl[4];
                    LDSM4(ph, sb + PWH + ao);
                    LDSM4(pl, sb + PWL + ao);
#pragma unroll
                    for (int hf = 0; hf < 2; hf++) {
                        hmma(acc_w[mi][hf], ph, vh + hf * 2);
                        hmma(acc_w[mi][hf], ph, vl + hf * 2);
                        hmma(acc_w[mi][hf], pl, vh + hf * 2);
                    }
                }
            }
        }
        __syncthreads();
    }

    // ---- gated fusion epilogue ----
#pragma unroll
    for (int mi = 0; mi < 2; mi++) {
#pragma unroll
        for (int half = 0; half < 2; half++) {
            const int r = warp_m * 32 + mi * 16 + g + half * 8;
            const int nq = n0 + (r >> 4);
            const int head = r & 15;
            const int hq = h * 16 + head;
            const float gl0 = g_kvg[nq * 352 + 256 + hq * 3 + 0];
            const float gl1 = g_kvg[nq * 352 + 256 + hq * 3 + 1];
            const float gl2 = g_kvg[nq * 352 + 256 + hq * 3 + 2];
            const float g0 = 1.f / (1.f + __expf(-gl0));
            const float g1 = 1.f / (1.f + __expf(-gl1));
            const float g2 = 1.f / (1.f + __expf(-gl2));
            const float inv_s = 1.f / hll[r];
            const float inv_w = 1.f / hll[64 + r];
#pragma unroll
            for (int hf = 0; hf < 2; hf++) {
                const int col = warp_n * 16 + hf * 8 + cq * 2;
                const int oi = nq * 2048 + h * 1024 + head * 64 + col;
                const float2 cmp = *(const float2*)&g_comp[oi];
                const float o0 = g0 * cmp.x + g1 * acc_s[mi][hf][half * 2]     * inv_s
                                            + g2 * acc_w[mi][hf][half * 2]     * inv_w;
                const float o1 = g0 * cmp.y + g1 * acc_s[mi][hf][half * 2 + 1] * inv_s
                                            + g2 * acc_w[mi][hf][half * 2 + 1] * inv_w;
                ushort2 hh, ll;
                bsplit(o0, hh.x, ll.x);
                bsplit(o1, hh.y, ll.y);
                *(ushort2*)(g_fh + oi) = hh;
                *(ushort2*)(g_fl + oi) = ll;
            }
        }
    }
}

// ---------------- launch ----------------
extern "C" void kernel_launch(void* const* d_in, const int* in_sizes, int n_in,
                              void* d_out, int out_size)
{
    const float* x   = (const float*)d_in[0];
    const float* Wq  = (const float*)d_in[2];
    const float* Wk  = (const float*)d_in[3];
    const float* Wv  = (const float*)d_in[4];
    const float* Wo  = (const float*)d_in[5];
    const float* Wg  = (const float*)d_in[6];
    const float* wck = (const float*)d_in[7];
    const float* wcv = (const float*)d_in[8];
    const float* pe  = (const float*)d_in[9];
    float* out = (float*)d_out;

    const int ntok = in_sizes[0] / 2048;     // T = 2048
    const int M = ntok / 64;

    float *q, *kvg;
    cudaGetSymbolAddress((void**)&q,   g_q);
    cudaGetSymbolAddress((void**)&kvg, g_kvg);

    __nv_bfloat16 *xh, *xl, *fh, *fl, *wqh, *wql, *woh, *wol, *wkvgh, *wkvgl;
    cudaGetSymbolAddress((void**)&xh, g_xh);     cudaGetSymbolAddress((void**)&xl, g_xl);
    cudaGetSymbolAddress((void**)&fh, g_fh);     cudaGetSymbolAddress((void**)&fl, g_fl);
    cudaGetSymbolAddress((void**)&wqh, g_wqt_h); cudaGetSymbolAddress((void**)&wql, g_wqt_l);
    cudaGetSymbolAddress((void**)&woh, g_wot_h); cudaGetSymbolAddress((void**)&wol, g_wot_l);
    cudaGetSymbolAddress((void**)&wkvgh, g_wkvgt_h);
    cudaGetSymbolAddress((void**)&wkvgl, g_wkvgt_l);

    cudaFuncSetAttribute(mma_gemm, cudaFuncAttributeMaxDynamicSharedMemorySize, SMEM_GEMM);
    cudaFuncSetAttribute(mma_gemm128, cudaFuncAttributeMaxDynamicSharedMemorySize, SMEM_GEMM8);
    cudaFuncSetAttribute(main_attn_kernel, cudaFuncAttributeMaxDynamicSharedMemorySize, ATTN_SMEM);

    const int tot = ntok * 2048;
    dim3 tb(32, 8);

    split_fp32<<<(tot / 4 + 255) / 256, 256>>>((const float4*)x, xh, xl, tot / 4);                // 0
    transpose_split<<<dim3(64, 64), tb>>>(Wq, wqh, wql, 2048, 2048);                              // 1
    transpose_split<<<dim3(4,  64), tb>>>(Wk, wkvgh,              wkvgl,              2048, 128); // 2
    mma_gemm<<<dim3(8, ntok / 128), 512, SMEM_GEMM>>>(xh, xl, wqh, wql, q, ntok, 2048, 2048);     // 3 <- ncu
    transpose_split<<<dim3(4,  64), tb>>>(Wv, wkvgh + 128 * 2048, wkvgl + 128 * 2048, 2048, 128); // 4
    transpose_split<<<dim3(3,  64), tb>>>(Wg, wkvgh + 256 * 2048, wkvgl + 256 * 2048, 2048, 96);  // 5
    mma_gemm128<<<dim3(3, ntok / 128), 256, SMEM_GEMM8>>>(xh, xl, wkvgh, wkvgl, kvg, ntok, 352, 2048);

    kv_prep<<<dim3(ntok / 32, 2, 2), tb>>>(ntok);
    compress_kernel<<<dim3(M, 2), 64>>>(wck, wcv, pe);
    comp_attn_kernel<<<dim3(ntok / 4, 2), 512>>>(ntok);
    main_attn_kernel<<<dim3(ntok / 4, 2), 256, ATTN_SMEM>>>(ntok);

    transpose_split<<<dim3(64, 64), tb>>>(Wo, woh, wol, 2048, 2048);
    mma_gemm<<<dim3(8, ntok / 128), 512, SMEM_GEMM>>>(fh, fl, woh, wol, out, ntok, 2048, 2048);
}

// round 12
// speedup vs baseline: 1.2284x; 1.1175x over previous
#include <cuda_runtime.h>
#include <cuda_bf16.h>
#include <math.h>
#include <stdint.h>

// Problem constants (T=2048, H=2048, HQ=32, HKV=2, D=64, G=16, M<=32)
#define TMAX 2048
#define MMAX 32

// ---------------- scratch (no allocation allowed) ----------------
__device__ float    g_q[TMAX * 2048];      // [n, HQ*D]
__device__ float    g_kvg[TMAX * 352];     // [n, k(128) | v(128) | gate(96)]
__device__ float    g_ck[MMAX * 2 * 64];
__device__ float    g_cv[MMAX * 2 * 64];
__device__ float    g_comp[TMAX * 2048];
__device__ unsigned g_sel[TMAX * 2];

// bf16 split operands
__device__ __nv_bfloat16 g_xh[2048 * 2048], g_xl[2048 * 2048];
__device__ __nv_bfloat16 g_fh[2048 * 2048], g_fl[2048 * 2048];
__device__ __nv_bfloat16 g_wqt_h[2048 * 2048], g_wqt_l[2048 * 2048];   // Wq^T [N,K]
__device__ __nv_bfloat16 g_wot_h[2048 * 2048], g_wot_l[2048 * 2048];   // Wo^T
__device__ __nv_bfloat16 g_wkvgt_h[352 * 2048], g_wkvgt_l[352 * 2048]; // [Wk|Wv|Wg]^T
// attention K / V^T split-bf16
__device__ __nv_bfloat16 g_kbh[TMAX * 128], g_kbl[TMAX * 128];          // [n][h][64]
__device__ __nv_bfloat16 g_vth[2 * 64 * TMAX], g_vtl[2 * 64 * TMAX];    // [h][d][n]

__device__ __forceinline__ uint32_t smem_u32(const void* p) {
    uint32_t a;
    asm("{ .reg .u64 t; cvta.to.shared.u64 t, %1; cvt.u32.u64 %0, t; }" : "=r"(a) : "l"(p));
    return a;
}

// ---------------- packed f32x2 helpers ----------------
__device__ __forceinline__ unsigned long long pk2(float x, float y) {
    unsigned long long r;
    asm("mov.b64 %0, {%1,%2};" : "=l"(r) : "f"(x), "f"(y));
    return r;
}
__device__ __forceinline__ unsigned long long pk2f2(float2 v) { return pk2(v.x, v.y); }
__device__ __forceinline__ void upk2(unsigned long long r, float& x, float& y) {
    asm("mov.b64 {%0,%1}, %2;" : "=f"(x), "=f"(y) : "l"(r));
}
__device__ __forceinline__ unsigned long long fma2(unsigned long long a,
                                                   unsigned long long b,
                                                   unsigned long long c) {
    unsigned long long d;
    asm("fma.rn.f32x2 %0, %1, %2, %3;" : "=l"(d) : "l"(a), "l"(b), "l"(c));
    return d;
}

// ---------------- mma helpers ----------------
#define LDSM4(r, addr) \
    asm volatile("ldmatrix.sync.aligned.m8n8.x4.shared.b16 {%0,%1,%2,%3}, [%4];" \
                 : "=r"((r)[0]), "=r"((r)[1]), "=r"((r)[2]), "=r"((r)[3]) : "r"(addr))

__device__ __forceinline__ void hmma(float* c, const uint32_t* a, const uint32_t* b) {
    asm volatile("mma.sync.aligned.m16n8k16.row.col.f32.bf16.bf16.f32 "
                 "{%0,%1,%2,%3},{%4,%5,%6,%7},{%8,%9},{%0,%1,%2,%3};"
                 : "+f"(c[0]), "+f"(c[1]), "+f"(c[2]), "+f"(c[3])
                 : "r"(a[0]), "r"(a[1]), "r"(a[2]), "r"(a[3]), "r"(b[0]), "r"(b[1]));
}

__device__ __forceinline__ void bsplit(float v, unsigned short& hi, unsigned short& lo) {
    __nv_bfloat16 h = __float2bfloat16(v);
    __nv_bfloat16 l = __float2bfloat16(v - __bfloat162float(h));
    hi = *(unsigned short*)&h; lo = *(unsigned short*)&l;
}

// ================= prep kernels =================
__global__ void split_fp32(const float4* __restrict__ A,
                           __nv_bfloat16* __restrict__ Ah,
                           __nv_bfloat16* __restrict__ Al, int total4)
{
    int i = blockIdx.x * 256 + threadIdx.x;
    if (i < total4) {
        float4 v = A[i];
        ushort4 hh, ll;
        bsplit(v.x, hh.x, ll.x); bsplit(v.y, hh.y, ll.y);
        bsplit(v.z, hh.z, ll.z); bsplit(v.w, hh.w, ll.w);
        *(ushort4*)(Ah + 4 * (size_t)i) = hh;
        *(ushort4*)(Al + 4 * (size_t)i) = ll;
    }
}

__global__ void transpose_split(const float* __restrict__ W,
                                __nv_bfloat16* __restrict__ Th,
                                __nv_bfloat16* __restrict__ Tl, int K, int N)
{
    __shared__ float t[32][33];
    const int k0 = blockIdx.y * 32, n0 = blockIdx.x * 32;
    const int tx = threadIdx.x, ty = threadIdx.y;  // 32 x 8
    for (int i = ty; i < 32; i += 8) {
        int k = k0 + i, n = n0 + tx;
        t[i][tx] = (n < N && k < K) ? W[(size_t)k * N + n] : 0.f;
    }
    __syncthreads();
    for (int i = ty; i < 32; i += 8) {
        int n = n0 + i, k = k0 + tx;
        if (n < N && k < K) {
            unsigned short hi, lo;
            bsplit(t[tx][i], hi, lo);
            *(unsigned short*)(Th + (size_t)n * K + k) = hi;
            *(unsigned short*)(Tl + (size_t)n * K + k) = lo;
        }
    }
}

// K split + V transpose-split. grid (n/32, 2, 2), block (32,8)
__global__ void kv_prep(int ntok)
{
    __shared__ float t[32][33];
    const int n0 = blockIdx.x * 32, h = blockIdx.y, dh = blockIdx.z * 32;
    const int tx = threadIdx.x, ty = threadIdx.y;
    for (int i = ty; i < 32; i += 8) {
        const int n = n0 + i, d = dh + tx;
        float kv = g_kvg[n * 352 + h * 64 + d];
        unsigned short hi, lo;
        bsplit(kv, hi, lo);
        *(unsigned short*)(g_kbh + n * 128 + h * 64 + d) = hi;
        *(unsigned short*)(g_kbl + n * 128 + h * 64 + d) = lo;
        t[i][tx] = g_kvg[n * 352 + h * 64 + 128 + d];
    }
    __syncthreads();
    for (int i = ty; i < 32; i += 8) {
        const int d = dh + i, n = n0 + tx;
        unsigned short hi, lo;
        bsplit(t[tx][i], hi, lo);
        *(unsigned short*)(g_vth + (h * 64 + d) * TMAX + n) = hi;
        *(unsigned short*)(g_vtl + (h * 64 + d) * TMAX + n) = lo;
    }
}

// ================= split-bf16 GEMM, 128x256 tile, 512 threads (big GEMMs) =================
#define A_MAT 14336
#define B_MAT 28672
#define STAGE_BYTES 86016
#define SMEM_GEMM (2 * STAGE_BYTES)

__global__ void __launch_bounds__(512) mma_gemm(
    const __nv_bfloat16* __restrict__ Ah, const __nv_bfloat16* __restrict__ Al,
    const __nv_bfloat16* __restrict__ Bth, const __nv_bfloat16* __restrict__ Btl,
    float* __restrict__ C, int M, int N, int K)
{
    extern __shared__ char smem[];
    const uint32_t sb = smem_u32(smem);
    const int tid = threadIdx.x;
    const int lane = tid & 31, wid = tid >> 5;
    const int warp_m = wid & 1, warp_n = wid >> 1;   // 2 x 8 warps
    const int row0 = blockIdx.y * 128, col0 = blockIdx.x * 256;
    const int nchunk = K >> 5;

    float acc[4][4][4];
#pragma unroll
    for (int a = 0; a < 4; a++)
#pragma unroll
        for (int b = 0; b < 4; b++)
#pragma unroll
            for (int c = 0; c < 4; c++) acc[a][b][c] = 0.f;

    const int mt = lane >> 3, rin = lane & 7;
    const uint32_t a_off = (uint32_t)((warp_m * 64 + (mt & 1) * 8 + rin) * 112 + ((mt >> 1) * 8) * 2);
    const uint32_t b_off = (uint32_t)((warp_n * 32 + ((mt >= 2) ? 8 : 0) + rin) * 112 + ((mt & 1) * 8) * 2);

    auto load_chunk = [&](int c) {
        const int k0 = c * 32;
        const uint32_t st = sb + (uint32_t)(c & 1) * STAGE_BYTES;
#pragma unroll
        for (int i = 0; i < 6; i++) {
            int v = tid + i * 512;
            uint32_t dst;
            const __nv_bfloat16* srcp;
            int sz = 16;
            if (v < 1024) {
                int mat = v >> 9, r = (v >> 2) & 127, c16 = v & 3;
                dst = st + mat * A_MAT + r * 112 + c16 * 16;
                srcp = (mat ? Al : Ah) + (size_t)(row0 + r) * K + k0 + c16 * 8;
            } else {
                int vb = v - 1024;
                int mat = vb >> 10, r = (vb >> 2) & 255, c16 = vb & 3;
                dst = st + 2 * A_MAT + mat * B_MAT + r * 112 + c16 * 16;
                int n = col0 + r;
                int nn = (n < N) ? n : 0;
                if (n >= N) sz = 0;
                srcp = (mat ? Btl : Bth) + (size_t)nn * K + k0 + c16 * 8;
            }
            asm volatile("cp.async.cg.shared.global [%0], [%1], 16, %2;"
                         :: "r"(dst), "l"(srcp), "r"(sz));
        }
        asm volatile("cp.async.commit_group;" ::: "memory");
    };

    load_chunk(0);

    for (int c = 0; c < nchunk; c++) {
        if (c + 1 < nchunk) {
            load_chunk(c + 1);
            asm volatile("cp.async.wait_group 1;" ::: "memory");
        } else {
            asm volatile("cp.async.wait_group 0;" ::: "memory");
        }
        __syncthreads();

        const uint32_t st = sb + (uint32_t)(c & 1) * STAGE_BYTES;
#pragma unroll
        for (int ks = 0; ks < 2; ks++) {
            uint32_t ah[4][4], al[4][4];
#pragma unroll
            for (int mi = 0; mi < 4; mi++) {
                uint32_t addr = st + a_off + mi * (16 * 112) + ks * 32;
                LDSM4(ah[mi], addr);
                LDSM4(al[mi], addr + A_MAT);
            }
#pragma unroll
            for (int b2 = 0; b2 < 2; b2++) {
                uint32_t bh[4], bl[4];
                uint32_t baddr = st + 2 * A_MAT + b_off + b2 * (16 * 112) + ks * 32;
                LDSM4(bh, baddr);
                LDSM4(bl, baddr + B_MAT);
#pragma unroll
                for (int p = 0; p < 3; p++) {
#pragma unroll
                    for (int mi = 0; mi < 4; mi++) {
#pragma unroll
                        for (int hf = 0; hf < 2; hf++) {
                            const int nt = b2 * 2 + hf;
                            const uint32_t* A_ = (p == 2) ? al[mi] : ah[mi];
                            const uint32_t* B_ = (p == 1) ? bl : bh;
                            hmma(acc[mi][nt], A_, B_ + hf * 2);
                        }
                    }
                }
            }
        }
        __syncthreads();
    }

    const int g = lane >> 2, c2 = lane & 3;
#pragma unroll
    for (int mi = 0; mi < 4; mi++) {
        const int r = row0 + warp_m * 64 + mi * 16 + g;
#pragma unroll
        for (int nt = 0; nt < 4; nt++) {
            const int col = col0 + warp_n * 32 + nt * 8 + c2 * 2;
            if (col < N) {
                *(float2*)(C + (size_t)r * N + col)       = make_float2(acc[mi][nt][0], acc[mi][nt][1]);
                *(float2*)(C + (size_t)(r + 8) * N + col) = make_float2(acc[mi][nt][2], acc[mi][nt][3]);
            }
        }
    }
}

// ================= split-bf16 GEMM, 128x128 tile, 256 threads (narrow GEMMs) =================
#define MAT_BYTES8  (128 * 112)
#define STAGE8 (4 * MAT_BYTES8)
#define SMEM_GEMM8 (2 * STAGE8)

__global__ void __launch_bounds__(256) mma_gemm128(
    const __nv_bfloat16* __restrict__ Ah, const __nv_bfloat16* __restrict__ Al,
    const __nv_bfloat16* __restrict__ Bth, const __nv_bfloat16* __restrict__ Btl,
    float* __restrict__ C, int M, int N, int K)
{
    extern __shared__ char smem[];
    const uint32_t sb = smem_u32(smem);
    const int tid = threadIdx.x;
    const int lane = tid & 31, wid = tid >> 5;
    const int warp_m = wid & 1, warp_n = wid >> 1;
    const int row0 = blockIdx.y * 128, col0 = blockIdx.x * 128;
    const int nchunk = K >> 5;

    float acc[4][4][4];
#pragma unroll
    for (int a = 0; a < 4; a++)
#pragma unroll
        for (int b = 0; b < 4; b++)
#pragma unroll
            for (int c = 0; c < 4; c++) acc[a][b][c] = 0.f;

    const int mt = lane >> 3, rin = lane & 7;
    const uint32_t a_off = (uint32_t)((warp_m * 64 + (mt & 1) * 8 + rin) * 112 + ((mt >> 1) * 8) * 2);
    const uint32_t b_off = (uint32_t)((warp_n * 32 + ((mt >= 2) ? 8 : 0) + rin) * 112 + ((mt & 1) * 8) * 2);

    auto load_chunk = [&](int c) {
        const int k0 = c * 32;
        const uint32_t st = sb + (uint32_t)(c & 1) * STAGE8;
#pragma unroll
        for (int i = 0; i < 8; i++) {
            int v = tid + i * 256;
            int mat = v >> 9, r = (v >> 2) & 127, c16 = v & 3;
            uint32_t dst = st + mat * MAT_BYTES8 + r * 112 + c16 * 16;
            const __nv_bfloat16* srcp;
            int sz = 16;
            if (mat == 0)      srcp = Ah + (size_t)(row0 + r) * K + k0 + c16 * 8;
            else if (mat == 1) srcp = Al + (size_t)(row0 + r) * K + k0 + c16 * 8;
            else {
                int n = col0 + r;
                int nn = (n < N) ? n : 0;
                if (n >= N) sz = 0;
                srcp = (mat == 2 ? Bth : Btl) + (size_t)nn * K + k0 + c16 * 8;
            }
            asm volatile("cp.async.cg.shared.global [%0], [%1], 16, %2;"
                         :: "r"(dst), "l"(srcp), "r"(sz));
        }
        asm volatile("cp.async.commit_group;" ::: "memory");
    };

    load_chunk(0);

    for (int c = 0; c < nchunk; c++) {
        if (c + 1 < nchunk) {
            load_chunk(c + 1);
            asm volatile("cp.async.wait_group 1;" ::: "memory");
        } else {
            asm volatile("cp.async.wait_group 0;" ::: "memory");
        }
        __syncthreads();

        const uint32_t st = sb + (uint32_t)(c & 1) * STAGE8;
#pragma unroll
        for (int ks = 0; ks < 2; ks++) {
            uint32_t ah[4][4], al[4][4];
#pragma unroll
            for (int mi = 0; mi < 4; mi++) {
                uint32_t addr = st + a_off + mi * (16 * 112) + ks * 32;
                LDSM4(ah[mi], addr);
                LDSM4(al[mi], addr + MAT_BYTES8);
            }
#pragma unroll
            for (int b2 = 0; b2 < 2; b2++) {
                uint32_t bh[4], bl[4];
                uint32_t baddr = st + 2 * MAT_BYTES8 + b_off + b2 * (16 * 112) + ks * 32;
                LDSM4(bh, baddr);
                LDSM4(bl, baddr + MAT_BYTES8);
#pragma unroll
                for (int p = 0; p < 3; p++) {
#pragma unroll
                    for (int mi = 0; mi < 4; mi++) {
#pragma unroll
                        for (int hf = 0; hf < 2; hf++) {
                            const int nt = b2 * 2 + hf;
                            const uint32_t* A_ = (p == 2) ? al[mi] : ah[mi];
                            const uint32_t* B_ = (p == 1) ? bl : bh;
                            hmma(acc[mi][nt], A_, B_ + hf * 2);
                        }
                    }
                }
            }
        }
        __syncthreads();
    }

    const int g = lane >> 2, c2 = lane & 3;
#pragma unroll
    for (int mi = 0; mi < 4; mi++) {
        const int r = row0 + warp_m * 64 + mi * 16 + g;
#pragma unroll
        for (int nt = 0; nt < 4; nt++) {
            const int col = col0 + warp_n * 32 + nt * 8 + c2 * 2;
            if (col < N) {
                *(float2*)(C + (size_t)r * N + col)       = make_float2(acc[mi][nt][0], acc[mi][nt][1]);
                *(float2*)(C + (size_t)(r + 8) * N + col) = make_float2(acc[mi][nt][2], acc[mi][nt][3]);
            }
        }
    }
}

// ---------------- compressed tokens ----------------
__global__ void compress_kernel(const float* __restrict__ wck,
                                const float* __restrict__ wcv,
                                const float* __restrict__ pe)
{
    const int m = blockIdx.x, h = blockIdx.y, d = threadIdx.x;  // 64 threads
    float a = 0.f, b = 0.f;
    for (int t = 0; t < 64; t++) {
        const float wk = wck[h * 64 + t];
        const float wv = wcv[h * 64 + t];
        const int row = m * 64 + t;
        a = fmaf(g_kvg[row * 352 + h * 64 + d] + pe[(h * 64 + t) * 64 + d], wk, a);
        b = fmaf(g_kvg[row * 352 + 128 + h * 64 + d], wv, b);
    }
    g_ck[(m * 2 + h) * 64 + d] = a;
    g_cv[(m * 2 + h) * 64 + d] = b;
}

// ---------------- compressed attention + top-k, 4 tokens per CTA ----------------
__global__ void __launch_bounds__(512) comp_attn_kernel(int ntok)
{
    const int n0 = blockIdx.x * 4, h = blockIdx.y;
    const int tid = threadIdx.x;
    const int tq = tid >> 7, ltid = tid & 127;
    const int M = ntok >> 6;
    __shared__ float  sq[4096];
    __shared__ float2 ckp[32 * 33];
    __shared__ float  scv[MMAX * 64];
    __shared__ float  lg[4 * 512];
    __shared__ float  ssum[4 * 32];

    for (int i = tid; i < 4096; i += 512) {
        int q = i >> 10;
        sq[i] = g_q[(n0 + q) * 2048 + h * 1024 + (i & 1023)] * 0.125f;
    }
    for (int i = tid; i < M * 32; i += 512) {
        int m = i >> 5, d2 = i & 31;
        ckp[d2 * 33 + m] = *(const float2*)&g_ck[(m * 2 + h) * 64 + 2 * d2];
    }
    for (int i = tid; i < M * 64; i += 512)
        scv[i] = g_cv[((i >> 6) * 2 + h) * 64 + (i & 63)];
    __syncthreads();

    const int n = n0 + tq;
    const int mvis = (n >= 63) ? (((n - 63) >> 6) + 1) : 0;

#pragma unroll
    for (int i = 0; i < 4; i++) {
        int e = ltid + i * 128;
        int g = e >> 5, m = e & 31;
        unsigned long long acc = 0ull;
#pragma unroll
        for (int d2 = 0; d2 < 32; d2++) {
            unsigned long long qp = pk2f2(*(const float2*)&sq[tq * 1024 + g * 64 + 2 * d2]);
            acc = fma2(qp, pk2f2(ckp[d2 * 33 + m]), acc);
        }
        float x, y; upk2(acc, x, y);
        lg[tq * 512 + g * 32 + m] = x + y;
    }
    __syncthreads();

    if (ltid < 16) {
        float* row = lg + tq * 512 + ltid * 32;
        if (mvis == 0) {
            for (int m = 0; m < M; m++) row[m] = 0.f;
        } else {
            float mx = -INFINITY;
            for (int m = 0; m < mvis; m++) mx = fmaxf(mx, row[m]);
            float s = 0.f;
            for (int m = 0; m < mvis; m++) {
                float p = __expf(row[m] - mx);
                row[m] = p; s += p;
            }
            const float inv = 1.f / s;
            for (int m = 0; m < mvis; m++) row[m] *= inv;
            for (int m = mvis; m < M; m++) row[m] = 0.f;
        }
    }
    __syncthreads();

#pragma unroll
    for (int i = 0; i < 4; i++) {
        int e2 = ltid + i * 128;
        int g = e2 >> 5, d2 = e2 & 31;
        unsigned long long acc = 0ull;
        for (int m = 0; m < mvis; m++) {
            float p = lg[tq * 512 + g * 32 + m];
            acc = fma2(pk2(p, p), pk2f2(*(const float2*)&scv[m * 64 + 2 * d2]), acc);
        }
        float x, y; upk2(acc, x, y);
        *(float2*)&g_comp[n * 2048 + h * 1024 + g * 64 + 2 * d2] = make_float2(x, y);
    }

    if (ltid < 32) {
        float s = 0.f;
        if (ltid < M)
            for (int g = 0; g < 16; g++) s += lg[tq * 512 + g * 32 + ltid];
        ssum[tq * 32 + ltid] = s;
    }
    __syncthreads();

    if (ltid == 0) {
        const int qblk = n >> 6;
        unsigned sel = 0;
        if (qblk + 1 <= 16) {
            sel = (1u << (qblk + 1)) - 1u;
        } else {
            float sc[32];
            for (int m = 0; m < 32; m++) {
                if (m > qblk)                                  sc[m] = -INFINITY;
                else if (m == 0 || m == qblk || m == qblk - 1) sc[m] = INFINITY;
                else                                           sc[m] = ssum[tq * 32 + m];
            }
            for (int t = 0; t < 16; t++) {
                int best = 0; float bv = -INFINITY;
                for (int m = 0; m < 32; m++) {
                    if ((sel >> m) & 1u) continue;
                    if (sc[m] > bv) { bv = sc[m]; best = m; }
                }
                sel |= 1u << best;
            }
        }
        g_sel[n * 2 + h] = sel;
    }
}

// ---------------- main attention on tensor cores ----------------
#define BST 72          // bf16 smem row stride (elements) = 144 bytes
#define SQH 0
#define SQL 9216
#define SKH 18432
#define SKL 27648
#define SVTH 36864
#define SVTL 46080
#define PSH 55296
#define PSL 64512
#define PWH 73728
#define PWL 82944
#define LG_OFF 92160    // float [64][66]
#define PM_OFF 109056   // float [512]
#define HMM_OFF 111104  // float [2][64]
#define HLL_OFF 111616
#define HRR_OFF 112128
#define ATTN_SMEM 112640

__global__ void __launch_bounds__(256, 2) main_attn_kernel(int ntok)
{
    extern __shared__ char dsm[];
    const uint32_t sb = smem_u32(dsm);
    float* lg  = (float*)(dsm + LG_OFF);
    float* pm  = (float*)(dsm + PM_OFF);
    float* hmm = (float*)(dsm + HMM_OFF);
    float* hll = (float*)(dsm + HLL_OFF);
    float* hrr = (float*)(dsm + HRR_OFF);

    // reversed CTA order: heaviest (largest n0) first for tail packing
    const int n0 = (gridDim.x - 1 - blockIdx.x) * 4, h = blockIdx.y;
    const int tid = threadIdx.x;
    const int lane = tid & 31, wid = tid >> 5;
    const int warp_m = wid & 1, warp_n = wid >> 1;
    const int g = lane >> 2, cq = lane & 3;

    for (int i = tid; i < 4096; i += 256) {
        int r = i >> 6, d = i & 63;
        float v = g_q[(n0 + (r >> 4)) * 2048 + h * 1024 + (r & 15) * 64 + d] * 0.125f;
        unsigned short hi, lo;
        bsplit(v, hi, lo);
        *(unsigned short*)(dsm + SQH + (r * BST + d) * 2) = hi;
        *(unsigned short*)(dsm + SQL + (r * BST + d) * 2) = lo;
    }
    if (tid < 128) { hmm[tid] = -INFINITY; hll[tid] = 0.f; }

    const unsigned sel0 = g_sel[n0 * 2 + h],       sel1 = g_sel[(n0 + 1) * 2 + h],
                   sel2 = g_sel[(n0 + 2) * 2 + h], sel3 = g_sel[(n0 + 3) * 2 + h];
    const unsigned selU = sel0 | sel1 | sel2 | sel3;
    const int qblk = n0 >> 6;

    const int mt = lane >> 3, rin = lane & 7;
    const uint32_t a_base = (uint32_t)(((mt & 1) * 8 + rin) * 144 + ((mt >> 1) * 8) * 2);
    const uint32_t b_base = (uint32_t)((warp_n * 16 + ((mt >= 2) ? 8 : 0) + rin) * 144 + ((mt & 1) * 8) * 2);

    float acc_s[2][2][4] = {}, acc_w[2][2][4] = {};

    __syncthreads();

    for (int c = 0; c <= qblk; c++) {
        const int base = n0 - c * 64;
        const bool wact = (base - 512) <= 63;          // window branch active
        const bool sact = (selU >> c) & 1u;            // sparse branch active
        if (!sact && !wact) continue;

        // K/V tiles via cp.async (8 x 16B per thread)
#pragma unroll
        for (int i2 = 0; i2 < 8; i2++) {
            int i = tid + i2 * 256;
            int mat = i >> 9, idx = i & 511;
            int row = idx >> 3, c16 = idx & 7;
            const __nv_bfloat16* src;
            if (mat == 0)      src = g_kbh + (size_t)(c * 64 + row) * 128 + h * 64 + c16 * 8;
            else if (mat == 1) src = g_kbl + (size_t)(c * 64 + row) * 128 + h * 64 + c16 * 8;
            else if (mat == 2) src = g_vth + (size_t)(h * 64 + row) * TMAX + c * 64 + c16 * 8;
            else               src = g_vtl + (size_t)(h * 64 + row) * TMAX + c * 64 + c16 * 8;
            uint32_t dst = sb + SKH + (uint32_t)(mat * 9216 + row * 144 + c16 * 16);
            asm volatile("cp.async.cg.shared.global [%0], [%1], 16;"
                         :: "r"(dst), "l"(src));
        }
        asm volatile("cp.async.commit_group;" ::: "memory");
        asm volatile("cp.async.wait_group 0;" ::: "memory");
        __syncthreads();

        // ---- S = Q K^T via HMMA (3-product) ----
        {
            float acc[2][2][4] = {};
#pragma unroll
            for (int ks = 0; ks < 4; ks++) {
                uint32_t kh[4], kl[4];
                LDSM4(kh, sb + SKH + b_base + ks * 32);
                LDSM4(kl, sb + SKL + b_base + ks * 32);
#pragma unroll
                for (int mi = 0; mi < 2; mi++) {
                    uint32_t qh[4], ql[4];
                    const uint32_t ao = (uint32_t)((warp_m * 32 + mi * 16) * 144) + a_base + ks * 32;
                    LDSM4(qh, sb + SQH + ao);
                    LDSM4(ql, sb + SQL + ao);
#pragma unroll
                    for (int hf = 0; hf < 2; hf++) {
                        hmma(acc[mi][hf], qh, kh + hf * 2);
                        hmma(acc[mi][hf], qh, kl + hf * 2);
                        hmma(acc[mi][hf], ql, kh + hf * 2);
                    }
                }
            }
#pragma unroll
            for (int mi = 0; mi < 2; mi++) {
                const int r0 = warp_m * 32 + mi * 16 + g;
#pragma unroll
                for (int hf = 0; hf < 2; hf++) {
                    const int col = warp_n * 16 + hf * 8 + cq * 2;
                    *(float2*)&lg[r0 * 66 + col]       = make_float2(acc[mi][hf][0], acc[mi][hf][1]);
                    *(float2*)&lg[(r0 + 8) * 66 + col] = make_float2(acc[mi][hf][2], acc[mi][hf][3]);
                }
            }
        }
        __syncthreads();

        // ---- segmented max (branch-guarded) ----
        {
            const int r = tid >> 2, seg = tid & 3;
            const int q = r >> 4;
            const int jn = min(63, base + q);
            if (sact) {
                const unsigned selq = (q == 0) ? sel0 : (q == 1) ? sel1 : (q == 2) ? sel2 : sel3;
                float ms = -INFINITY;
                if ((selq >> c) & 1u) {
                    const int hi2 = min(seg * 16 + 15, jn);
                    for (int j = seg * 16; j <= hi2; j++) ms = fmaxf(ms, lg[r * 66 + j]);
                }
                pm[tid] = ms;
            }
            if (wact) {
                const int jw0 = base + q - 512;
                float mw = -INFINITY;
                if (jw0 <= 63) {
                    const int lo2 = max(seg * 16, jw0);
                    const int hi2 = min(seg * 16 + 15, jn);
                    for (int j = lo2; j <= hi2; j++) mw = fmaxf(mw, lg[r * 66 + j]);
                }
                pm[256 + tid] = mw;
            }
        }
        __syncthreads();
        if (tid < 128) {
            const int br = tid >> 6, r = tid & 63;
            const bool act = br ? wact : sact;
            if (act) {
                const float* p = pm + br * 256 + r * 4;
                const float cm = fmaxf(fmaxf(p[0], p[1]), fmaxf(p[2], p[3]));
                const float om = hmm[br * 64 + r];
                const float nm = fmaxf(om, cm);
                hmm[br * 64 + r] = nm;
                hrr[br * 64 + r] = (cm == -INFINITY) ? 1.f : __expf(om - nm);
            } else {
                hrr[br * 64 + r] = 1.f;
            }
        }
        __syncthreads();

        // ---- exp + partial sums + split-bf16 P store (branch-guarded) ----
        {
            const int r = tid >> 2, seg = tid & 3;
            const int q = r >> 4;
            const int jn = base + q;
            const uint32_t po = (uint32_t)((r * BST + seg * 16) * 2);
            if (sact) {
                const unsigned selq = (q == 0) ? sel0 : (q == 1) ? sel1 : (q == 2) ? sel2 : sel3;
                const bool srow = (selq >> c) & 1u;
                const float ms = hmm[r];
                float ss = 0.f;
                unsigned short eh[16], el[16];
#pragma unroll
                for (int jj = 0; jj < 16; jj++) {
                    const int j = seg * 16 + jj;
                    float es = (srow && j <= jn) ? __expf(lg[r * 66 + j] - ms) : 0.f;
                    ss += es;
                    bsplit(es, eh[jj], el[jj]);
                }
                pm[tid] = ss;
#pragma unroll
                for (int v4 = 0; v4 < 4; v4++) {
                    *(ushort4*)(dsm + PSH + po + v4 * 8) = make_ushort4(eh[v4*4], eh[v4*4+1], eh[v4*4+2], eh[v4*4+3]);
                    *(ushort4*)(dsm + PSL + po + v4 * 8) = make_ushort4(el[v4*4], el[v4*4+1], el[v4*4+2], el[v4*4+3]);
                }
            }
            if (wact) {
                const int jw0 = base + q - 512;
                const float mw = hmm[64 + r];
                float sw = 0.f;
                unsigned short wh[16], wl[16];
#pragma unroll
                for (int jj = 0; jj < 16; jj++) {
                    const int j = seg * 16 + jj;
                    float ew = (j <= jn && j >= jw0) ? __expf(lg[r * 66 + j] - mw) : 0.f;
                    sw += ew;
                    bsplit(ew, wh[jj], wl[jj]);
                }
                pm[256 + tid] = sw;
#pragma unroll
                for (int v4 = 0; v4 < 4; v4++) {
                    *(ushort4*)(dsm + PWH + po + v4 * 8) = make_ushort4(wh[v4*4], wh[v4*4+1], wh[v4*4+2], wh[v4*4+3]);
                    *(ushort4*)(dsm + PWL + po + v4 * 8) = make_ushort4(wl[v4*4], wl[v4*4+1], wl[v4*4+2], wl[v4*4+3]);
                }
            }
        }
        __syncthreads();
        if (tid < 128) {
            const int br = tid >> 6, r = tid & 63;
            const bool act = br ? wact : sact;
            if (act) {
                const float* p = pm + br * 256 + r * 4;
                hll[br * 64 + r] = hll[br * 64 + r] * hrr[br * 64 + r]
                                 + (p[0] + p[1]) + (p[2] + p[3]);
            }
        }

        // ---- PV via HMMA with flash rescale (branch-guarded) ----
        if (sact) {
#pragma unroll
            for (int mi = 0; mi < 2; mi++) {
                const int rb = warp_m * 32 + mi * 16 + g;
                const float rs0 = hrr[rb], rs1 = hrr[rb + 8];
#pragma unroll
                for (int hf = 0; hf < 2; hf++) {
                    acc_s[mi][hf][0] *= rs0; acc_s[mi][hf][1] *= rs0;
                    acc_s[mi][hf][2] *= rs1; acc_s[mi][hf][3] *= rs1;
                }
            }
        }
        if (wact) {
#pragma unroll
            for (int mi = 0; mi < 2; mi++) {
                const int rb = warp_m * 32 + mi * 16 + g;
                const float rw0 = hrr[64 + rb], rw1 = hrr[64 + rb + 8];
#pragma unroll
                for (int hf = 0; hf < 2; hf++) {
                    acc_w[mi][hf][0] *= rw0; acc_w[mi][hf][1] *= rw0;
                    acc_w[mi][hf][2] *= rw1; acc_w[mi][hf][3] *= rw1;
                }
            }
        }
#pragma unroll
        for (int ks = 0; ks < 4; ks++) {
            uint32_t vh[4], vl[4];
            LDSM4(vh, sb + SVTH + b_base + ks * 32);
            LDSM4(vl, sb + SVTL + b_base + ks * 32);
#pragma unroll
            for (int mi = 0; mi < 2; mi++) {
                const uint32_t ao = (uint32_t)((warp_m * 32 + mi * 16) * 144) + a_base + ks * 32;
                if (sact) {
                    uint32_t ph[4], pl[4];
                    LDSM4(ph, sb + PSH + ao);
                    LDSM4(pl, sb + PSL + ao);
#pragma unroll
                    for (int hf = 0; hf < 2; hf++) {
                        hmma(acc_s[mi][hf], ph, vh + hf * 2);
                        hmma(acc_s[mi][hf], ph, vl + hf * 2);
                        hmma(acc_s[mi][hf], pl, vh + hf * 2);
                    }
                }
                if (wact) {
                    uint32_t ph[4], pl[4];
                    LDSM4(ph, sb + PWH + ao);
                    LDSM4(pl, sb + PWL + ao);
#pragma unroll
                    for (int hf = 0; hf < 2; hf++) {
                        hmma(acc_w[mi][hf], ph, vh + hf * 2);
                        hmma(acc_w[mi][hf], ph, vl + hf * 2);
                        hmma(acc_w[mi][hf], pl, vh + hf * 2);
                    }
                }
            }
        }
        __syncthreads();
    }

    // ---- gated fusion epilogue ----
#pragma unroll
    for (int mi = 0; mi < 2; mi++) {
#pragma unroll
        for (int half = 0; half < 2; half++) {
            const int r = warp_m * 32 + mi * 16 + g + half * 8;
            const int nq = n0 + (r >> 4);
            const int head = r & 15;
            const int hq = h * 16 + head;
            const float gl0 = g_kvg[nq * 352 + 256 + hq * 3 + 0];
            const float gl1 = g_kvg[nq * 352 + 256 + hq * 3 + 1];
            const float gl2 = g_kvg[nq * 352 + 256 + hq * 3 + 2];
            const float g0 = 1.f / (1.f + __expf(-gl0));
            const float g1 = 1.f / (1.f + __expf(-gl1));
            const float g2 = 1.f / (1.f + __expf(-gl2));
            const float inv_s = 1.f / hll[r];
            const float inv_w = 1.f / hll[64 + r];
#pragma unroll
            for (int hf = 0; hf < 2; hf++) {
                const int col = warp_n * 16 + hf * 8 + cq * 2;
                const int oi = nq * 2048 + h * 1024 + head * 64 + col;
                const float2 cmp = *(const float2*)&g_comp[oi];
                const float o0 = g0 * cmp.x + g1 * acc_s[mi][hf][half * 2]     * inv_s
                                            + g2 * acc_w[mi][hf][half * 2]     * inv_w;
                const float o1 = g0 * cmp.y + g1 * acc_s[mi][hf][half * 2 + 1] * inv_s
                                            + g2 * acc_w[mi][hf][half * 2 + 1] * inv_w;
                ushort2 hh, ll;
                bsplit(o0, hh.x, ll.x);
                bsplit(o1, hh.y, ll.y);
                *(ushort2*)(g_fh + oi) = hh;
                *(ushort2*)(g_fl + oi) = ll;
            }
        }
    }
}

// ---------------- launch ----------------
extern "C" void kernel_launch(void* const* d_in, const int* in_sizes, int n_in,
                              void* d_out, int out_size)
{
    const float* x   = (const float*)d_in[0];
    const float* Wq  = (const float*)d_in[2];
    const float* Wk  = (const float*)d_in[3];
    const float* Wv  = (const float*)d_in[4];
    const float* Wo  = (const float*)d_in[5];
    const float* Wg  = (const float*)d_in[6];
    const float* wck = (const float*)d_in[7];
    const float* wcv = (const float*)d_in[8];
    const float* pe  = (const float*)d_in[9];
    float* out = (float*)d_out;

    const int ntok = in_sizes[0] / 2048;     // T = 2048
    const int M = ntok / 64;

    float *q, *kvg;
    cudaGetSymbolAddress((void**)&q,   g_q);
    cudaGetSymbolAddress((void**)&kvg, g_kvg);

    __nv_bfloat16 *xh, *xl, *fh, *fl, *wqh, *wql, *woh, *wol, *wkvgh, *wkvgl;
    cudaGetSymbolAddress((void**)&xh, g_xh);     cudaGetSymbolAddress((void**)&xl, g_xl);
    cudaGetSymbolAddress((void**)&fh, g_fh);     cudaGetSymbolAddress((void**)&fl, g_fl);
    cudaGetSymbolAddress((void**)&wqh, g_wqt_h); cudaGetSymbolAddress((void**)&wql, g_wqt_l);
    cudaGetSymbolAddress((void**)&woh, g_wot_h); cudaGetSymbolAddress((void**)&wol, g_wot_l);
    cudaGetSymbolAddress((void**)&wkvgh, g_wkvgt_h);
    cudaGetSymbolAddress((void**)&wkvgl, g_wkvgt_l);

    cudaFuncSetAttribute(mma_gemm, cudaFuncAttributeMaxDynamicSharedMemorySize, SMEM_GEMM);
    cudaFuncSetAttribute(mma_gemm128, cudaFuncAttributeMaxDynamicSharedMemorySize, SMEM_GEMM8);
    cudaFuncSetAttribute(main_attn_kernel, cudaFuncAttributeMaxDynamicSharedMemorySize, ATTN_SMEM);

    const int tot = ntok * 2048;
    dim3 tb(32, 8);

    split_fp32<<<(tot / 4 + 255) / 256, 256>>>((const float4*)x, xh, xl, tot / 4);                // 0
    transpose_split<<<dim3(64, 64), tb>>>(Wq, wqh, wql, 2048, 2048);                              // 1
    transpose_split<<<dim3(4,  64), tb>>>(Wk, wkvgh,              wkvgl,              2048, 128); // 2
    mma_gemm<<<dim3(8, ntok / 128), 512, SMEM_GEMM>>>(xh, xl, wqh, wql, q, ntok, 2048, 2048);     // 3 <- ncu
    transpose_split<<<dim3(4,  64), tb>>>(Wv, wkvgh + 128 * 2048, wkvgl + 128 * 2048, 2048, 128); // 4
    transpose_split<<<dim3(3,  64), tb>>>(Wg, wkvgh + 256 * 2048, wkvgl + 256 * 2048, 2048, 96);  // 5
    mma_gemm128<<<dim3(3, ntok / 128), 256, SMEM_GEMM8>>>(xh, xl, wkvgh, wkvgl, kvg, ntok, 352, 2048);

    kv_prep<<<dim3(ntok / 32, 2, 2), tb>>>(ntok);
    compress_kernel<<<dim3(M, 2), 64>>>(wck, wcv, pe);
    comp_attn_kernel<<<dim3(ntok / 4, 2), 512>>>(ntok);
    main_attn_kernel<<<dim3(ntok / 4, 2), 256, ATTN_SMEM>>>(ntok);

    transpose_split<<<dim3(64, 64), tb>>>(Wo, woh, wol, 2048, 2048);
    mma_gemm<<<dim3(8, ntok / 128), 512, SMEM_GEMM>>>(fh, fl, woh, wol, out, ntok, 2048, 2048);
}

// round 13
// speedup vs baseline: 1.2737x; 1.0369x over previous
#include <cuda_runtime.h>
#include <cuda_bf16.h>
#include <math.h>
#include <stdint.h>

// Problem constants (T=2048, H=2048, HQ=32, HKV=2, D=64, G=16, M<=32)
#define TMAX 2048
#define MMAX 32

// ---------------- scratch (no allocation allowed) ----------------
__device__ float    g_q[TMAX * 2048];      // [n, HQ*D]
__device__ float    g_kvg[TMAX * 352];     // [n, k(128) | v(128) | gate(96)]
__device__ float    g_ck[MMAX * 2 * 64];
__device__ float    g_cv[MMAX * 2 * 64];
__device__ float    g_comp[TMAX * 2048];
__device__ unsigned g_sel[TMAX * 2];

// bf16 split operands
__device__ __nv_bfloat16 g_xh[2048 * 2048], g_xl[2048 * 2048];
__device__ __nv_bfloat16 g_fh[2048 * 2048], g_fl[2048 * 2048];
__device__ __nv_bfloat16 g_wqt_h[2048 * 2048], g_wqt_l[2048 * 2048];   // Wq^T [N,K]
__device__ __nv_bfloat16 g_wot_h[2048 * 2048], g_wot_l[2048 * 2048];   // Wo^T
__device__ __nv_bfloat16 g_wkvgt_h[352 * 2048], g_wkvgt_l[352 * 2048]; // [Wk|Wv|Wg]^T
// attention K / V^T split-bf16
__device__ __nv_bfloat16 g_kbh[TMAX * 128], g_kbl[TMAX * 128];          // [n][h][64]
__device__ __nv_bfloat16 g_vth[2 * 64 * TMAX], g_vtl[2 * 64 * TMAX];    // [h][d][n]

__device__ __forceinline__ uint32_t smem_u32(const void* p) {
    uint32_t a;
    asm("{ .reg .u64 t; cvta.to.shared.u64 t, %1; cvt.u32.u64 %0, t; }" : "=r"(a) : "l"(p));
    return a;
}

// ---------------- packed f32x2 helpers ----------------
__device__ __forceinline__ unsigned long long pk2(float x, float y) {
    unsigned long long r;
    asm("mov.b64 %0, {%1,%2};" : "=l"(r) : "f"(x), "f"(y));
    return r;
}
__device__ __forceinline__ unsigned long long pk2f2(float2 v) { return pk2(v.x, v.y); }
__device__ __forceinline__ void upk2(unsigned long long r, float& x, float& y) {
    asm("mov.b64 {%0,%1}, %2;" : "=f"(x), "=f"(y) : "l"(r));
}
__device__ __forceinline__ unsigned long long fma2(unsigned long long a,
                                                   unsigned long long b,
                                                   unsigned long long c) {
    unsigned long long d;
    asm("fma.rn.f32x2 %0, %1, %2, %3;" : "=l"(d) : "l"(a), "l"(b), "l"(c));
    return d;
}

// ---------------- mma helpers ----------------
#define LDSM4(r, addr) \
    asm volatile("ldmatrix.sync.aligned.m8n8.x4.shared.b16 {%0,%1,%2,%3}, [%4];" \
                 : "=r"((r)[0]), "=r"((r)[1]), "=r"((r)[2]), "=r"((r)[3]) : "r"(addr))

__device__ __forceinline__ void hmma(float* c, const uint32_t* a, const uint32_t* b) {
    asm volatile("mma.sync.aligned.m16n8k16.row.col.f32.bf16.bf16.f32 "
                 "{%0,%1,%2,%3},{%4,%5,%6,%7},{%8,%9},{%0,%1,%2,%3};"
                 : "+f"(c[0]), "+f"(c[1]), "+f"(c[2]), "+f"(c[3])
                 : "r"(a[0]), "r"(a[1]), "r"(a[2]), "r"(a[3]), "r"(b[0]), "r"(b[1]));
}

__device__ __forceinline__ void bsplit(float v, unsigned short& hi, unsigned short& lo) {
    __nv_bfloat16 h = __float2bfloat16(v);
    __nv_bfloat16 l = __float2bfloat16(v - __bfloat162float(h));
    hi = *(unsigned short*)&h; lo = *(unsigned short*)&l;
}

// ================= prep kernels =================
__global__ void split_fp32(const float4* __restrict__ A,
                           __nv_bfloat16* __restrict__ Ah,
                           __nv_bfloat16* __restrict__ Al, int total4)
{
    int i = blockIdx.x * 256 + threadIdx.x;
    if (i < total4) {
        float4 v = A[i];
        ushort4 hh, ll;
        bsplit(v.x, hh.x, ll.x); bsplit(v.y, hh.y, ll.y);
        bsplit(v.z, hh.z, ll.z); bsplit(v.w, hh.w, ll.w);
        *(ushort4*)(Ah + 4 * (size_t)i) = hh;
        *(ushort4*)(Al + 4 * (size_t)i) = ll;
    }
}

__global__ void transpose_split(const float* __restrict__ W,
                                __nv_bfloat16* __restrict__ Th,
                                __nv_bfloat16* __restrict__ Tl, int K, int N)
{
    __shared__ float t[32][33];
    const int k0 = blockIdx.y * 32, n0 = blockIdx.x * 32;
    const int tx = threadIdx.x, ty = threadIdx.y;  // 32 x 8
    for (int i = ty; i < 32; i += 8) {
        int k = k0 + i, n = n0 + tx;
        t[i][tx] = (n < N && k < K) ? W[(size_t)k * N + n] : 0.f;
    }
    __syncthreads();
    for (int i = ty; i < 32; i += 8) {
        int n = n0 + i, k = k0 + tx;
        if (n < N && k < K) {
            unsigned short hi, lo;
            bsplit(t[tx][i], hi, lo);
            *(unsigned short*)(Th + (size_t)n * K + k) = hi;
            *(unsigned short*)(Tl + (size_t)n * K + k) = lo;
        }
    }
}

// K split + V transpose-split. grid (n/32, 2, 2), block (32,8)
__global__ void kv_prep(int ntok)
{
    __shared__ float t[32][33];
    const int n0 = blockIdx.x * 32, h = blockIdx.y, dh = blockIdx.z * 32;
    const int tx = threadIdx.x, ty = threadIdx.y;
    for (int i = ty; i < 32; i += 8) {
        const int n = n0 + i, d = dh + tx;
        float kv = g_kvg[n * 352 + h * 64 + d];
        unsigned short hi, lo;
        bsplit(kv, hi, lo);
        *(unsigned short*)(g_kbh + n * 128 + h * 64 + d) = hi;
        *(unsigned short*)(g_kbl + n * 128 + h * 64 + d) = lo;
        t[i][tx] = g_kvg[n * 352 + h * 64 + 128 + d];
    }
    __syncthreads();
    for (int i = ty; i < 32; i += 8) {
        const int d = dh + i, n = n0 + tx;
        unsigned short hi, lo;
        bsplit(t[tx][i], hi, lo);
        *(unsigned short*)(g_vth + (h * 64 + d) * TMAX + n) = hi;
        *(unsigned short*)(g_vtl + (h * 64 + d) * TMAX + n) = lo;
    }
}

// ================= split-bf16 GEMM, 128x256 tile, 512 threads (big GEMMs) =================
#define A_MAT 14336
#define B_MAT 28672
#define STAGE_BYTES 86016
#define SMEM_GEMM (2 * STAGE_BYTES)

__global__ void __launch_bounds__(512) mma_gemm(
    const __nv_bfloat16* __restrict__ Ah, const __nv_bfloat16* __restrict__ Al,
    const __nv_bfloat16* __restrict__ Bth, const __nv_bfloat16* __restrict__ Btl,
    float* __restrict__ C, int M, int N, int K)
{
    extern __shared__ char smem[];
    const uint32_t sb = smem_u32(smem);
    const int tid = threadIdx.x;
    const int lane = tid & 31, wid = tid >> 5;
    const int warp_m = wid & 1, warp_n = wid >> 1;   // 2 x 8 warps
    const int row0 = blockIdx.y * 128, col0 = blockIdx.x * 256;
    const int nchunk = K >> 5;

    float acc[4][4][4];
#pragma unroll
    for (int a = 0; a < 4; a++)
#pragma unroll
        for (int b = 0; b < 4; b++)
#pragma unroll
            for (int c = 0; c < 4; c++) acc[a][b][c] = 0.f;

    const int mt = lane >> 3, rin = lane & 7;
    const uint32_t a_off = (uint32_t)((warp_m * 64 + (mt & 1) * 8 + rin) * 112 + ((mt >> 1) * 8) * 2);
    const uint32_t b_off = (uint32_t)((warp_n * 32 + ((mt >= 2) ? 8 : 0) + rin) * 112 + ((mt & 1) * 8) * 2);

    auto load_chunk = [&](int c) {
        const int k0 = c * 32;
        const uint32_t st = sb + (uint32_t)(c & 1) * STAGE_BYTES;
#pragma unroll
        for (int i = 0; i < 6; i++) {
            int v = tid + i * 512;
            uint32_t dst;
            const __nv_bfloat16* srcp;
            int sz = 16;
            if (v < 1024) {
                int mat = v >> 9, r = (v >> 2) & 127, c16 = v & 3;
                dst = st + mat * A_MAT + r * 112 + c16 * 16;
                srcp = (mat ? Al : Ah) + (size_t)(row0 + r) * K + k0 + c16 * 8;
            } else {
                int vb = v - 1024;
                int mat = vb >> 10, r = (vb >> 2) & 255, c16 = vb & 3;
                dst = st + 2 * A_MAT + mat * B_MAT + r * 112 + c16 * 16;
                int n = col0 + r;
                int nn = (n < N) ? n : 0;
                if (n >= N) sz = 0;
                srcp = (mat ? Btl : Bth) + (size_t)nn * K + k0 + c16 * 8;
            }
            asm volatile("cp.async.cg.shared.global [%0], [%1], 16, %2;"
                         :: "r"(dst), "l"(srcp), "r"(sz));
        }
        asm volatile("cp.async.commit_group;" ::: "memory");
    };

    load_chunk(0);

    for (int c = 0; c < nchunk; c++) {
        if (c + 1 < nchunk) {
            load_chunk(c + 1);
            asm volatile("cp.async.wait_group 1;" ::: "memory");
        } else {
            asm volatile("cp.async.wait_group 0;" ::: "memory");
        }
        __syncthreads();

        const uint32_t st = sb + (uint32_t)(c & 1) * STAGE_BYTES;
#pragma unroll
        for (int ks = 0; ks < 2; ks++) {
            uint32_t ah[4][4], al[4][4];
#pragma unroll
            for (int mi = 0; mi < 4; mi++) {
                uint32_t addr = st + a_off + mi * (16 * 112) + ks * 32;
                LDSM4(ah[mi], addr);
                LDSM4(al[mi], addr + A_MAT);
            }
#pragma unroll
            for (int b2 = 0; b2 < 2; b2++) {
                uint32_t bh[4], bl[4];
                uint32_t baddr = st + 2 * A_MAT + b_off + b2 * (16 * 112) + ks * 32;
                LDSM4(bh, baddr);
                LDSM4(bl, baddr + B_MAT);
#pragma unroll
                for (int p = 0; p < 3; p++) {
#pragma unroll
                    for (int mi = 0; mi < 4; mi++) {
#pragma unroll
                        for (int hf = 0; hf < 2; hf++) {
                            const int nt = b2 * 2 + hf;
                            const uint32_t* A_ = (p == 2) ? al[mi] : ah[mi];
                            const uint32_t* B_ = (p == 1) ? bl : bh;
                            hmma(acc[mi][nt], A_, B_ + hf * 2);
                        }
                    }
                }
            }
        }
        __syncthreads();
    }

    const int g = lane >> 2, c2 = lane & 3;
#pragma unroll
    for (int mi = 0; mi < 4; mi++) {
        const int r = row0 + warp_m * 64 + mi * 16 + g;
#pragma unroll
        for (int nt = 0; nt < 4; nt++) {
            const int col = col0 + warp_n * 32 + nt * 8 + c2 * 2;
            if (col < N) {
                *(float2*)(C + (size_t)r * N + col)       = make_float2(acc[mi][nt][0], acc[mi][nt][1]);
                *(float2*)(C + (size_t)(r + 8) * N + col) = make_float2(acc[mi][nt][2], acc[mi][nt][3]);
            }
        }
    }
}

// ================= split-bf16 GEMM, 128x128 tile, 256 threads (narrow GEMMs) =================
#define MAT_BYTES8  (128 * 112)
#define STAGE8 (4 * MAT_BYTES8)
#define SMEM_GEMM8 (2 * STAGE8)

__global__ void __launch_bounds__(256) mma_gemm128(
    const __nv_bfloat16* __restrict__ Ah, const __nv_bfloat16* __restrict__ Al,
    const __nv_bfloat16* __restrict__ Bth, const __nv_bfloat16* __restrict__ Btl,
    float* __restrict__ C, int M, int N, int K)
{
    extern __shared__ char smem[];
    const uint32_t sb = smem_u32(smem);
    const int tid = threadIdx.x;
    const int lane = tid & 31, wid = tid >> 5;
    const int warp_m = wid & 1, warp_n = wid >> 1;
    const int row0 = blockIdx.y * 128, col0 = blockIdx.x * 128;
    const int nchunk = K >> 5;

    float acc[4][4][4];
#pragma unroll
    for (int a = 0; a < 4; a++)
#pragma unroll
        for (int b = 0; b < 4; b++)
#pragma unroll
            for (int c = 0; c < 4; c++) acc[a][b][c] = 0.f;

    const int mt = lane >> 3, rin = lane & 7;
    const uint32_t a_off = (uint32_t)((warp_m * 64 + (mt & 1) * 8 + rin) * 112 + ((mt >> 1) * 8) * 2);
    const uint32_t b_off = (uint32_t)((warp_n * 32 + ((mt >= 2) ? 8 : 0) + rin) * 112 + ((mt & 1) * 8) * 2);

    auto load_chunk = [&](int c) {
        const int k0 = c * 32;
        const uint32_t st = sb + (uint32_t)(c & 1) * STAGE8;
#pragma unroll
        for (int i = 0; i < 8; i++) {
            int v = tid + i * 256;
            int mat = v >> 9, r = (v >> 2) & 127, c16 = v & 3;
            uint32_t dst = st + mat * MAT_BYTES8 + r * 112 + c16 * 16;
            const __nv_bfloat16* srcp;
            int sz = 16;
            if (mat == 0)      srcp = Ah + (size_t)(row0 + r) * K + k0 + c16 * 8;
            else if (mat == 1) srcp = Al + (size_t)(row0 + r) * K + k0 + c16 * 8;
            else {
                int n = col0 + r;
                int nn = (n < N) ? n : 0;
                if (n >= N) sz = 0;
                srcp = (mat == 2 ? Bth : Btl) + (size_t)nn * K + k0 + c16 * 8;
            }
            asm volatile("cp.async.cg.shared.global [%0], [%1], 16, %2;"
                         :: "r"(dst), "l"(srcp), "r"(sz));
        }
        asm volatile("cp.async.commit_group;" ::: "memory");
    };

    load_chunk(0);

    for (int c = 0; c < nchunk; c++) {
        if (c + 1 < nchunk) {
            load_chunk(c + 1);
            asm volatile("cp.async.wait_group 1;" ::: "memory");
        } else {
            asm volatile("cp.async.wait_group 0;" ::: "memory");
        }
        __syncthreads();

        const uint32_t st = sb + (uint32_t)(c & 1) * STAGE8;
#pragma unroll
        for (int ks = 0; ks < 2; ks++) {
            uint32_t ah[4][4], al[4][4];
#pragma unroll
            for (int mi = 0; mi < 4; mi++) {
                uint32_t addr = st + a_off + mi * (16 * 112) + ks * 32;
                LDSM4(ah[mi], addr);
                LDSM4(al[mi], addr + MAT_BYTES8);
            }
#pragma unroll
            for (int b2 = 0; b2 < 2; b2++) {
                uint32_t bh[4], bl[4];
                uint32_t baddr = st + 2 * MAT_BYTES8 + b_off + b2 * (16 * 112) + ks * 32;
                LDSM4(bh, baddr);
                LDSM4(bl, baddr + MAT_BYTES8);
#pragma unroll
                for (int p = 0; p < 3; p++) {
#pragma unroll
                    for (int mi = 0; mi < 4; mi++) {
#pragma unroll
                        for (int hf = 0; hf < 2; hf++) {
                            const int nt = b2 * 2 + hf;
                            const uint32_t* A_ = (p == 2) ? al[mi] : ah[mi];
                            const uint32_t* B_ = (p == 1) ? bl : bh;
                            hmma(acc[mi][nt], A_, B_ + hf * 2);
                        }
                    }
                }
            }
        }
        __syncthreads();
    }

    const int g = lane >> 2, c2 = lane & 3;
#pragma unroll
    for (int mi = 0; mi < 4; mi++) {
        const int r = row0 + warp_m * 64 + mi * 16 + g;
#pragma unroll
        for (int nt = 0; nt < 4; nt++) {
            const int col = col0 + warp_n * 32 + nt * 8 + c2 * 2;
            if (col < N) {
                *(float2*)(C + (size_t)r * N + col)       = make_float2(acc[mi][nt][0], acc[mi][nt][1]);
                *(float2*)(C + (size_t)(r + 8) * N + col) = make_float2(acc[mi][nt][2], acc[mi][nt][3]);
            }
        }
    }
}

// ---------------- compressed tokens ----------------
__global__ void compress_kernel(const float* __restrict__ wck,
                                const float* __restrict__ wcv,
                                const float* __restrict__ pe)
{
    const int m = blockIdx.x, h = blockIdx.y, d = threadIdx.x;  // 64 threads
    float a = 0.f, b = 0.f;
    for (int t = 0; t < 64; t++) {
        const float wk = wck[h * 64 + t];
        const float wv = wcv[h * 64 + t];
        const int row = m * 64 + t;
        a = fmaf(g_kvg[row * 352 + h * 64 + d] + pe[(h * 64 + t) * 64 + d], wk, a);
        b = fmaf(g_kvg[row * 352 + 128 + h * 64 + d], wv, b);
    }
    g_ck[(m * 2 + h) * 64 + d] = a;
    g_cv[(m * 2 + h) * 64 + d] = b;
}

// ---------------- compressed attention + top-k, 8 tokens per CTA, dynamic smem ----------------
#define CSMEM (66816)
__global__ void __launch_bounds__(512) comp_attn_kernel(int ntok)
{
    extern __shared__ float csm[];
    float*  sq   = csm;                        // [8][1024] prescaled Q
    float2* ckp  = (float2*)(csm + 8192);      // [32][33] d-pair ck
    float*  scv  = csm + 8192 + 2112;          // [32][64]
    float*  lg   = scv + 2048;                 // [8][512]
    float*  ssum = lg + 4096;                  // [8][32]

    const int n0 = blockIdx.x * 8, h = blockIdx.y;
    const int tid = threadIdx.x;
    const int tq = tid >> 6, ltid = tid & 63;
    const int M = ntok >> 6;

    for (int i = tid; i < 8192; i += 512) {
        int q = i >> 10;
        sq[i] = g_q[(n0 + q) * 2048 + h * 1024 + (i & 1023)] * 0.125f;
    }
    for (int i = tid; i < M * 32; i += 512) {
        int m = i >> 5, d2 = i & 31;
        ckp[d2 * 33 + m] = *(const float2*)&g_ck[(m * 2 + h) * 64 + 2 * d2];
    }
    for (int i = tid; i < M * 64; i += 512)
        scv[i] = g_cv[((i >> 6) * 2 + h) * 64 + (i & 63)];
    __syncthreads();

    const int n = n0 + tq;
    const int mvis = (n >= 63) ? (((n - 63) >> 6) + 1) : 0;

#pragma unroll
    for (int i = 0; i < 8; i++) {
        int e = ltid + i * 64;
        int g = e >> 5, m = e & 31;
        unsigned long long acc = 0ull;
#pragma unroll
        for (int d2 = 0; d2 < 32; d2++) {
            unsigned long long qp = pk2f2(*(const float2*)&sq[tq * 1024 + g * 64 + 2 * d2]);
            acc = fma2(qp, pk2f2(ckp[d2 * 33 + m]), acc);
        }
        float x, y; upk2(acc, x, y);
        lg[tq * 512 + g * 32 + m] = x + y;
    }
    __syncthreads();

    if (ltid < 16) {
        float* row = lg + tq * 512 + ltid * 32;
        if (mvis == 0) {
            for (int m = 0; m < M; m++) row[m] = 0.f;
        } else {
            float mx = -INFINITY;
            for (int m = 0; m < mvis; m++) mx = fmaxf(mx, row[m]);
            float s = 0.f;
            for (int m = 0; m < mvis; m++) {
                float p = __expf(row[m] - mx);
                row[m] = p; s += p;
            }
            const float inv = 1.f / s;
            for (int m = 0; m < mvis; m++) row[m] *= inv;
            for (int m = mvis; m < M; m++) row[m] = 0.f;
        }
    }
    __syncthreads();

#pragma unroll
    for (int i = 0; i < 8; i++) {
        int e2 = ltid + i * 64;
        int g = e2 >> 5, d2 = e2 & 31;
        unsigned long long acc = 0ull;
        for (int m = 0; m < mvis; m++) {
            float p = lg[tq * 512 + g * 32 + m];
            acc = fma2(pk2(p, p), pk2f2(*(const float2*)&scv[m * 64 + 2 * d2]), acc);
        }
        float x, y; upk2(acc, x, y);
        *(float2*)&g_comp[n * 2048 + h * 1024 + g * 64 + 2 * d2] = make_float2(x, y);
    }

    if (ltid < 32) {
        float s = 0.f;
        if (ltid < M)
            for (int g = 0; g < 16; g++) s += lg[tq * 512 + g * 32 + ltid];
        ssum[tq * 32 + ltid] = s;
    }
    __syncthreads();

    if (ltid == 0) {
        const int qblk = n >> 6;
        unsigned sel = 0;
        if (qblk + 1 <= 16) {
            sel = (1u << (qblk + 1)) - 1u;
        } else {
            float sc[32];
            for (int m = 0; m < 32; m++) {
                if (m > qblk)                                  sc[m] = -INFINITY;
                else if (m == 0 || m == qblk || m == qblk - 1) sc[m] = INFINITY;
                else                                           sc[m] = ssum[tq * 32 + m];
            }
            for (int t = 0; t < 16; t++) {
                int best = 0; float bv = -INFINITY;
                for (int m = 0; m < 32; m++) {
                    if ((sel >> m) & 1u) continue;
                    if (sc[m] > bv) { bv = sc[m]; best = m; }
                }
                sel |= 1u << best;
            }
        }
        g_sel[n * 2 + h] = sel;
    }
}

// ---------------- main attention on tensor cores (K-prefetch pipelined) ----------------
#define BST 72          // bf16 smem row stride (elements) = 144 bytes
#define SQH 0
#define SQL 9216
#define SKH 18432
#define SKL 27648
#define SVTH 36864
#define SVTL 46080
#define PSH 55296
#define PSL 64512
#define PWH 73728
#define PWL 82944
#define LG_OFF 92160    // float [64][66]
#define PM_OFF 109056   // float [512]
#define HMM_OFF 111104  // float [2][64]
#define HLL_OFF 111616
#define HRR_OFF 112128
#define ATTN_SMEM 112640

__global__ void __launch_bounds__(256, 2) main_attn_kernel(int ntok)
{
    extern __shared__ char dsm[];
    const uint32_t sb = smem_u32(dsm);
    float* lg  = (float*)(dsm + LG_OFF);
    float* pm  = (float*)(dsm + PM_OFF);
    float* hmm = (float*)(dsm + HMM_OFF);
    float* hll = (float*)(dsm + HLL_OFF);
    float* hrr = (float*)(dsm + HRR_OFF);

    // reversed CTA order: heaviest first for tail packing
    const int n0 = (gridDim.x - 1 - blockIdx.x) * 4, h = blockIdx.y;
    const int tid = threadIdx.x;
    const int lane = tid & 31, wid = tid >> 5;
    const int warp_m = wid & 1, warp_n = wid >> 1;
    const int g = lane >> 2, cq = lane & 3;

    const unsigned sel0 = g_sel[n0 * 2 + h],       sel1 = g_sel[(n0 + 1) * 2 + h],
                   sel2 = g_sel[(n0 + 2) * 2 + h], sel3 = g_sel[(n0 + 3) * 2 + h];
    const unsigned selU = sel0 | sel1 | sel2 | sel3;
    const int qblk = n0 >> 6;

    // chunk activity: sparse OR window (window active iff n0 - c*64 <= 575)
    auto active = [&](int c) -> bool {
        return ((selU >> c) & 1u) || ((n0 - c * 64 - 512) <= 63);
    };

    // cp.async helpers: mats 0,1 = K hi/lo; 2,3 = V^T hi/lo
    auto loadK = [&](int c) {
#pragma unroll
        for (int i2 = 0; i2 < 4; i2++) {
            int i = tid + i2 * 256;                 // 0..1023 -> mats 0,1
            int mat = i >> 9, idx = i & 511;
            int row = idx >> 3, c16 = idx & 7;
            const __nv_bfloat16* src = (mat == 0 ? g_kbh : g_kbl)
                                     + (size_t)(c * 64 + row) * 128 + h * 64 + c16 * 8;
            uint32_t dst = sb + SKH + (uint32_t)(mat * 9216 + row * 144 + c16 * 16);
            asm volatile("cp.async.cg.shared.global [%0], [%1], 16;" :: "r"(dst), "l"(src));
        }
        asm volatile("cp.async.commit_group;" ::: "memory");
    };
    auto loadV = [&](int c) {
#pragma unroll
        for (int i2 = 0; i2 < 4; i2++) {
            int i = tid + i2 * 256;                 // mats 2,3
            int mat = i >> 9, idx = i & 511;
            int row = idx >> 3, c16 = idx & 7;
            const __nv_bfloat16* src = (mat == 0 ? g_vth : g_vtl)
                                     + (size_t)(h * 64 + row) * TMAX + c * 64 + c16 * 8;
            uint32_t dst = sb + SVTH + (uint32_t)(mat * 9216 + row * 144 + c16 * 16);
            asm volatile("cp.async.cg.shared.global [%0], [%1], 16;" :: "r"(dst), "l"(src));
        }
        asm volatile("cp.async.commit_group;" ::: "memory");
    };

    // find first active chunk and preload its K+V
    int c0 = 0;
    while (c0 <= qblk && !active(c0)) c0++;
    loadK(c0);
    loadV(c0);

    for (int i = tid; i < 4096; i += 256) {
        int r = i >> 6, d = i & 63;
        float v = g_q[(n0 + (r >> 4)) * 2048 + h * 1024 + (r & 15) * 64 + d] * 0.125f;
        unsigned short hi, lo;
        bsplit(v, hi, lo);
        *(unsigned short*)(dsm + SQH + (r * BST + d) * 2) = hi;
        *(unsigned short*)(dsm + SQL + (r * BST + d) * 2) = lo;
    }
    if (tid < 128) { hmm[tid] = -INFINITY; hll[tid] = 0.f; }

    const int mt = lane >> 3, rin = lane & 7;
    const uint32_t a_base = (uint32_t)(((mt & 1) * 8 + rin) * 144 + ((mt >> 1) * 8) * 2);
    const uint32_t b_base = (uint32_t)((warp_n * 16 + ((mt >= 2) ? 8 : 0) + rin) * 144 + ((mt & 1) * 8) * 2);

    float acc_s[2][2][4] = {}, acc_w[2][2][4] = {};

    for (int c = c0; c <= qblk;) {
        // next active chunk
        int cn = c + 1;
        while (cn <= qblk && !active(cn)) cn++;

        const int base = n0 - c * 64;
        const bool wact = (base - 512) <= 63;
        const bool sact = (selU >> c) & 1u;

        asm volatile("cp.async.wait_group 0;" ::: "memory");
        __syncthreads();

        // ---- S = Q K^T via HMMA (3-product) ----
        {
            float acc[2][2][4] = {};
#pragma unroll
            for (int ks = 0; ks < 4; ks++) {
                uint32_t kh[4], kl[4];
                LDSM4(kh, sb + SKH + b_base + ks * 32);
                LDSM4(kl, sb + SKL + b_base + ks * 32);
#pragma unroll
                for (int mi = 0; mi < 2; mi++) {
                    uint32_t qh[4], ql[4];
                    const uint32_t ao = (uint32_t)((warp_m * 32 + mi * 16) * 144) + a_base + ks * 32;
                    LDSM4(qh, sb + SQH + ao);
                    LDSM4(ql, sb + SQL + ao);
#pragma unroll
                    for (int hf = 0; hf < 2; hf++) {
                        hmma(acc[mi][hf], qh, kh + hf * 2);
                        hmma(acc[mi][hf], qh, kl + hf * 2);
                        hmma(acc[mi][hf], ql, kh + hf * 2);
                    }
                }
            }
#pragma unroll
            for (int mi = 0; mi < 2; mi++) {
                const int r0 = warp_m * 32 + mi * 16 + g;
#pragma unroll
                for (int hf = 0; hf < 2; hf++) {
                    const int col = warp_n * 16 + hf * 8 + cq * 2;
                    *(float2*)&lg[r0 * 66 + col]       = make_float2(acc[mi][hf][0], acc[mi][hf][1]);
                    *(float2*)&lg[(r0 + 8) * 66 + col] = make_float2(acc[mi][hf][2], acc[mi][hf][3]);
                }
            }
        }
        __syncthreads();

        // K region dead from here: prefetch next chunk's K (overlaps softmax + PV)
        if (cn <= qblk) loadK(cn);

        // ---- segmented max (branch-guarded) ----
        {
            const int r = tid >> 2, seg = tid & 3;
            const int q = r >> 4;
            const int jn = min(63, base + q);
            if (sact) {
                const unsigned selq = (q == 0) ? sel0 : (q == 1) ? sel1 : (q == 2) ? sel2 : sel3;
                float ms = -INFINITY;
                if ((selq >> c) & 1u) {
                    const int hi2 = min(seg * 16 + 15, jn);
                    for (int j = seg * 16; j <= hi2; j++) ms = fmaxf(ms, lg[r * 66 + j]);
                }
                pm[tid] = ms;
            }
            if (wact) {
                const int jw0 = base + q - 512;
                float mw = -INFINITY;
                if (jw0 <= 63) {
                    const int lo2 = max(seg * 16, jw0);
                    const int hi2 = min(seg * 16 + 15, jn);
                    for (int j = lo2; j <= hi2; j++) mw = fmaxf(mw, lg[r * 66 + j]);
                }
                pm[256 + tid] = mw;
            }
        }
        __syncthreads();
        if (tid < 128) {
            const int br = tid >> 6, r = tid & 63;
            const bool act = br ? wact : sact;
            if (act) {
                const float* p = pm + br * 256 + r * 4;
                const float cm = fmaxf(fmaxf(p[0], p[1]), fmaxf(p[2], p[3]));
                const float om = hmm[br * 64 + r];
                const float nm = fmaxf(om, cm);
                hmm[br * 64 + r] = nm;
                hrr[br * 64 + r] = (cm == -INFINITY) ? 1.f : __expf(om - nm);
            } else {
                hrr[br * 64 + r] = 1.f;
            }
        }
        __syncthreads();

        // ---- exp + partial sums + split-bf16 P store (branch-guarded) ----
        {
            const int r = tid >> 2, seg = tid & 3;
            const int q = r >> 4;
            const int jn = base + q;
            const uint32_t po = (uint32_t)((r * BST + seg * 16) * 2);
            if (sact) {
                const unsigned selq = (q == 0) ? sel0 : (q == 1) ? sel1 : (q == 2) ? sel2 : sel3;
                const bool srow = (selq >> c) & 1u;
                const float ms = hmm[r];
                float ss = 0.f;
                unsigned short eh[16], el[16];
#pragma unroll
                for (int jj = 0; jj < 16; jj++) {
                    const int j = seg * 16 + jj;
                    float es = (srow && j <= jn) ? __expf(lg[r * 66 + j] - ms) : 0.f;
                    ss += es;
                    bsplit(es, eh[jj], el[jj]);
                }
                pm[tid] = ss;
#pragma unroll
                for (int v4 = 0; v4 < 4; v4++) {
                    *(ushort4*)(dsm + PSH + po + v4 * 8) = make_ushort4(eh[v4*4], eh[v4*4+1], eh[v4*4+2], eh[v4*4+3]);
                    *(ushort4*)(dsm + PSL + po + v4 * 8) = make_ushort4(el[v4*4], el[v4*4+1], el[v4*4+2], el[v4*4+3]);
                }
            }
            if (wact) {
                const int jw0 = base + q - 512;
                const float mw = hmm[64 + r];
                float sw = 0.f;
                unsigned short wh[16], wl[16];
#pragma unroll
                for (int jj = 0; jj < 16; jj++) {
                    const int j = seg * 16 + jj;
                    float ew = (j <= jn && j >= jw0) ? __expf(lg[r * 66 + j] - mw) : 0.f;
                    sw += ew;
                    bsplit(ew, wh[jj], wl[jj]);
                }
                pm[256 + tid] = sw;
#pragma unroll
                for (int v4 = 0; v4 < 4; v4++) {
                    *(ushort4*)(dsm + PWH + po + v4 * 8) = make_ushort4(wh[v4*4], wh[v4*4+1], wh[v4*4+2], wh[v4*4+3]);
                    *(ushort4*)(dsm + PWL + po + v4 * 8) = make_ushort4(wl[v4*4], wl[v4*4+1], wl[v4*4+2], wl[v4*4+3]);
                }
            }
        }
        __syncthreads();
        if (tid < 128) {
            const int br = tid >> 6, r = tid & 63;
            const bool act = br ? wact : sact;
            if (act) {
                const float* p = pm + br * 256 + r * 4;
                hll[br * 64 + r] = hll[br * 64 + r] * hrr[br * 64 + r]
                                 + (p[0] + p[1]) + (p[2] + p[3]);
            }
        }

        // ---- PV via HMMA with flash rescale (branch-guarded) ----
        if (sact) {
#pragma unroll
            for (int mi = 0; mi < 2; mi++) {
                const int rb = warp_m * 32 + mi * 16 + g;
                const float rs0 = hrr[rb], rs1 = hrr[rb + 8];
#pragma unroll
                for (int hf = 0; hf < 2; hf++) {
                    acc_s[mi][hf][0] *= rs0; acc_s[mi][hf][1] *= rs0;
                    acc_s[mi][hf][2] *= rs1; acc_s[mi][hf][3] *= rs1;
                }
            }
        }
        if (wact) {
#pragma unroll
            for (int mi = 0; mi < 2; mi++) {
                const int rb = warp_m * 32 + mi * 16 + g;
                const float rw0 = hrr[64 + rb], rw1 = hrr[64 + rb + 8];
#pragma unroll
                for (int hf = 0; hf < 2; hf++) {
                    acc_w[mi][hf][0] *= rw0; acc_w[mi][hf][1] *= rw0;
                    acc_w[mi][hf][2] *= rw1; acc_w[mi][hf][3] *= rw1;
                }
            }
        }
#pragma unroll
        for (int ks = 0; ks < 4; ks++) {
            uint32_t vh[4], vl[4];
            LDSM4(vh, sb + SVTH + b_base + ks * 32);
            LDSM4(vl, sb + SVTL + b_base + ks * 32);
#pragma unroll
            for (int mi = 0; mi < 2; mi++) {
                const uint32_t ao = (uint32_t)((warp_m * 32 + mi * 16) * 144) + a_base + ks * 32;
                if (sact) {
                    uint32_t ph[4], pl[4];
                    LDSM4(ph, sb + PSH + ao);
                    LDSM4(pl, sb + PSL + ao);
#pragma unroll
                    for (int hf = 0; hf < 2; hf++) {
                        hmma(acc_s[mi][hf], ph, vh + hf * 2);
                        hmma(acc_s[mi][hf], ph, vl + hf * 2);
                        hmma(acc_s[mi][hf], pl, vh + hf * 2);
                    }
                }
                if (wact) {
                    uint32_t ph[4], pl[4];
                    LDSM4(ph, sb + PWH + ao);
                    LDSM4(pl, sb + PWL + ao);
#pragma unroll
                    for (int hf = 0; hf < 2; hf++) {
                        hmma(acc_w[mi][hf], ph, vh + hf * 2);
                        hmma(acc_w[mi][hf], ph, vl + hf * 2);
                        hmma(acc_w[mi][hf], pl, vh + hf * 2);
                    }
                }
            }
        }
        __syncthreads();
        // V region dead: prefetch next chunk's V
        if (cn <= qblk) loadV(cn);
        c = cn;
    }

    // ---- gated fusion epilogue ----
#pragma unroll
    for (int mi = 0; mi < 2; mi++) {
#pragma unroll
        for (int half = 0; half < 2; half++) {
            const int r = warp_m * 32 + mi * 16 + g + half * 8;
            const int nq = n0 + (r >> 4);
            const int head = r & 15;
            const int hq = h * 16 + head;
            const float gl0 = g_kvg[nq * 352 + 256 + hq * 3 + 0];
            const float gl1 = g_kvg[nq * 352 + 256 + hq * 3 + 1];
            const float gl2 = g_kvg[nq * 352 + 256 + hq * 3 + 2];
            const float g0 = 1.f / (1.f + __expf(-gl0));
            const float g1 = 1.f / (1.f + __expf(-gl1));
            const float g2 = 1.f / (1.f + __expf(-gl2));
            const float inv_s = 1.f / hll[r];
            const float inv_w = 1.f / hll[64 + r];
#pragma unroll
            for (int hf = 0; hf < 2; hf++) {
                const int col = warp_n * 16 + hf * 8 + cq * 2;
                const int oi = nq * 2048 + h * 1024 + head * 64 + col;
                const float2 cmp = *(const float2*)&g_comp[oi];
                const float o0 = g0 * cmp.x + g1 * acc_s[mi][hf][half * 2]     * inv_s
                                            + g2 * acc_w[mi][hf][half * 2]     * inv_w;
                const float o1 = g0 * cmp.y + g1 * acc_s[mi][hf][half * 2 + 1] * inv_s
                                            + g2 * acc_w[mi][hf][half * 2 + 1] * inv_w;
                ushort2 hh, ll;
                bsplit(o0, hh.x, ll.x);
                bsplit(o1, hh.y, ll.y);
                *(ushort2*)(g_fh + oi) = hh;
                *(ushort2*)(g_fl + oi) = ll;
            }
        }
    }
}

// ---------------- launch ----------------
extern "C" void kernel_launch(void* const* d_in, const int* in_sizes, int n_in,
                              void* d_out, int out_size)
{
    const float* x   = (const float*)d_in[0];
    const float* Wq  = (const float*)d_in[2];
    const float* Wk  = (const float*)d_in[3];
    const float* Wv  = (const float*)d_in[4];
    const float* Wo  = (const float*)d_in[5];
    const float* Wg  = (const float*)d_in[6];
    const float* wck = (const float*)d_in[7];
    const float* wcv = (const float*)d_in[8];
    const float* pe  = (const float*)d_in[9];
    float* out = (float*)d_out;

    const int ntok = in_sizes[0] / 2048;     // T = 2048
    const int M = ntok / 64;

    float *q, *kvg;
    cudaGetSymbolAddress((void**)&q,   g_q);
    cudaGetSymbolAddress((void**)&kvg, g_kvg);

    __nv_bfloat16 *xh, *xl, *fh, *fl, *wqh, *wql, *woh, *wol, *wkvgh, *wkvgl;
    cudaGetSymbolAddress((void**)&xh, g_xh);     cudaGetSymbolAddress((void**)&xl, g_xl);
    cudaGetSymbolAddress((void**)&fh, g_fh);     cudaGetSymbolAddress((void**)&fl, g_fl);
    cudaGetSymbolAddress((void**)&wqh, g_wqt_h); cudaGetSymbolAddress((void**)&wql, g_wqt_l);
    cudaGetSymbolAddress((void**)&woh, g_wot_h); cudaGetSymbolAddress((void**)&wol, g_wot_l);
    cudaGetSymbolAddress((void**)&wkvgh, g_wkvgt_h);
    cudaGetSymbolAddress((void**)&wkvgl, g_wkvgt_l);

    cudaFuncSetAttribute(mma_gemm, cudaFuncAttributeMaxDynamicSharedMemorySize, SMEM_GEMM);
    cudaFuncSetAttribute(mma_gemm128, cudaFuncAttributeMaxDynamicSharedMemorySize, SMEM_GEMM8);
    cudaFuncSetAttribute(main_attn_kernel, cudaFuncAttributeMaxDynamicSharedMemorySize, ATTN_SMEM);
    cudaFuncSetAttribute(comp_attn_kernel, cudaFuncAttributeMaxDynamicSharedMemorySize, CSMEM);

    const int tot = ntok * 2048;
    dim3 tb(32, 8);

    split_fp32<<<(tot / 4 + 255) / 256, 256>>>((const float4*)x, xh, xl, tot / 4);                // 0
    transpose_split<<<dim3(64, 64), tb>>>(Wq, wqh, wql, 2048, 2048);                              // 1
    transpose_split<<<dim3(4,  64), tb>>>(Wk, wkvgh,              wkvgl,              2048, 128); // 2
    mma_gemm<<<dim3(8, ntok / 128), 512, SMEM_GEMM>>>(xh, xl, wqh, wql, q, ntok, 2048, 2048);     // 3 <- ncu
    transpose_split<<<dim3(4,  64), tb>>>(Wv, wkvgh + 128 * 2048, wkvgl + 128 * 2048, 2048, 128); // 4
    transpose_split<<<dim3(3,  64), tb>>>(Wg, wkvgh + 256 * 2048, wkvgl + 256 * 2048, 2048, 96);  // 5
    mma_gemm128<<<dim3(3, ntok / 128), 256, SMEM_GEMM8>>>(xh, xl, wkvgh, wkvgl, kvg, ntok, 352, 2048);

    kv_prep<<<dim3(ntok / 32, 2, 2), tb>>>(ntok);
    compress_kernel<<<dim3(M, 2), 64>>>(wck, wcv, pe);
    comp_attn_kernel<<<dim3(ntok / 8, 2), 512, CSMEM>>>(ntok);
    main_attn_kernel<<<dim3(ntok / 4, 2), 256, ATTN_SMEM>>>(ntok);

    transpose_split<<<dim3(64, 64), tb>>>(Wo, woh, wol, 2048, 2048);
    mma_gemm<<<dim3(8, ntok / 128), 512, SMEM_GEMM>>>(fh, fl, woh, wol, out, ntok, 2048, 2048);
}

// round 14
// speedup vs baseline: 1.2834x; 1.0076x over previous
#include <cuda_runtime.h>
#include <cuda_bf16.h>
#include <math.h>
#include <stdint.h>

// Problem constants (T=2048, H=2048, HQ=32, HKV=2, D=64, G=16, M<=32)
#define TMAX 2048
#define MMAX 32
#define QSCALE 0.180336879f   // 0.125 * log2(e)

// ---------------- scratch (no allocation allowed) ----------------
__device__ float    g_q[TMAX * 2048];      // [n, HQ*D]
__device__ float    g_kvg[TMAX * 352];     // [n, k(128) | v(128) | gate(96)]
__device__ float    g_ck[MMAX * 2 * 64];
__device__ float    g_cv[MMAX * 2 * 64];
__device__ float    g_comp[TMAX * 2048];
__device__ unsigned g_sel[TMAX * 2];

// bf16 split operands
__device__ __nv_bfloat16 g_xh[2048 * 2048], g_xl[2048 * 2048];
__device__ __nv_bfloat16 g_fh[2048 * 2048], g_fl[2048 * 2048];
__device__ __nv_bfloat16 g_wqt_h[2048 * 2048], g_wqt_l[2048 * 2048];   // Wq^T [N,K]
__device__ __nv_bfloat16 g_wot_h[2048 * 2048], g_wot_l[2048 * 2048];   // Wo^T
__device__ __nv_bfloat16 g_wkvgt_h[352 * 2048], g_wkvgt_l[352 * 2048]; // [Wk|Wv|Wg]^T
// attention K / V^T split-bf16
__device__ __nv_bfloat16 g_kbh[TMAX * 128], g_kbl[TMAX * 128];          // [n][h][64]
__device__ __nv_bfloat16 g_vth[2 * 64 * TMAX], g_vtl[2 * 64 * TMAX];    // [h][d][n]

__device__ __forceinline__ uint32_t smem_u32(const void* p) {
    uint32_t a;
    asm("{ .reg .u64 t; cvta.to.shared.u64 t, %1; cvt.u32.u64 %0, t; }" : "=r"(a) : "l"(p));
    return a;
}

// ---------------- packed f32x2 helpers ----------------
__device__ __forceinline__ unsigned long long pk2(float x, float y) {
    unsigned long long r;
    asm("mov.b64 %0, {%1,%2};" : "=l"(r) : "f"(x), "f"(y));
    return r;
}
__device__ __forceinline__ unsigned long long pk2f2(float2 v) { return pk2(v.x, v.y); }
__device__ __forceinline__ void upk2(unsigned long long r, float& x, float& y) {
    asm("mov.b64 {%0,%1}, %2;" : "=f"(x), "=f"(y) : "l"(r));
}
__device__ __forceinline__ unsigned long long fma2(unsigned long long a,
                                                   unsigned long long b,
                                                   unsigned long long c) {
    unsigned long long d;
    asm("fma.rn.f32x2 %0, %1, %2, %3;" : "=l"(d) : "l"(a), "l"(b), "l"(c));
    return d;
}

// ---------------- mma helpers ----------------
#define LDSM4(r, addr) \
    asm volatile("ldmatrix.sync.aligned.m8n8.x4.shared.b16 {%0,%1,%2,%3}, [%4];" \
                 : "=r"((r)[0]), "=r"((r)[1]), "=r"((r)[2]), "=r"((r)[3]) : "r"(addr))

__device__ __forceinline__ void hmma(float* c, const uint32_t* a, const uint32_t* b) {
    asm volatile("mma.sync.aligned.m16n8k16.row.col.f32.bf16.bf16.f32 "
                 "{%0,%1,%2,%3},{%4,%5,%6,%7},{%8,%9},{%0,%1,%2,%3};"
                 : "+f"(c[0]), "+f"(c[1]), "+f"(c[2]), "+f"(c[3])
                 : "r"(a[0]), "r"(a[1]), "r"(a[2]), "r"(a[3]), "r"(b[0]), "r"(b[1]));
}

__device__ __forceinline__ void bsplit(float v, unsigned short& hi, unsigned short& lo) {
    __nv_bfloat16 h = __float2bfloat16(v);
    __nv_bfloat16 l = __float2bfloat16(v - __bfloat162float(h));
    hi = *(unsigned short*)&h; lo = *(unsigned short*)&l;
}

// ================= prep kernels =================
__global__ void split_fp32(const float4* __restrict__ A,
                           __nv_bfloat16* __restrict__ Ah,
                           __nv_bfloat16* __restrict__ Al, int total4)
{
    int i = blockIdx.x * 256 + threadIdx.x;
    if (i < total4) {
        float4 v = A[i];
        ushort4 hh, ll;
        bsplit(v.x, hh.x, ll.x); bsplit(v.y, hh.y, ll.y);
        bsplit(v.z, hh.z, ll.z); bsplit(v.w, hh.w, ll.w);
        *(ushort4*)(Ah + 4 * (size_t)i) = hh;
        *(ushort4*)(Al + 4 * (size_t)i) = ll;
    }
}

__global__ void transpose_split(const float* __restrict__ W,
                                __nv_bfloat16* __restrict__ Th,
                                __nv_bfloat16* __restrict__ Tl, int K, int N)
{
    __shared__ float t[32][33];
    const int k0 = blockIdx.y * 32, n0 = blockIdx.x * 32;
    const int tx = threadIdx.x, ty = threadIdx.y;  // 32 x 8
    for (int i = ty; i < 32; i += 8) {
        int k = k0 + i, n = n0 + tx;
        t[i][tx] = (n < N && k < K) ? W[(size_t)k * N + n] : 0.f;
    }
    __syncthreads();
    for (int i = ty; i < 32; i += 8) {
        int n = n0 + i, k = k0 + tx;
        if (n < N && k < K) {
            unsigned short hi, lo;
            bsplit(t[tx][i], hi, lo);
            *(unsigned short*)(Th + (size_t)n * K + k) = hi;
            *(unsigned short*)(Tl + (size_t)n * K + k) = lo;
        }
    }
}

// K split + V transpose-split. grid (n/32, 2, 2), block (32,8)
__global__ void kv_prep(int ntok)
{
    __shared__ float t[32][33];
    const int n0 = blockIdx.x * 32, h = blockIdx.y, dh = blockIdx.z * 32;
    const int tx = threadIdx.x, ty = threadIdx.y;
    for (int i = ty; i < 32; i += 8) {
        const int n = n0 + i, d = dh + tx;
        float kv = g_kvg[n * 352 + h * 64 + d];
        unsigned short hi, lo;
        bsplit(kv, hi, lo);
        *(unsigned short*)(g_kbh + n * 128 + h * 64 + d) = hi;
        *(unsigned short*)(g_kbl + n * 128 + h * 64 + d) = lo;
        t[i][tx] = g_kvg[n * 352 + h * 64 + 128 + d];
    }
    __syncthreads();
    for (int i = ty; i < 32; i += 8) {
        const int d = dh + i, n = n0 + tx;
        unsigned short hi, lo;
        bsplit(t[tx][i], hi, lo);
        *(unsigned short*)(g_vth + (h * 64 + d) * TMAX + n) = hi;
        *(unsigned short*)(g_vtl + (h * 64 + d) * TMAX + n) = lo;
    }
}

// ================= split-bf16 GEMM, 128x256 tile, 512 threads (big GEMMs) =================
#define A_MAT 14336
#define B_MAT 28672
#define STAGE_BYTES 86016
#define SMEM_GEMM (2 * STAGE_BYTES)

__global__ void __launch_bounds__(512) mma_gemm(
    const __nv_bfloat16* __restrict__ Ah, const __nv_bfloat16* __restrict__ Al,
    const __nv_bfloat16* __restrict__ Bth, const __nv_bfloat16* __restrict__ Btl,
    float* __restrict__ C, int M, int N, int K)
{
    extern __shared__ char smem[];
    const uint32_t sb = smem_u32(smem);
    const int tid = threadIdx.x;
    const int lane = tid & 31, wid = tid >> 5;
    const int warp_m = wid & 1, warp_n = wid >> 1;   // 2 x 8 warps
    const int row0 = blockIdx.y * 128, col0 = blockIdx.x * 256;
    const int nchunk = K >> 5;

    float acc[4][4][4];
#pragma unroll
    for (int a = 0; a < 4; a++)
#pragma unroll
        for (int b = 0; b < 4; b++)
#pragma unroll
            for (int c = 0; c < 4; c++) acc[a][b][c] = 0.f;

    const int mt = lane >> 3, rin = lane & 7;
    const uint32_t a_off = (uint32_t)((warp_m * 64 + (mt & 1) * 8 + rin) * 112 + ((mt >> 1) * 8) * 2);
    const uint32_t b_off = (uint32_t)((warp_n * 32 + ((mt >= 2) ? 8 : 0) + rin) * 112 + ((mt & 1) * 8) * 2);

    auto load_chunk = [&](int c) {
        const int k0 = c * 32;
        const uint32_t st = sb + (uint32_t)(c & 1) * STAGE_BYTES;
#pragma unroll
        for (int i = 0; i < 6; i++) {
            int v = tid + i * 512;
            uint32_t dst;
            const __nv_bfloat16* srcp;
            int sz = 16;
            if (v < 1024) {
                int mat = v >> 9, r = (v >> 2) & 127, c16 = v & 3;
                dst = st + mat * A_MAT + r * 112 + c16 * 16;
                srcp = (mat ? Al : Ah) + (size_t)(row0 + r) * K + k0 + c16 * 8;
            } else {
                int vb = v - 1024;
                int mat = vb >> 10, r = (vb >> 2) & 255, c16 = vb & 3;
                dst = st + 2 * A_MAT + mat * B_MAT + r * 112 + c16 * 16;
                int n = col0 + r;
                int nn = (n < N) ? n : 0;
                if (n >= N) sz = 0;
                srcp = (mat ? Btl : Bth) + (size_t)nn * K + k0 + c16 * 8;
            }
            asm volatile("cp.async.cg.shared.global [%0], [%1], 16, %2;"
                         :: "r"(dst), "l"(srcp), "r"(sz));
        }
        asm volatile("cp.async.commit_group;" ::: "memory");
    };

    load_chunk(0);

    for (int c = 0; c < nchunk; c++) {
        if (c + 1 < nchunk) {
            load_chunk(c + 1);
            asm volatile("cp.async.wait_group 1;" ::: "memory");
        } else {
            asm volatile("cp.async.wait_group 0;" ::: "memory");
        }
        __syncthreads();

        const uint32_t st = sb + (uint32_t)(c & 1) * STAGE_BYTES;
#pragma unroll
        for (int ks = 0; ks < 2; ks++) {
            uint32_t ah[4][4], al[4][4];
#pragma unroll
            for (int mi = 0; mi < 4; mi++) {
                uint32_t addr = st + a_off + mi * (16 * 112) + ks * 32;
                LDSM4(ah[mi], addr);
                LDSM4(al[mi], addr + A_MAT);
            }
#pragma unroll
            for (int b2 = 0; b2 < 2; b2++) {
                uint32_t bh[4], bl[4];
                uint32_t baddr = st + 2 * A_MAT + b_off + b2 * (16 * 112) + ks * 32;
                LDSM4(bh, baddr);
                LDSM4(bl, baddr + B_MAT);
#pragma unroll
                for (int p = 0; p < 3; p++) {
#pragma unroll
                    for (int mi = 0; mi < 4; mi++) {
#pragma unroll
                        for (int hf = 0; hf < 2; hf++) {
                            const int nt = b2 * 2 + hf;
                            const uint32_t* A_ = (p == 2) ? al[mi] : ah[mi];
                            const uint32_t* B_ = (p == 1) ? bl : bh;
                            hmma(acc[mi][nt], A_, B_ + hf * 2);
                        }
                    }
                }
            }
        }
        __syncthreads();
    }

    const int g = lane >> 2, c2 = lane & 3;
#pragma unroll
    for (int mi = 0; mi < 4; mi++) {
        const int r = row0 + warp_m * 64 + mi * 16 + g;
#pragma unroll
        for (int nt = 0; nt < 4; nt++) {
            const int col = col0 + warp_n * 32 + nt * 8 + c2 * 2;
            if (col < N) {
                *(float2*)(C + (size_t)r * N + col)       = make_float2(acc[mi][nt][0], acc[mi][nt][1]);
                *(float2*)(C + (size_t)(r + 8) * N + col) = make_float2(acc[mi][nt][2], acc[mi][nt][3]);
            }
        }
    }
}

// ================= split-bf16 GEMM, 128x128 tile, 256 threads (narrow GEMMs) =================
#define MAT_BYTES8  (128 * 112)
#define STAGE8 (4 * MAT_BYTES8)
#define SMEM_GEMM8 (2 * STAGE8)

__global__ void __launch_bounds__(256) mma_gemm128(
    const __nv_bfloat16* __restrict__ Ah, const __nv_bfloat16* __restrict__ Al,
    const __nv_bfloat16* __restrict__ Bth, const __nv_bfloat16* __restrict__ Btl,
    float* __restrict__ C, int M, int N, int K)
{
    extern __shared__ char smem[];
    const uint32_t sb = smem_u32(smem);
    const int tid = threadIdx.x;
    const int lane = tid & 31, wid = tid >> 5;
    const int warp_m = wid & 1, warp_n = wid >> 1;
    const int row0 = blockIdx.y * 128, col0 = blockIdx.x * 128;
    const int nchunk = K >> 5;

    float acc[4][4][4];
#pragma unroll
    for (int a = 0; a < 4; a++)
#pragma unroll
        for (int b = 0; b < 4; b++)
#pragma unroll
            for (int c = 0; c < 4; c++) acc[a][b][c] = 0.f;

    const int mt = lane >> 3, rin = lane & 7;
    const uint32_t a_off = (uint32_t)((warp_m * 64 + (mt & 1) * 8 + rin) * 112 + ((mt >> 1) * 8) * 2);
    const uint32_t b_off = (uint32_t)((warp_n * 32 + ((mt >= 2) ? 8 : 0) + rin) * 112 + ((mt & 1) * 8) * 2);

    auto load_chunk = [&](int c) {
        const int k0 = c * 32;
        const uint32_t st = sb + (uint32_t)(c & 1) * STAGE8;
#pragma unroll
        for (int i = 0; i < 8; i++) {
            int v = tid + i * 256;
            int mat = v >> 9, r = (v >> 2) & 127, c16 = v & 3;
            uint32_t dst = st + mat * MAT_BYTES8 + r * 112 + c16 * 16;
            const __nv_bfloat16* srcp;
            int sz = 16;
            if (mat == 0)      srcp = Ah + (size_t)(row0 + r) * K + k0 + c16 * 8;
            else if (mat == 1) srcp = Al + (size_t)(row0 + r) * K + k0 + c16 * 8;
            else {
                int n = col0 + r;
                int nn = (n < N) ? n : 0;
                if (n >= N) sz = 0;
                srcp = (mat == 2 ? Bth : Btl) + (size_t)nn * K + k0 + c16 * 8;
            }
            asm volatile("cp.async.cg.shared.global [%0], [%1], 16, %2;"
                         :: "r"(dst), "l"(srcp), "r"(sz));
        }
        asm volatile("cp.async.commit_group;" ::: "memory");
    };

    load_chunk(0);

    for (int c = 0; c < nchunk; c++) {
        if (c + 1 < nchunk) {
            load_chunk(c + 1);
            asm volatile("cp.async.wait_group 1;" ::: "memory");
        } else {
            asm volatile("cp.async.wait_group 0;" ::: "memory");
        }
        __syncthreads();

        const uint32_t st = sb + (uint32_t)(c & 1) * STAGE8;
#pragma unroll
        for (int ks = 0; ks < 2; ks++) {
            uint32_t ah[4][4], al[4][4];
#pragma unroll
            for (int mi = 0; mi < 4; mi++) {
                uint32_t addr = st + a_off + mi * (16 * 112) + ks * 32;
                LDSM4(ah[mi], addr);
                LDSM4(al[mi], addr + MAT_BYTES8);
            }
#pragma unroll
            for (int b2 = 0; b2 < 2; b2++) {
                uint32_t bh[4], bl[4];
                uint32_t baddr = st + 2 * MAT_BYTES8 + b_off + b2 * (16 * 112) + ks * 32;
                LDSM4(bh, baddr);
                LDSM4(bl, baddr + MAT_BYTES8);
#pragma unroll
                for (int p = 0; p < 3; p++) {
#pragma unroll
                    for (int mi = 0; mi < 4; mi++) {
#pragma unroll
                        for (int hf = 0; hf < 2; hf++) {
                            const int nt = b2 * 2 + hf;
                            const uint32_t* A_ = (p == 2) ? al[mi] : ah[mi];
                            const uint32_t* B_ = (p == 1) ? bl : bh;
                            hmma(acc[mi][nt], A_, B_ + hf * 2);
                        }
                    }
                }
            }
        }
        __syncthreads();
    }

    const int g = lane >> 2, c2 = lane & 3;
#pragma unroll
    for (int mi = 0; mi < 4; mi++) {
        const int r = row0 + warp_m * 64 + mi * 16 + g;
#pragma unroll
        for (int nt = 0; nt < 4; nt++) {
            const int col = col0 + warp_n * 32 + nt * 8 + c2 * 2;
            if (col < N) {
                *(float2*)(C + (size_t)r * N + col)       = make_float2(acc[mi][nt][0], acc[mi][nt][1]);
                *(float2*)(C + (size_t)(r + 8) * N + col) = make_float2(acc[mi][nt][2], acc[mi][nt][3]);
            }
        }
    }
}

// ---------------- compressed tokens ----------------
__global__ void compress_kernel(const float* __restrict__ wck,
                                const float* __restrict__ wcv,
                                const float* __restrict__ pe)
{
    const int m = blockIdx.x, h = blockIdx.y, d = threadIdx.x;  // 64 threads
    float a = 0.f, b = 0.f;
    for (int t = 0; t < 64; t++) {
        const float wk = wck[h * 64 + t];
        const float wv = wcv[h * 64 + t];
        const int row = m * 64 + t;
        a = fmaf(g_kvg[row * 352 + h * 64 + d] + pe[(h * 64 + t) * 64 + d], wk, a);
        b = fmaf(g_kvg[row * 352 + 128 + h * 64 + d], wv, b);
    }
    g_ck[(m * 2 + h) * 64 + d] = a;
    g_cv[(m * 2 + h) * 64 + d] = b;
}

// ---------------- compressed attention + top-k, 8 tokens per CTA, dynamic smem ----------------
#define CSMEM (66816)
__global__ void __launch_bounds__(512) comp_attn_kernel(int ntok)
{
    extern __shared__ float csm[];
    float*  sq   = csm;                        // [8][1024] prescaled Q (log2 domain)
    float2* ckp  = (float2*)(csm + 8192);      // [32][33] d-pair ck
    float*  scv  = csm + 8192 + 2112;          // [32][64]
    float*  lg   = scv + 2048;                 // [8][512]
    float*  ssum = lg + 4096;                  // [8][32]

    const int n0 = blockIdx.x * 8, h = blockIdx.y;
    const int tid = threadIdx.x;
    const int tq = tid >> 6, ltid = tid & 63;
    const int M = ntok >> 6;

    for (int i = tid; i < 8192; i += 512) {
        int q = i >> 10;
        sq[i] = g_q[(n0 + q) * 2048 + h * 1024 + (i & 1023)] * QSCALE;
    }
    for (int i = tid; i < M * 32; i += 512) {
        int m = i >> 5, d2 = i & 31;
        ckp[d2 * 33 + m] = *(const float2*)&g_ck[(m * 2 + h) * 64 + 2 * d2];
    }
    for (int i = tid; i < M * 64; i += 512)
        scv[i] = g_cv[((i >> 6) * 2 + h) * 64 + (i & 63)];
    __syncthreads();

    const int n = n0 + tq;
    const int mvis = (n >= 63) ? (((n - 63) >> 6) + 1) : 0;

#pragma unroll
    for (int i = 0; i < 8; i++) {
        int e = ltid + i * 64;
        int g = e >> 5, m = e & 31;
        unsigned long long acc = 0ull;
#pragma unroll
        for (int d2 = 0; d2 < 32; d2++) {
            unsigned long long qp = pk2f2(*(const float2*)&sq[tq * 1024 + g * 64 + 2 * d2]);
            acc = fma2(qp, pk2f2(ckp[d2 * 33 + m]), acc);
        }
        float x, y; upk2(acc, x, y);
        lg[tq * 512 + g * 32 + m] = x + y;
    }
    __syncthreads();

    if (ltid < 16) {
        float* row = lg + tq * 512 + ltid * 32;
        if (mvis == 0) {
            for (int m = 0; m < M; m++) row[m] = 0.f;
        } else {
            float mx = -INFINITY;
            for (int m = 0; m < mvis; m++) mx = fmaxf(mx, row[m]);
            float s = 0.f;
            for (int m = 0; m < mvis; m++) {
                float p = exp2f(row[m] - mx);
                row[m] = p; s += p;
            }
            const float inv = 1.f / s;
            for (int m = 0; m < mvis; m++) row[m] *= inv;
            for (int m = mvis; m < M; m++) row[m] = 0.f;
        }
    }
    __syncthreads();

#pragma unroll
    for (int i = 0; i < 8; i++) {
        int e2 = ltid + i * 64;
        int g = e2 >> 5, d2 = e2 & 31;
        unsigned long long acc = 0ull;
        for (int m = 0; m < mvis; m++) {
            float p = lg[tq * 512 + g * 32 + m];
            acc = fma2(pk2(p, p), pk2f2(*(const float2*)&scv[m * 64 + 2 * d2]), acc);
        }
        float x, y; upk2(acc, x, y);
        *(float2*)&g_comp[n * 2048 + h * 1024 + g * 64 + 2 * d2] = make_float2(x, y);
    }

    if (ltid < 32) {
        float s = 0.f;
        if (ltid < M)
            for (int g = 0; g < 16; g++) s += lg[tq * 512 + g * 32 + ltid];
        ssum[tq * 32 + ltid] = s;
    }
    __syncthreads();

    if (ltid == 0) {
        const int qblk = n >> 6;
        unsigned sel = 0;
        if (qblk + 1 <= 16) {
            sel = (1u << (qblk + 1)) - 1u;
        } else {
            float sc[32];
            for (int m = 0; m < 32; m++) {
                if (m > qblk)                                  sc[m] = -INFINITY;
                else if (m == 0 || m == qblk || m == qblk - 1) sc[m] = INFINITY;
                else                                           sc[m] = ssum[tq * 32 + m];
            }
            for (int t = 0; t < 16; t++) {
                int best = 0; float bv = -INFINITY;
                for (int m = 0; m < 32; m++) {
                    if ((sel >> m) & 1u) continue;
                    if (sc[m] > bv) { bv = sc[m]; best = m; }
                }
                sel |= 1u << best;
            }
        }
        g_sel[n * 2 + h] = sel;
    }
}

// ---------------- main attention on tensor cores (K-prefetch pipelined, shared exp) ----------------
#define BST 72          // bf16 smem row stride (elements) = 144 bytes
#define SQH 0
#define SQL 9216
#define SKH 18432
#define SKL 27648
#define SVTH 36864
#define SVTL 46080
#define PSH 55296
#define PSL 64512
#define PWH 73728
#define PWL 82944
#define LG_OFF 92160    // float [64][66]
#define PM_OFF 109056   // float [512]
#define HMM_OFF 111104  // float [2][64]
#define HLL_OFF 111616
#define HRR_OFF 112128
#define ATTN_SMEM 112640

__global__ void __launch_bounds__(256, 2) main_attn_kernel(int ntok)
{
    extern __shared__ char dsm[];
    const uint32_t sb = smem_u32(dsm);
    float* lg  = (float*)(dsm + LG_OFF);
    float* pm  = (float*)(dsm + PM_OFF);
    float* hmm = (float*)(dsm + HMM_OFF);
    float* hll = (float*)(dsm + HLL_OFF);
    float* hrr = (float*)(dsm + HRR_OFF);

    // reversed CTA order: heaviest first for tail packing
    const int n0 = (gridDim.x - 1 - blockIdx.x) * 4, h = blockIdx.y;
    const int tid = threadIdx.x;
    const int lane = tid & 31, wid = tid >> 5;
    const int warp_m = wid & 1, warp_n = wid >> 1;
    const int g = lane >> 2, cq = lane & 3;

    const unsigned sel0 = g_sel[n0 * 2 + h],       sel1 = g_sel[(n0 + 1) * 2 + h],
                   sel2 = g_sel[(n0 + 2) * 2 + h], sel3 = g_sel[(n0 + 3) * 2 + h];
    const unsigned selU = sel0 | sel1 | sel2 | sel3;
    const int qblk = n0 >> 6;

    auto active = [&](int c) -> bool {
        return ((selU >> c) & 1u) || ((n0 - c * 64 - 512) <= 63);
    };

    auto loadK = [&](int c) {
#pragma unroll
        for (int i2 = 0; i2 < 4; i2++) {
            int i = tid + i2 * 256;
            int mat = i >> 9, idx = i & 511;
            int row = idx >> 3, c16 = idx & 7;
            const __nv_bfloat16* src = (mat == 0 ? g_kbh : g_kbl)
                                     + (size_t)(c * 64 + row) * 128 + h * 64 + c16 * 8;
            uint32_t dst = sb + SKH + (uint32_t)(mat * 9216 + row * 144 + c16 * 16);
            asm volatile("cp.async.cg.shared.global [%0], [%1], 16;" :: "r"(dst), "l"(src));
        }
        asm volatile("cp.async.commit_group;" ::: "memory");
    };
    auto loadV = [&](int c) {
#pragma unroll
        for (int i2 = 0; i2 < 4; i2++) {
            int i = tid + i2 * 256;
            int mat = i >> 9, idx = i & 511;
            int row = idx >> 3, c16 = idx & 7;
            const __nv_bfloat16* src = (mat == 0 ? g_vth : g_vtl)
                                     + (size_t)(h * 64 + row) * TMAX + c * 64 + c16 * 8;
            uint32_t dst = sb + SVTH + (uint32_t)(mat * 9216 + row * 144 + c16 * 16);
            asm volatile("cp.async.cg.shared.global [%0], [%1], 16;" :: "r"(dst), "l"(src));
        }
        asm volatile("cp.async.commit_group;" ::: "memory");
    };

    int c0 = 0;
    while (c0 <= qblk && !active(c0)) c0++;
    loadK(c0);
    loadV(c0);

    for (int i = tid; i < 4096; i += 256) {
        int r = i >> 6, d = i & 63;
        float v = g_q[(n0 + (r >> 4)) * 2048 + h * 1024 + (r & 15) * 64 + d] * QSCALE;
        unsigned short hi, lo;
        bsplit(v, hi, lo);
        *(unsigned short*)(dsm + SQH + (r * BST + d) * 2) = hi;
        *(unsigned short*)(dsm + SQL + (r * BST + d) * 2) = lo;
    }
    if (tid < 128) { hmm[tid] = -INFINITY; hll[tid] = 0.f; }

    const int mt = lane >> 3, rin = lane & 7;
    const uint32_t a_base = (uint32_t)(((mt & 1) * 8 + rin) * 144 + ((mt >> 1) * 8) * 2);
    const uint32_t b_base = (uint32_t)((warp_n * 16 + ((mt >= 2) ? 8 : 0) + rin) * 144 + ((mt & 1) * 8) * 2);

    float acc_s[2][2][4] = {}, acc_w[2][2][4] = {};

    for (int c = c0; c <= qblk;) {
        int cn = c + 1;
        while (cn <= qblk && !active(cn)) cn++;

        const int base = n0 - c * 64;
        const bool wact = (base - 512) <= 63;
        const bool sact = (selU >> c) & 1u;

        asm volatile("cp.async.wait_group 0;" ::: "memory");
        __syncthreads();

        // ---- S = Q K^T via HMMA (3-product) ----
        {
            float acc[2][2][4] = {};
#pragma unroll
            for (int ks = 0; ks < 4; ks++) {
                uint32_t kh[4], kl[4];
                LDSM4(kh, sb + SKH + b_base + ks * 32);
                LDSM4(kl, sb + SKL + b_base + ks * 32);
#pragma unroll
                for (int mi = 0; mi < 2; mi++) {
                    uint32_t qh[4], ql[4];
                    const uint32_t ao = (uint32_t)((warp_m * 32 + mi * 16) * 144) + a_base + ks * 32;
                    LDSM4(qh, sb + SQH + ao);
                    LDSM4(ql, sb + SQL + ao);
#pragma unroll
                    for (int hf = 0; hf < 2; hf++) {
                        hmma(acc[mi][hf], qh, kh + hf * 2);
                        hmma(acc[mi][hf], qh, kl + hf * 2);
                        hmma(acc[mi][hf], ql, kh + hf * 2);
                    }
                }
            }
#pragma unroll
            for (int mi = 0; mi < 2; mi++) {
                const int r0 = warp_m * 32 + mi * 16 + g;
#pragma unroll
                for (int hf = 0; hf < 2; hf++) {
                    const int col = warp_n * 16 + hf * 8 + cq * 2;
                    *(float2*)&lg[r0 * 66 + col]       = make_float2(acc[mi][hf][0], acc[mi][hf][1]);
                    *(float2*)&lg[(r0 + 8) * 66 + col] = make_float2(acc[mi][hf][2], acc[mi][hf][3]);
                }
            }
        }
        __syncthreads();

        if (cn <= qblk) loadK(cn);

        // ---- segmented max (branch-guarded) ----
        {
            const int r = tid >> 2, seg = tid & 3;
            const int q = r >> 4;
            const int jn = min(63, base + q);
            if (sact) {
                const unsigned selq = (q == 0) ? sel0 : (q == 1) ? sel1 : (q == 2) ? sel2 : sel3;
                float ms = -INFINITY;
                if ((selq >> c) & 1u) {
                    const int hi2 = min(seg * 16 + 15, jn);
                    for (int j = seg * 16; j <= hi2; j++) ms = fmaxf(ms, lg[r * 66 + j]);
                }
                pm[tid] = ms;
            }
            if (wact) {
                const int jw0 = base + q - 512;
                float mw = -INFINITY;
                if (jw0 <= 63) {
                    const int lo2 = max(seg * 16, jw0);
                    const int hi2 = min(seg * 16 + 15, jn);
                    for (int j = lo2; j <= hi2; j++) mw = fmaxf(mw, lg[r * 66 + j]);
                }
                pm[256 + tid] = mw;
            }
        }
        __syncthreads();
        if (tid < 128) {
            const int br = tid >> 6, r = tid & 63;
            const bool act = br ? wact : sact;
            if (act) {
                const float* p = pm + br * 256 + r * 4;
                const float cm = fmaxf(fmaxf(p[0], p[1]), fmaxf(p[2], p[3]));
                const float om = hmm[br * 64 + r];
                const float nm = fmaxf(om, cm);
                hmm[br * 64 + r] = nm;
                hrr[br * 64 + r] = (cm == -INFINITY) ? 1.f : exp2f(om - nm);
            } else {
                hrr[br * 64 + r] = 1.f;
            }
        }
        __syncthreads();

        // ---- exp (shared across branches) + partial sums + split-bf16 P store ----
        {
            const int r = tid >> 2, seg = tid & 3;
            const int q = r >> 4;
            const int jn = base + q;
            const int jw0 = base + q - 512;
            const uint32_t po = (uint32_t)((r * BST + seg * 16) * 2);
            const unsigned selq = (q == 0) ? sel0 : (q == 1) ? sel1 : (q == 2) ? sel2 : sel3;
            const bool srow = sact && ((selq >> c) & 1u);
            const bool wrow = wact && (jw0 <= 63);
            const float ms = hmm[r], mw = hmm[64 + r];

            float ev[16];
            if (sact) {
                float ss = 0.f;
                unsigned short eh[16], el[16];
                if (srow) {
#pragma unroll
                    for (int jj = 0; jj < 16; jj++) {
                        const int j = seg * 16 + jj;
                        float e = (j <= jn) ? exp2f(lg[r * 66 + j] - ms) : 0.f;
                        ev[jj] = e;
                        ss += e;
                        bsplit(e, eh[jj], el[jj]);
                    }
                } else {
#pragma unroll
                    for (int jj = 0; jj < 16; jj++) { ev[jj] = 0.f; eh[jj] = 0; el[jj] = 0; }
                }
                pm[tid] = ss;
#pragma unroll
                for (int v4 = 0; v4 < 4; v4++) {
                    *(ushort4*)(dsm + PSH + po + v4 * 8) = make_ushort4(eh[v4*4], eh[v4*4+1], eh[v4*4+2], eh[v4*4+3]);
                    *(ushort4*)(dsm + PSL + po + v4 * 8) = make_ushort4(el[v4*4], el[v4*4+1], el[v4*4+2], el[v4*4+3]);
                }
            }
            if (wact) {
                float sw = 0.f;
                unsigned short wh[16], wl[16];
                if (wrow) {
                    if (srow) {
                        // shared exponential: e_w = e_s * 2^(ms - mw)
                        const float sc = exp2f(ms - mw);
#pragma unroll
                        for (int jj = 0; jj < 16; jj++) {
                            const int j = seg * 16 + jj;
                            float ew = (j >= jw0) ? ev[jj] * sc : 0.f;   // ev already 0 past jn
                            sw += ew;
                            bsplit(ew, wh[jj], wl[jj]);
                        }
                    } else {
#pragma unroll
                        for (int jj = 0; jj < 16; jj++) {
                            const int j = seg * 16 + jj;
                            float ew = (j <= jn && j >= jw0) ? exp2f(lg[r * 66 + j] - mw) : 0.f;
                            sw += ew;
                            bsplit(ew, wh[jj], wl[jj]);
                        }
                    }
                } else {
#pragma unroll
                    for (int jj = 0; jj < 16; jj++) { wh[jj] = 0; wl[jj] = 0; }
                }
                pm[256 + tid] = sw;
#pragma unroll
                for (int v4 = 0; v4 < 4; v4++) {
                    *(ushort4*)(dsm + PWH + po + v4 * 8) = make_ushort4(wh[v4*4], wh[v4*4+1], wh[v4*4+2], wh[v4*4+3]);
                    *(ushort4*)(dsm + PWL + po + v4 * 8) = make_ushort4(wl[v4*4], wl[v4*4+1], wl[v4*4+2], wl[v4*4+3]);
                }
            }
        }
        __syncthreads();
        if (tid < 128) {
            const int br = tid >> 6, r = tid & 63;
            const bool act = br ? wact : sact;
            if (act) {
                const float* p = pm + br * 256 + r * 4;
                hll[br * 64 + r] = hll[br * 64 + r] * hrr[br * 64 + r]
                                 + (p[0] + p[1]) + (p[2] + p[3]);
            }
        }

        // ---- PV via HMMA with flash rescale (branch-guarded) ----
        if (sact) {
#pragma unroll
            for (int mi = 0; mi < 2; mi++) {
                const int rb = warp_m * 32 + mi * 16 + g;
                const float rs0 = hrr[rb], rs1 = hrr[rb + 8];
#pragma unroll
                for (int hf = 0; hf < 2; hf++) {
                    acc_s[mi][hf][0] *= rs0; acc_s[mi][hf][1] *= rs0;
                    acc_s[mi][hf][2] *= rs1; acc_s[mi][hf][3] *= rs1;
                }
            }
        }
        if (wact) {
#pragma unroll
            for (int mi = 0; mi < 2; mi++) {
                const int rb = warp_m * 32 + mi * 16 + g;
                const float rw0 = hrr[64 + rb], rw1 = hrr[64 + rb + 8];
#pragma unroll
                for (int hf = 0; hf < 2; hf++) {
                    acc_w[mi][hf][0] *= rw0; acc_w[mi][hf][1] *= rw0;
                    acc_w[mi][hf][2] *= rw1; acc_w[mi][hf][3] *= rw1;
                }
            }
        }
#pragma unroll
        for (int ks = 0; ks < 4; ks++) {
            uint32_t vh[4], vl[4];
            LDSM4(vh, sb + SVTH + b_base + ks * 32);
            LDSM4(vl, sb + SVTL + b_base + ks * 32);
#pragma unroll
            for (int mi = 0; mi < 2; mi++) {
                const uint32_t ao = (uint32_t)((warp_m * 32 + mi * 16) * 144) + a_base + ks * 32;
                if (sact) {
                    uint32_t ph[4], pl[4];
                    LDSM4(ph, sb + PSH + ao);
                    LDSM4(pl, sb + PSL + ao);
#pragma unroll
                    for (int hf = 0; hf < 2; hf++) {
                        hmma(acc_s[mi][hf], ph, vh + hf * 2);
                        hmma(acc_s[mi][hf], ph, vl + hf * 2);
                        hmma(acc_s[mi][hf], pl, vh + hf * 2);
                    }
                }
                if (wact) {
                    uint32_t ph[4], pl[4];
                    LDSM4(ph, sb + PWH + ao);
                    LDSM4(pl, sb + PWL + ao);
#pragma unroll
                    for (int hf = 0; hf < 2; hf++) {
                        hmma(acc_w[mi][hf], ph, vh + hf * 2);
                        hmma(acc_w[mi][hf], ph, vl + hf * 2);
                        hmma(acc_w[mi][hf], pl, vh + hf * 2);
                    }
                }
            }
        }
        __syncthreads();
        if (cn <= qblk) loadV(cn);
        c = cn;
    }

    // ---- gated fusion epilogue ----
#pragma unroll
    for (int mi = 0; mi < 2; mi++) {
#pragma unroll
        for (int half = 0; half < 2; half++) {
            const int r = warp_m * 32 + mi * 16 + g + half * 8;
            const int nq = n0 + (r >> 4);
            const int head = r & 15;
            const int hq = h * 16 + head;
            const float gl0 = g_kvg[nq * 352 + 256 + hq * 3 + 0];
            const float gl1 = g_kvg[nq * 352 + 256 + hq * 3 + 1];
            const float gl2 = g_kvg[nq * 352 + 256 + hq * 3 + 2];
            const float g0 = 1.f / (1.f + __expf(-gl0));
            const float g1 = 1.f / (1.f + __expf(-gl1));
            const float g2 = 1.f / (1.f + __expf(-gl2));
            const float inv_s = 1.f / hll[r];
            const float inv_w = 1.f / hll[64 + r];
#pragma unroll
            for (int hf = 0; hf < 2; hf++) {
                const int col = warp_n * 16 + hf * 8 + cq * 2;
                const int oi = nq * 2048 + h * 1024 + head * 64 + col;
                const float2 cmp = *(const float2*)&g_comp[oi];
                const float o0 = g0 * cmp.x + g1 * acc_s[mi][hf][half * 2]     * inv_s
                                            + g2 * acc_w[mi][hf][half * 2]     * inv_w;
                const float o1 = g0 * cmp.y + g1 * acc_s[mi][hf][half * 2 + 1] * inv_s
                                            + g2 * acc_w[mi][hf][half * 2 + 1] * inv_w;
                ushort2 hh, ll;
                bsplit(o0, hh.x, ll.x);
                bsplit(o1, hh.y, ll.y);
                *(ushort2*)(g_fh + oi) = hh;
                *(ushort2*)(g_fl + oi) = ll;
            }
        }
    }
}

// ---------------- launch ----------------
extern "C" void kernel_launch(void* const* d_in, const int* in_sizes, int n_in,
                              void* d_out, int out_size)
{
    const float* x   = (const float*)d_in[0];
    const float* Wq  = (const float*)d_in[2];
    const float* Wk  = (const float*)d_in[3];
    const float* Wv  = (const float*)d_in[4];
    const float* Wo  = (const float*)d_in[5];
    const float* Wg  = (const float*)d_in[6];
    const float* wck = (const float*)d_in[7];
    const float* wcv = (const float*)d_in[8];
    const float* pe  = (const float*)d_in[9];
    float* out = (float*)d_out;

    const int ntok = in_sizes[0] / 2048;     // T = 2048
    const int M = ntok / 64;

    float *q, *kvg;
    cudaGetSymbolAddress((void**)&q,   g_q);
    cudaGetSymbolAddress((void**)&kvg, g_kvg);

    __nv_bfloat16 *xh, *xl, *fh, *fl, *wqh, *wql, *woh, *wol, *wkvgh, *wkvgl;
    cudaGetSymbolAddress((void**)&xh, g_xh);     cudaGetSymbolAddress((void**)&xl, g_xl);
    cudaGetSymbolAddress((void**)&fh, g_fh);     cudaGetSymbolAddress((void**)&fl, g_fl);
    cudaGetSymbolAddress((void**)&wqh, g_wqt_h); cudaGetSymbolAddress((void**)&wql, g_wqt_l);
    cudaGetSymbolAddress((void**)&woh, g_wot_h); cudaGetSymbolAddress((void**)&wol, g_wot_l);
    cudaGetSymbolAddress((void**)&wkvgh, g_wkvgt_h);
    cudaGetSymbolAddress((void**)&wkvgl, g_wkvgt_l);

    cudaFuncSetAttribute(mma_gemm, cudaFuncAttributeMaxDynamicSharedMemorySize, SMEM_GEMM);
    cudaFuncSetAttribute(mma_gemm128, cudaFuncAttributeMaxDynamicSharedMemorySize, SMEM_GEMM8);
    cudaFuncSetAttribute(main_attn_kernel, cudaFuncAttributeMaxDynamicSharedMemorySize, ATTN_SMEM);
    cudaFuncSetAttribute(comp_attn_kernel, cudaFuncAttributeMaxDynamicSharedMemorySize, CSMEM);

    const int tot = ntok * 2048;
    dim3 tb(32, 8);

    split_fp32<<<(tot / 4 + 255) / 256, 256>>>((const float4*)x, xh, xl, tot / 4);                // 0
    transpose_split<<<dim3(64, 64), tb>>>(Wq, wqh, wql, 2048, 2048);                              // 1
    transpose_split<<<dim3(4,  64), tb>>>(Wk, wkvgh,              wkvgl,              2048, 128); // 2
    mma_gemm<<<dim3(8, ntok / 128), 512, SMEM_GEMM>>>(xh, xl, wqh, wql, q, ntok, 2048, 2048);     // 3 <- ncu
    transpose_split<<<dim3(4,  64), tb>>>(Wv, wkvgh + 128 * 2048, wkvgl + 128 * 2048, 2048, 128); // 4
    transpose_split<<<dim3(3,  64), tb>>>(Wg, wkvgh + 256 * 2048, wkvgl + 256 * 2048, 2048, 96);  // 5
    mma_gemm128<<<dim3(3, ntok / 128), 256, SMEM_GEMM8>>>(xh, xl, wkvgh, wkvgl, kvg, ntok, 352, 2048);

    kv_prep<<<dim3(ntok / 32, 2, 2), tb>>>(ntok);
    compress_kernel<<<dim3(M, 2), 64>>>(wck, wcv, pe);
    comp_attn_kernel<<<dim3(ntok / 8, 2), 512, CSMEM>>>(ntok);
    main_attn_kernel<<<dim3(ntok / 4, 2), 256, ATTN_SMEM>>>(ntok);

    transpose_split<<<dim3(64, 64), tb>>>(Wo, woh, wol, 2048, 2048);
    mma_gemm<<<dim3(8, ntok / 128), 512, SMEM_GEMM>>>(fh, fl, woh, wol, out, ntok, 2048, 2048);
}

// round 15
// speedup vs baseline: 1.3657x; 1.0641x over previous
#include <cuda_runtime.h>
#include <cuda_bf16.h>
#include <math.h>
#include <stdint.h>

// Problem constants (T=2048, H=2048, HQ=32, HKV=2, D=64, G=16, M<=32)
#define TMAX 2048
#define MMAX 32
#define QSCALE 0.180336879f   // 0.125 * log2(e)

// ---------------- scratch (no allocation allowed) ----------------
__device__ float    g_q[TMAX * 2048];      // [n, HQ*D]
__device__ float    g_kvg[TMAX * 352];     // [n, k(128) | v(128) | gate(96)]
__device__ float    g_ck[MMAX * 2 * 64];
__device__ float    g_cv[MMAX * 2 * 64];
__device__ float    g_comp[TMAX * 2048];
__device__ unsigned g_sel[TMAX * 2];

// bf16 split operands
__device__ __nv_bfloat16 g_xh[2048 * 2048], g_xl[2048 * 2048];
__device__ __nv_bfloat16 g_fh[2048 * 2048], g_fl[2048 * 2048];
__device__ __nv_bfloat16 g_wqt_h[2048 * 2048], g_wqt_l[2048 * 2048];   // Wq^T [N,K]
__device__ __nv_bfloat16 g_wot_h[2048 * 2048], g_wot_l[2048 * 2048];   // Wo^T
__device__ __nv_bfloat16 g_wkvgt_h[352 * 2048], g_wkvgt_l[352 * 2048]; // [Wk|Wv|Wg]^T
// attention K / V^T split-bf16
__device__ __nv_bfloat16 g_kbh[TMAX * 128], g_kbl[TMAX * 128];          // [n][h][64]
__device__ __nv_bfloat16 g_vth[2 * 64 * TMAX], g_vtl[2 * 64 * TMAX];    // [h][d][n]

__device__ __forceinline__ uint32_t smem_u32(const void* p) {
    uint32_t a;
    asm("{ .reg .u64 t; cvta.to.shared.u64 t, %1; cvt.u32.u64 %0, t; }" : "=r"(a) : "l"(p));
    return a;
}

// ---------------- packed f32x2 helpers ----------------
__device__ __forceinline__ unsigned long long pk2(float x, float y) {
    unsigned long long r;
    asm("mov.b64 %0, {%1,%2};" : "=l"(r) : "f"(x), "f"(y));
    return r;
}
__device__ __forceinline__ unsigned long long pk2f2(float2 v) { return pk2(v.x, v.y); }
__device__ __forceinline__ void upk2(unsigned long long r, float& x, float& y) {
    asm("mov.b64 {%0,%1}, %2;" : "=f"(x), "=f"(y) : "l"(r));
}
__device__ __forceinline__ unsigned long long fma2(unsigned long long a,
                                                   unsigned long long b,
                                                   unsigned long long c) {
    unsigned long long d;
    asm("fma.rn.f32x2 %0, %1, %2, %3;" : "=l"(d) : "l"(a), "l"(b), "l"(c));
    return d;
}

// ---------------- mma helpers ----------------
#define LDSM4(r, addr) \
    asm volatile("ldmatrix.sync.aligned.m8n8.x4.shared.b16 {%0,%1,%2,%3}, [%4];" \
                 : "=r"((r)[0]), "=r"((r)[1]), "=r"((r)[2]), "=r"((r)[3]) : "r"(addr))

__device__ __forceinline__ void hmma(float* c, const uint32_t* a, const uint32_t* b) {
    asm volatile("mma.sync.aligned.m16n8k16.row.col.f32.bf16.bf16.f32 "
                 "{%0,%1,%2,%3},{%4,%5,%6,%7},{%8,%9},{%0,%1,%2,%3};"
                 : "+f"(c[0]), "+f"(c[1]), "+f"(c[2]), "+f"(c[3])
                 : "r"(a[0]), "r"(a[1]), "r"(a[2]), "r"(a[3]), "r"(b[0]), "r"(b[1]));
}

__device__ __forceinline__ void bsplit(float v, unsigned short& hi, unsigned short& lo) {
    __nv_bfloat16 h = __float2bfloat16(v);
    __nv_bfloat16 l = __float2bfloat16(v - __bfloat162float(h));
    hi = *(unsigned short*)&h; lo = *(unsigned short*)&l;
}

// ================= prep kernels =================
__global__ void split_fp32(const float4* __restrict__ A,
                           __nv_bfloat16* __restrict__ Ah,
                           __nv_bfloat16* __restrict__ Al, int total4)
{
    int i = blockIdx.x * 256 + threadIdx.x;
    if (i < total4) {
        float4 v = A[i];
        ushort4 hh, ll;
        bsplit(v.x, hh.x, ll.x); bsplit(v.y, hh.y, ll.y);
        bsplit(v.z, hh.z, ll.z); bsplit(v.w, hh.w, ll.w);
        *(ushort4*)(Ah + 4 * (size_t)i) = hh;
        *(ushort4*)(Al + 4 * (size_t)i) = ll;
    }
}

__global__ void transpose_split(const float* __restrict__ W,
                                __nv_bfloat16* __restrict__ Th,
                                __nv_bfloat16* __restrict__ Tl, int K, int N)
{
    __shared__ float t[32][33];
    const int k0 = blockIdx.y * 32, n0 = blockIdx.x * 32;
    const int tx = threadIdx.x, ty = threadIdx.y;  // 32 x 8
    for (int i = ty; i < 32; i += 8) {
        int k = k0 + i, n = n0 + tx;
        t[i][tx] = (n < N && k < K) ? W[(size_t)k * N + n] : 0.f;
    }
    __syncthreads();
    for (int i = ty; i < 32; i += 8) {
        int n = n0 + i, k = k0 + tx;
        if (n < N && k < K) {
            unsigned short hi, lo;
            bsplit(t[tx][i], hi, lo);
            *(unsigned short*)(Th + (size_t)n * K + k) = hi;
            *(unsigned short*)(Tl + (size_t)n * K + k) = lo;
        }
    }
}

// K split + V transpose-split. grid (n/32, 2, 2), block (32,8)
__global__ void kv_prep(int ntok)
{
    __shared__ float t[32][33];
    const int n0 = blockIdx.x * 32, h = blockIdx.y, dh = blockIdx.z * 32;
    const int tx = threadIdx.x, ty = threadIdx.y;
    for (int i = ty; i < 32; i += 8) {
        const int n = n0 + i, d = dh + tx;
        float kv = g_kvg[n * 352 + h * 64 + d];
        unsigned short hi, lo;
        bsplit(kv, hi, lo);
        *(unsigned short*)(g_kbh + n * 128 + h * 64 + d) = hi;
        *(unsigned short*)(g_kbl + n * 128 + h * 64 + d) = lo;
        t[i][tx] = g_kvg[n * 352 + h * 64 + 128 + d];
    }
    __syncthreads();
    for (int i = ty; i < 32; i += 8) {
        const int d = dh + i, n = n0 + tx;
        unsigned short hi, lo;
        bsplit(t[tx][i], hi, lo);
        *(unsigned short*)(g_vth + (h * 64 + d) * TMAX + n) = hi;
        *(unsigned short*)(g_vtl + (h * 64 + d) * TMAX + n) = lo;
    }
}

// ================= split-bf16 GEMM on mma.sync, 128x128 tile, XOR-swizzled =================
// 64B rows (no padding), swizzle c16 ^= (row>>1)&3 -> ldmatrix conflict-free.
// Stage = 4 mats x 8KB = 32KB; 2 stages = 64KB -> 2 CTAs/SM (regs capped at 128).
#define SW_MAT 8192
#define SW_STAGE 32768
#define SMEM_SW (2 * SW_STAGE)

__global__ void __launch_bounds__(256, 2) mma_gemm_sw(
    const __nv_bfloat16* __restrict__ Ah, const __nv_bfloat16* __restrict__ Al,
    const __nv_bfloat16* __restrict__ Bth, const __nv_bfloat16* __restrict__ Btl,
    float* __restrict__ C, int M, int N, int K)
{
    extern __shared__ char smem[];
    const uint32_t sb = smem_u32(smem);
    const int tid = threadIdx.x;
    const int lane = tid & 31, wid = tid >> 5;
    const int warp_m = wid & 1, warp_n = wid >> 1;   // 2 x 4 warps
    const int row0 = blockIdx.y * 128, col0 = blockIdx.x * 128;
    const int nchunk = K >> 5;

    float acc[4][4][4];
#pragma unroll
    for (int a = 0; a < 4; a++)
#pragma unroll
        for (int b = 0; b < 4; b++)
#pragma unroll
            for (int c = 0; c < 4; c++) acc[a][b][c] = 0.f;

    const int mt = lane >> 3, rin = lane & 7;
    const int r3 = (rin >> 1) & 3;                   // row bases are multiples of 8
    // A: row = warp_m*64 + mi*16 + (mt&1)*8 + rin ; base granule c0 = mt>>1
    const uint32_t a_row = (uint32_t)((warp_m * 64 + (mt & 1) * 8 + rin) * 64);
    const int a_c0 = mt >> 1;
    const uint32_t a_swk0 = (uint32_t)(((0 + a_c0) ^ r3) * 16);
    const uint32_t a_swk1 = (uint32_t)(((2 + a_c0) ^ r3) * 16);
    // B: row = warp_n*32 + b2*16 + ((mt>=2)?8:0) + rin ; base granule = mt&1
    const uint32_t b_row = (uint32_t)((warp_n * 32 + ((mt >= 2) ? 8 : 0) + rin) * 64);
    const int b_c0 = mt & 1;
    const uint32_t b_swk0 = (uint32_t)(((0 + b_c0) ^ r3) * 16);
    const uint32_t b_swk1 = (uint32_t)(((2 + b_c0) ^ r3) * 16);

    auto load_chunk = [&](int c) {
        const int k0 = c * 32;
        const uint32_t st = sb + (uint32_t)(c & 1) * SW_STAGE;
        // 2048 16B vectors: Ah[0,512) Al[512,1024) Bh[1024,1536) Bl[1536,2048)
#pragma unroll
        for (int i = 0; i < 8; i++) {
            int v = tid + i * 256;
            int mat = v >> 9, idx = v & 511;
            int row = idx >> 2, c16 = idx & 3;
            uint32_t dst = st + mat * SW_MAT + row * 64
                         + (uint32_t)((c16 ^ ((row >> 1) & 3)) * 16);
            const __nv_bfloat16* srcp;
            int sz = 16;
            if (mat < 2) {
                srcp = (mat ? Al : Ah) + (size_t)(row0 + row) * K + k0 + c16 * 8;
            } else {
                int n = col0 + row;
                int nn = (n < N) ? n : 0;
                if (n >= N) sz = 0;
                srcp = (mat == 3 ? Btl : Bth) + (size_t)nn * K + k0 + c16 * 8;
            }
            asm volatile("cp.async.cg.shared.global [%0], [%1], 16, %2;"
                         :: "r"(dst), "l"(srcp), "r"(sz));
        }
        asm volatile("cp.async.commit_group;" ::: "memory");
    };

    load_chunk(0);

    for (int c = 0; c < nchunk; c++) {
        if (c + 1 < nchunk) {
            load_chunk(c + 1);
            asm volatile("cp.async.wait_group 1;" ::: "memory");
        } else {
            asm volatile("cp.async.wait_group 0;" ::: "memory");
        }
        __syncthreads();

        const uint32_t st = sb + (uint32_t)(c & 1) * SW_STAGE;
#pragma unroll
        for (int ks = 0; ks < 2; ks++) {
            const uint32_t a_sw = ks ? a_swk1 : a_swk0;
            const uint32_t b_sw = ks ? b_swk1 : b_swk0;
            uint32_t ah[4][4], al[4][4];
#pragma unroll
            for (int mi = 0; mi < 4; mi++) {
                uint32_t addr = st + a_row + mi * (16 * 64) + a_sw;
                LDSM4(ah[mi], addr);
                LDSM4(al[mi], addr + SW_MAT);
            }
#pragma unroll
            for (int b2 = 0; b2 < 2; b2++) {
                uint32_t bh[4], bl[4];
                uint32_t baddr = st + 2 * SW_MAT + b_row + b2 * (16 * 64) + b_sw;
                LDSM4(bh, baddr);
                LDSM4(bl, baddr + SW_MAT);
#pragma unroll
                for (int p = 0; p < 3; p++) {
#pragma unroll
                    for (int mi = 0; mi < 4; mi++) {
#pragma unroll
                        for (int hf = 0; hf < 2; hf++) {
                            const int nt = b2 * 2 + hf;
                            const uint32_t* A_ = (p == 2) ? al[mi] : ah[mi];
                            const uint32_t* B_ = (p == 1) ? bl : bh;
                            hmma(acc[mi][nt], A_, B_ + hf * 2);
                        }
                    }
                }
            }
        }
        __syncthreads();
    }

    const int g = lane >> 2, c2 = lane & 3;
#pragma unroll
    for (int mi = 0; mi < 4; mi++) {
        const int r = row0 + warp_m * 64 + mi * 16 + g;
#pragma unroll
        for (int nt = 0; nt < 4; nt++) {
            const int col = col0 + warp_n * 32 + nt * 8 + c2 * 2;
            if (col < N) {
                *(float2*)(C + (size_t)r * N + col)       = make_float2(acc[mi][nt][0], acc[mi][nt][1]);
                *(float2*)(C + (size_t)(r + 8) * N + col) = make_float2(acc[mi][nt][2], acc[mi][nt][3]);
            }
        }
    }
}

// ---------------- compressed tokens ----------------
__global__ void compress_kernel(const float* __restrict__ wck,
                                const float* __restrict__ wcv,
                                const float* __restrict__ pe)
{
    const int m = blockIdx.x, h = blockIdx.y, d = threadIdx.x;  // 64 threads
    float a = 0.f, b = 0.f;
    for (int t = 0; t < 64; t++) {
        const float wk = wck[h * 64 + t];
        const float wv = wcv[h * 64 + t];
        const int row = m * 64 + t;
        a = fmaf(g_kvg[row * 352 + h * 64 + d] + pe[(h * 64 + t) * 64 + d], wk, a);
        b = fmaf(g_kvg[row * 352 + 128 + h * 64 + d], wv, b);
    }
    g_ck[(m * 2 + h) * 64 + d] = a;
    g_cv[(m * 2 + h) * 64 + d] = b;
}

// ---------------- compressed attention + top-k, 8 tokens per CTA, dynamic smem ----------------
#define CSMEM (66816)
__global__ void __launch_bounds__(512) comp_attn_kernel(int ntok)
{
    extern __shared__ float csm[];
    float*  sq   = csm;                        // [8][1024] prescaled Q (log2 domain)
    float2* ckp  = (float2*)(csm + 8192);      // [32][33] d-pair ck
    float*  scv  = csm + 8192 + 2112;          // [32][64]
    float*  lg   = scv + 2048;                 // [8][512]
    float*  ssum = lg + 4096;                  // [8][32]

    const int n0 = blockIdx.x * 8, h = blockIdx.y;
    const int tid = threadIdx.x;
    const int tq = tid >> 6, ltid = tid & 63;
    const int M = ntok >> 6;

    for (int i = tid; i < 8192; i += 512) {
        int q = i >> 10;
        sq[i] = g_q[(n0 + q) * 2048 + h * 1024 + (i & 1023)] * QSCALE;
    }
    for (int i = tid; i < M * 32; i += 512) {
        int m = i >> 5, d2 = i & 31;
        ckp[d2 * 33 + m] = *(const float2*)&g_ck[(m * 2 + h) * 64 + 2 * d2];
    }
    for (int i = tid; i < M * 64; i += 512)
        scv[i] = g_cv[((i >> 6) * 2 + h) * 64 + (i & 63)];
    __syncthreads();

    const int n = n0 + tq;
    const int mvis = (n >= 63) ? (((n - 63) >> 6) + 1) : 0;

#pragma unroll
    for (int i = 0; i < 8; i++) {
        int e = ltid + i * 64;
        int g = e >> 5, m = e & 31;
        unsigned long long acc = 0ull;
#pragma unroll
        for (int d2 = 0; d2 < 32; d2++) {
            unsigned long long qp = pk2f2(*(const float2*)&sq[tq * 1024 + g * 64 + 2 * d2]);
            acc = fma2(qp, pk2f2(ckp[d2 * 33 + m]), acc);
        }
        float x, y; upk2(acc, x, y);
        lg[tq * 512 + g * 32 + m] = x + y;
    }
    __syncthreads();

    if (ltid < 16) {
        float* row = lg + tq * 512 + ltid * 32;
        if (mvis == 0) {
            for (int m = 0; m < M; m++) row[m] = 0.f;
        } else {
            float mx = -INFINITY;
            for (int m = 0; m < mvis; m++) mx = fmaxf(mx, row[m]);
            float s = 0.f;
            for (int m = 0; m < mvis; m++) {
                float p = exp2f(row[m] - mx);
                row[m] = p; s += p;
            }
            const float inv = 1.f / s;
            for (int m = 0; m < mvis; m++) row[m] *= inv;
            for (int m = mvis; m < M; m++) row[m] = 0.f;
        }
    }
    __syncthreads();

#pragma unroll
    for (int i = 0; i < 8; i++) {
        int e2 = ltid + i * 64;
        int g = e2 >> 5, d2 = e2 & 31;
        unsigned long long acc = 0ull;
        for (int m = 0; m < mvis; m++) {
            float p = lg[tq * 512 + g * 32 + m];
            acc = fma2(pk2(p, p), pk2f2(*(const float2*)&scv[m * 64 + 2 * d2]), acc);
        }
        float x, y; upk2(acc, x, y);
        *(float2*)&g_comp[n * 2048 + h * 1024 + g * 64 + 2 * d2] = make_float2(x, y);
    }

    if (ltid < 32) {
        float s = 0.f;
        if (ltid < M)
            for (int g = 0; g < 16; g++) s += lg[tq * 512 + g * 32 + ltid];
        ssum[tq * 32 + ltid] = s;
    }
    __syncthreads();

    if (ltid == 0) {
        const int qblk = n >> 6;
        unsigned sel = 0;
        if (qblk + 1 <= 16) {
            sel = (1u << (qblk + 1)) - 1u;
        } else {
            float sc[32];
            for (int m = 0; m < 32; m++) {
                if (m > qblk)                                  sc[m] = -INFINITY;
                else if (m == 0 || m == qblk || m == qblk - 1) sc[m] = INFINITY;
                else                                           sc[m] = ssum[tq * 32 + m];
            }
            for (int t = 0; t < 16; t++) {
                int best = 0; float bv = -INFINITY;
                for (int m = 0; m < 32; m++) {
                    if ((sel >> m) & 1u) continue;
                    if (sc[m] > bv) { bv = sc[m]; best = m; }
                }
                sel |= 1u << best;
            }
        }
        g_sel[n * 2 + h] = sel;
    }
}

// ---------------- main attention on tensor cores (K-prefetch pipelined, shared exp) ----------------
#define BST 72          // bf16 smem row stride (elements) = 144 bytes
#define SQH 0
#define SQL 9216
#define SKH 18432
#define SKL 27648
#define SVTH 36864
#define SVTL 46080
#define PSH 55296
#define PSL 64512
#define PWH 73728
#define PWL 82944
#define LG_OFF 92160    // float [64][66]
#define PM_OFF 109056   // float [512]
#define HMM_OFF 111104  // float [2][64]
#define HLL_OFF 111616
#define HRR_OFF 112128
#define ATTN_SMEM 112640

__global__ void __launch_bounds__(256, 2) main_attn_kernel(int ntok)
{
    extern __shared__ char dsm[];
    const uint32_t sb = smem_u32(dsm);
    float* lg  = (float*)(dsm + LG_OFF);
    float* pm  = (float*)(dsm + PM_OFF);
    float* hmm = (float*)(dsm + HMM_OFF);
    float* hll = (float*)(dsm + HLL_OFF);
    float* hrr = (float*)(dsm + HRR_OFF);

    // reversed CTA order: heaviest first for tail packing
    const int n0 = (gridDim.x - 1 - blockIdx.x) * 4, h = blockIdx.y;
    const int tid = threadIdx.x;
    const int lane = tid & 31, wid = tid >> 5;
    const int warp_m = wid & 1, warp_n = wid >> 1;
    const int g = lane >> 2, cq = lane & 3;

    const unsigned sel0 = g_sel[n0 * 2 + h],       sel1 = g_sel[(n0 + 1) * 2 + h],
                   sel2 = g_sel[(n0 + 2) * 2 + h], sel3 = g_sel[(n0 + 3) * 2 + h];
    const unsigned selU = sel0 | sel1 | sel2 | sel3;
    const int qblk = n0 >> 6;

    auto active = [&](int c) -> bool {
        return ((selU >> c) & 1u) || ((n0 - c * 64 - 512) <= 63);
    };

    auto loadK = [&](int c) {
#pragma unroll
        for (int i2 = 0; i2 < 4; i2++) {
            int i = tid + i2 * 256;
            int mat = i >> 9, idx = i & 511;
            int row = idx >> 3, c16 = idx & 7;
            const __nv_bfloat16* src = (mat == 0 ? g_kbh : g_kbl)
                                     + (size_t)(c * 64 + row) * 128 + h * 64 + c16 * 8;
            uint32_t dst = sb + SKH + (uint32_t)(mat * 9216 + row * 144 + c16 * 16);
            asm volatile("cp.async.cg.shared.global [%0], [%1], 16;" :: "r"(dst), "l"(src));
        }
        asm volatile("cp.async.commit_group;" ::: "memory");
    };
    auto loadV = [&](int c) {
#pragma unroll
        for (int i2 = 0; i2 < 4; i2++) {
            int i = tid + i2 * 256;
            int mat = i >> 9, idx = i & 511;
            int row = idx >> 3, c16 = idx & 7;
            const __nv_bfloat16* src = (mat == 0 ? g_vth : g_vtl)
                                     + (size_t)(h * 64 + row) * TMAX + c * 64 + c16 * 8;
            uint32_t dst = sb + SVTH + (uint32_t)(mat * 9216 + row * 144 + c16 * 16);
            asm volatile("cp.async.cg.shared.global [%0], [%1], 16;" :: "r"(dst), "l"(src));
        }
        asm volatile("cp.async.commit_group;" ::: "memory");
    };

    int c0 = 0;
    while (c0 <= qblk && !active(c0)) c0++;
    loadK(c0);
    loadV(c0);

    for (int i = tid; i < 4096; i += 256) {
        int r = i >> 6, d = i & 63;
        float v = g_q[(n0 + (r >> 4)) * 2048 + h * 1024 + (r & 15) * 64 + d] * QSCALE;
        unsigned short hi, lo;
        bsplit(v, hi, lo);
        *(unsigned short*)(dsm + SQH + (r * BST + d) * 2) = hi;
        *(unsigned short*)(dsm + SQL + (r * BST + d) * 2) = lo;
    }
    if (tid < 128) { hmm[tid] = -INFINITY; hll[tid] = 0.f; }

    const int mt = lane >> 3, rin = lane & 7;
    const uint32_t a_base = (uint32_t)(((mt & 1) * 8 + rin) * 144 + ((mt >> 1) * 8) * 2);
    const uint32_t b_base = (uint32_t)((warp_n * 16 + ((mt >= 2) ? 8 : 0) + rin) * 144 + ((mt & 1) * 8) * 2);

    float acc_s[2][2][4] = {}, acc_w[2][2][4] = {};

    for (int c = c0; c <= qblk;) {
        int cn = c + 1;
        while (cn <= qblk && !active(cn)) cn++;

        const int base = n0 - c * 64;
        const bool wact = (base - 512) <= 63;
        const bool sact = (selU >> c) & 1u;

        asm volatile("cp.async.wait_group 0;" ::: "memory");
        __syncthreads();

        // ---- S = Q K^T via HMMA (3-product) ----
        {
            float acc[2][2][4] = {};
#pragma unroll
            for (int ks = 0; ks < 4; ks++) {
                uint32_t kh[4], kl[4];
                LDSM4(kh, sb + SKH + b_base + ks * 32);
                LDSM4(kl, sb + SKL + b_base + ks * 32);
#pragma unroll
                for (int mi = 0; mi < 2; mi++) {
                    uint32_t qh[4], ql[4];
                    const uint32_t ao = (uint32_t)((warp_m * 32 + mi * 16) * 144) + a_base + ks * 32;
                    LDSM4(qh, sb + SQH + ao);
                    LDSM4(ql, sb + SQL + ao);
#pragma unroll
                    for (int hf = 0; hf < 2; hf++) {
                        hmma(acc[mi][hf], qh, kh + hf * 2);
                        hmma(acc[mi][hf], qh, kl + hf * 2);
                        hmma(acc[mi][hf], ql, kh + hf * 2);
                    }
                }
            }
#pragma unroll
            for (int mi = 0; mi < 2; mi++) {
                const int r0 = warp_m * 32 + mi * 16 + g;
#pragma unroll
                for (int hf = 0; hf < 2; hf++) {
                    const int col = warp_n * 16 + hf * 8 + cq * 2;
                    *(float2*)&lg[r0 * 66 + col]       = make_float2(acc[mi][hf][0], acc[mi][hf][1]);
                    *(float2*)&lg[(r0 + 8) * 66 + col] = make_float2(acc[mi][hf][2], acc[mi][hf][3]);
                }
            }
        }
        __syncthreads();

        if (cn <= qblk) loadK(cn);

        // ---- segmented max (branch-guarded) ----
        {
            const int r = tid >> 2, seg = tid & 3;
            const int q = r >> 4;
            const int jn = min(63, base + q);
            if (sact) {
                const unsigned selq = (q == 0) ? sel0 : (q == 1) ? sel1 : (q == 2) ? sel2 : sel3;
                float ms = -INFINITY;
                if ((selq >> c) & 1u) {
                    const int hi2 = min(seg * 16 + 15, jn);
                    for (int j = seg * 16; j <= hi2; j++) ms = fmaxf(ms, lg[r * 66 + j]);
                }
                pm[tid] = ms;
            }
            if (wact) {
                const int jw0 = base + q - 512;
                float mw = -INFINITY;
                if (jw0 <= 63) {
                    const int lo2 = max(seg * 16, jw0);
                    const int hi2 = min(seg * 16 + 15, jn);
                    for (int j = lo2; j <= hi2; j++) mw = fmaxf(mw, lg[r * 66 + j]);
                }
                pm[256 + tid] = mw;
            }
        }
        __syncthreads();
        if (tid < 128) {
            const int br = tid >> 6, r = tid & 63;
            const bool act = br ? wact : sact;
            if (act) {
                const float* p = pm + br * 256 + r * 4;
                const float cm = fmaxf(fmaxf(p[0], p[1]), fmaxf(p[2], p[3]));
                const float om = hmm[br * 64 + r];
                const float nm = fmaxf(om, cm);
                hmm[br * 64 + r] = nm;
                hrr[br * 64 + r] = (cm == -INFINITY) ? 1.f : exp2f(om - nm);
            } else {
                hrr[br * 64 + r] = 1.f;
            }
        }
        __syncthreads();

        // ---- exp (shared across branches) + partial sums + split-bf16 P store ----
        {
            const int r = tid >> 2, seg = tid & 3;
            const int q = r >> 4;
            const int jn = base + q;
            const int jw0 = base + q - 512;
            const uint32_t po = (uint32_t)((r * BST + seg * 16) * 2);
            const unsigned selq = (q == 0) ? sel0 : (q == 1) ? sel1 : (q == 2) ? sel2 : sel3;
            const bool srow = sact && ((selq >> c) & 1u);
            const bool wrow = wact && (jw0 <= 63);
            const float ms = hmm[r], mw = hmm[64 + r];

            float ev[16];
            if (sact) {
                float ss = 0.f;
                unsigned short eh[16], el[16];
                if (srow) {
#pragma unroll
                    for (int jj = 0; jj < 16; jj++) {
                        const int j = seg * 16 + jj;
                        float e = (j <= jn) ? exp2f(lg[r * 66 + j] - ms) : 0.f;
                        ev[jj] = e;
                        ss += e;
                        bsplit(e, eh[jj], el[jj]);
                    }
                } else {
#pragma unroll
                    for (int jj = 0; jj < 16; jj++) { ev[jj] = 0.f; eh[jj] = 0; el[jj] = 0; }
                }
                pm[tid] = ss;
#pragma unroll
                for (int v4 = 0; v4 < 4; v4++) {
                    *(ushort4*)(dsm + PSH + po + v4 * 8) = make_ushort4(eh[v4*4], eh[v4*4+1], eh[v4*4+2], eh[v4*4+3]);
                    *(ushort4*)(dsm + PSL + po + v4 * 8) = make_ushort4(el[v4*4], el[v4*4+1], el[v4*4+2], el[v4*4+3]);
                }
            }
            if (wact) {
                float sw = 0.f;
                unsigned short wh[16], wl[16];
                if (wrow) {
                    if (srow) {
                        const float sc = exp2f(ms - mw);
#pragma unroll
                        for (int jj = 0; jj < 16; jj++) {
                            const int j = seg * 16 + jj;
                            float ew = (j >= jw0) ? ev[jj] * sc : 0.f;
                            sw += ew;
                            bsplit(ew, wh[jj], wl[jj]);
                        }
                    } else {
#pragma unroll
                        for (int jj = 0; jj < 16; jj++) {
                            const int j = seg * 16 + jj;
                            float ew = (j <= jn && j >= jw0) ? exp2f(lg[r * 66 + j] - mw) : 0.f;
                            sw += ew;
                            bsplit(ew, wh[jj], wl[jj]);
                        }
                    }
                } else {
#pragma unroll
                    for (int jj = 0; jj < 16; jj++) { wh[jj] = 0; wl[jj] = 0; }
                }
                pm[256 + tid] = sw;
#pragma unroll
                for (int v4 = 0; v4 < 4; v4++) {
                    *(ushort4*)(dsm + PWH + po + v4 * 8) = make_ushort4(wh[v4*4], wh[v4*4+1], wh[v4*4+2], wh[v4*4+3]);
                    *(ushort4*)(dsm + PWL + po + v4 * 8) = make_ushort4(wl[v4*4], wl[v4*4+1], wl[v4*4+2], wl[v4*4+3]);
                }
            }
        }
        __syncthreads();
        if (tid < 128) {
            const int br = tid >> 6, r = tid & 63;
            const bool act = br ? wact : sact;
            if (act) {
                const float* p = pm + br * 256 + r * 4;
                hll[br * 64 + r] = hll[br * 64 + r] * hrr[br * 64 + r]
                                 + (p[0] + p[1]) + (p[2] + p[3]);
            }
        }

        // ---- PV via HMMA with flash rescale (branch-guarded) ----
        if (sact) {
#pragma unroll
            for (int mi = 0; mi < 2; mi++) {
                const int rb = warp_m * 32 + mi * 16 + g;
                const float rs0 = hrr[rb], rs1 = hrr[rb + 8];
#pragma unroll
                for (int hf = 0; hf < 2; hf++) {
                    acc_s[mi][hf][0] *= rs0; acc_s[mi][hf][1] *= rs0;
                    acc_s[mi][hf][2] *= rs1; acc_s[mi][hf][3] *= rs1;
                }
            }
        }
        if (wact) {
#pragma unroll
            for (int mi = 0; mi < 2; mi++) {
                const int rb = warp_m * 32 + mi * 16 + g;
                const float rw0 = hrr[64 + rb], rw1 = hrr[64 + rb + 8];
#pragma unroll
                for (int hf = 0; hf < 2; hf++) {
                    acc_w[mi][hf][0] *= rw0; acc_w[mi][hf][1] *= rw0;
                    acc_w[mi][hf][2] *= rw1; acc_w[mi][hf][3] *= rw1;
                }
            }
        }
#pragma unroll
        for (int ks = 0; ks < 4; ks++) {
            uint32_t vh[4], vl[4];
            LDSM4(vh, sb + SVTH + b_base + ks * 32);
            LDSM4(vl, sb + SVTL + b_base + ks * 32);
#pragma unroll
            for (int mi = 0; mi < 2; mi++) {
                const uint32_t ao = (uint32_t)((warp_m * 32 + mi * 16) * 144) + a_base + ks * 32;
                if (sact) {
                    uint32_t ph[4], pl[4];
                    LDSM4(ph, sb + PSH + ao);
                    LDSM4(pl, sb + PSL + ao);
#pragma unroll
                    for (int hf = 0; hf < 2; hf++) {
                        hmma(acc_s[mi][hf], ph, vh + hf * 2);
                        hmma(acc_s[mi][hf], ph, vl + hf * 2);
                        hmma(acc_s[mi][hf], pl, vh + hf * 2);
                    }
                }
                if (wact) {
                    uint32_t ph[4], pl[4];
                    LDSM4(ph, sb + PWH + ao);
                    LDSM4(pl, sb + PWL + ao);
#pragma unroll
                    for (int hf = 0; hf < 2; hf++) {
                        hmma(acc_w[mi][hf], ph, vh + hf * 2);
                        hmma(acc_w[mi][hf], ph, vl + hf * 2);
                        hmma(acc_w[mi][hf], pl, vh + hf * 2);
                    }
                }
            }
        }
        __syncthreads();
        if (cn <= qblk) loadV(cn);
        c = cn;
    }

    // ---- gated fusion epilogue ----
#pragma unroll
    for (int mi = 0; mi < 2; mi++) {
#pragma unroll
        for (int half = 0; half < 2; half++) {
            const int r = warp_m * 32 + mi * 16 + g + half * 8;
            const int nq = n0 + (r >> 4);
            const int head = r & 15;
            const int hq = h * 16 + head;
            const float gl0 = g_kvg[nq * 352 + 256 + hq * 3 + 0];
            const float gl1 = g_kvg[nq * 352 + 256 + hq * 3 + 1];
            const float gl2 = g_kvg[nq * 352 + 256 + hq * 3 + 2];
            const float g0 = 1.f / (1.f + __expf(-gl0));
            const float g1 = 1.f / (1.f + __expf(-gl1));
            const float g2 = 1.f / (1.f + __expf(-gl2));
            const float inv_s = 1.f / hll[r];
            const float inv_w = 1.f / hll[64 + r];
#pragma unroll
            for (int hf = 0; hf < 2; hf++) {
                const int col = warp_n * 16 + hf * 8 + cq * 2;
                const int oi = nq * 2048 + h * 1024 + head * 64 + col;
                const float2 cmp = *(const float2*)&g_comp[oi];
                const float o0 = g0 * cmp.x + g1 * acc_s[mi][hf][half * 2]     * inv_s
                                            + g2 * acc_w[mi][hf][half * 2]     * inv_w;
                const float o1 = g0 * cmp.y + g1 * acc_s[mi][hf][half * 2 + 1] * inv_s
                                            + g2 * acc_w[mi][hf][half * 2 + 1] * inv_w;
                ushort2 hh, ll;
                bsplit(o0, hh.x, ll.x);
                bsplit(o1, hh.y, ll.y);
                *(ushort2*)(g_fh + oi) = hh;
                *(ushort2*)(g_fl + oi) = ll;
            }
        }
    }
}

// ---------------- launch ----------------
extern "C" void kernel_launch(void* const* d_in, const int* in_sizes, int n_in,
                              void* d_out, int out_size)
{
    const float* x   = (const float*)d_in[0];
    const float* Wq  = (const float*)d_in[2];
    const float* Wk  = (const float*)d_in[3];
    const float* Wv  = (const float*)d_in[4];
    const float* Wo  = (const float*)d_in[5];
    const float* Wg  = (const float*)d_in[6];
    const float* wck = (const float*)d_in[7];
    const float* wcv = (const float*)d_in[8];
    const float* pe  = (const float*)d_in[9];
    float* out = (float*)d_out;

    const int ntok = in_sizes[0] / 2048;     // T = 2048
    const int M = ntok / 64;

    float *q, *kvg;
    cudaGetSymbolAddress((void**)&q,   g_q);
    cudaGetSymbolAddress((void**)&kvg, g_kvg);

    __nv_bfloat16 *xh, *xl, *fh, *fl, *wqh, *wql, *woh, *wol, *wkvgh, *wkvgl;
    cudaGetSymbolAddress((void**)&xh, g_xh);     cudaGetSymbolAddress((void**)&xl, g_xl);
    cudaGetSymbolAddress((void**)&fh, g_fh);     cudaGetSymbolAddress((void**)&fl, g_fl);
    cudaGetSymbolAddress((void**)&wqh, g_wqt_h); cudaGetSymbolAddress((void**)&wql, g_wqt_l);
    cudaGetSymbolAddress((void**)&woh, g_wot_h); cudaGetSymbolAddress((void**)&wol, g_wot_l);
    cudaGetSymbolAddress((void**)&wkvgh, g_wkvgt_h);
    cudaGetSymbolAddress((void**)&wkvgl, g_wkvgt_l);

    cudaFuncSetAttribute(mma_gemm_sw, cudaFuncAttributeMaxDynamicSharedMemorySize, SMEM_SW);
    cudaFuncSetAttribute(main_attn_kernel, cudaFuncAttributeMaxDynamicSharedMemorySize, ATTN_SMEM);
    cudaFuncSetAttribute(comp_attn_kernel, cudaFuncAttributeMaxDynamicSharedMemorySize, CSMEM);

    const int tot = ntok * 2048;
    dim3 tb(32, 8);

    split_fp32<<<(tot / 4 + 255) / 256, 256>>>((const float4*)x, xh, xl, tot / 4);                // 0
    transpose_split<<<dim3(64, 64), tb>>>(Wq, wqh, wql, 2048, 2048);                              // 1
    transpose_split<<<dim3(4,  64), tb>>>(Wk, wkvgh,              wkvgl,              2048, 128); // 2
    mma_gemm_sw<<<dim3(16, ntok / 128), 256, SMEM_SW>>>(xh, xl, wqh, wql, q, ntok, 2048, 2048);   // 3 <- ncu
    transpose_split<<<dim3(4,  64), tb>>>(Wv, wkvgh + 128 * 2048, wkvgl + 128 * 2048, 2048, 128); // 4
    transpose_split<<<dim3(3,  64), tb>>>(Wg, wkvgh + 256 * 2048, wkvgl + 256 * 2048, 2048, 96);  // 5
    mma_gemm_sw<<<dim3(3, ntok / 128), 256, SMEM_SW>>>(xh, xl, wkvgh, wkvgl, kvg, ntok, 352, 2048);

    kv_prep<<<dim3(ntok / 32, 2, 2), tb>>>(ntok);
    compress_kernel<<<dim3(M, 2), 64>>>(wck, wcv, pe);
    comp_attn_kernel<<<dim3(ntok / 8, 2), 512, CSMEM>>>(ntok);
    main_attn_kernel<<<dim3(ntok / 4, 2), 256, ATTN_SMEM>>>(ntok);

    transpose_split<<<dim3(64, 64), tb>>>(Wo, woh, wol, 2048, 2048);
    mma_gemm_sw<<<dim3(16, ntok / 128), 256, SMEM_SW>>>(fh, fl, woh, wol, out, ntok, 2048, 2048);
}

// round 16
// speedup vs baseline: 1.3762x; 1.0077x over previous
#include <cuda_runtime.h>
#include <cuda_bf16.h>
#include <math.h>
#include <stdint.h>

// Problem constants (T=2048, H=2048, HQ=32, HKV=2, D=64, G=16, M<=32)
#define TMAX 2048
#define MMAX 32
#define QSCALE 0.180336879f   // 0.125 * log2(e)

// ---------------- scratch (no allocation allowed) ----------------
__device__ float    g_q[TMAX * 2048];      // [n, HQ*D]
__device__ float    g_kvg[TMAX * 352];     // [n, k(128) | v(128) | gate(96)]
__device__ float    g_ck[MMAX * 2 * 64];
__device__ float    g_cv[MMAX * 2 * 64];
__device__ float    g_comp[TMAX * 2048];
__device__ unsigned g_sel[TMAX * 2];

// bf16 split operands
__device__ __nv_bfloat16 g_xh[2048 * 2048], g_xl[2048 * 2048];
__device__ __nv_bfloat16 g_fh[2048 * 2048], g_fl[2048 * 2048];
__device__ __nv_bfloat16 g_wqt_h[2048 * 2048], g_wqt_l[2048 * 2048];   // Wq^T [N,K]
__device__ __nv_bfloat16 g_wot_h[2048 * 2048], g_wot_l[2048 * 2048];   // Wo^T
__device__ __nv_bfloat16 g_wkvgt_h[352 * 2048], g_wkvgt_l[352 * 2048]; // [Wk|Wv|Wg]^T
// attention K / V^T split-bf16
__device__ __nv_bfloat16 g_kbh[TMAX * 128], g_kbl[TMAX * 128];          // [n][h][64]
__device__ __nv_bfloat16 g_vth[2 * 64 * TMAX], g_vtl[2 * 64 * TMAX];    // [h][d][n]

__device__ __forceinline__ uint32_t smem_u32(const void* p) {
    uint32_t a;
    asm("{ .reg .u64 t; cvta.to.shared.u64 t, %1; cvt.u32.u64 %0, t; }" : "=r"(a) : "l"(p));
    return a;
}

// ---------------- packed f32x2 helpers ----------------
__device__ __forceinline__ unsigned long long pk2(float x, float y) {
    unsigned long long r;
    asm("mov.b64 %0, {%1,%2};" : "=l"(r) : "f"(x), "f"(y));
    return r;
}
__device__ __forceinline__ unsigned long long pk2f2(float2 v) { return pk2(v.x, v.y); }
__device__ __forceinline__ void upk2(unsigned long long r, float& x, float& y) {
    asm("mov.b64 {%0,%1}, %2;" : "=f"(x), "=f"(y) : "l"(r));
}
__device__ __forceinline__ unsigned long long fma2(unsigned long long a,
                                                   unsigned long long b,
                                                   unsigned long long c) {
    unsigned long long d;
    asm("fma.rn.f32x2 %0, %1, %2, %3;" : "=l"(d) : "l"(a), "l"(b), "l"(c));
    return d;
}

// ---------------- mma helpers ----------------
#define LDSM4(r, addr) \
    asm volatile("ldmatrix.sync.aligned.m8n8.x4.shared.b16 {%0,%1,%2,%3}, [%4];" \
                 : "=r"((r)[0]), "=r"((r)[1]), "=r"((r)[2]), "=r"((r)[3]) : "r"(addr))

__device__ __forceinline__ void hmma(float* c, const uint32_t* a, const uint32_t* b) {
    asm volatile("mma.sync.aligned.m16n8k16.row.col.f32.bf16.bf16.f32 "
                 "{%0,%1,%2,%3},{%4,%5,%6,%7},{%8,%9},{%0,%1,%2,%3};"
                 : "+f"(c[0]), "+f"(c[1]), "+f"(c[2]), "+f"(c[3])
                 : "r"(a[0]), "r"(a[1]), "r"(a[2]), "r"(a[3]), "r"(b[0]), "r"(b[1]));
}

__device__ __forceinline__ void bsplit(float v, unsigned short& hi, unsigned short& lo) {
    __nv_bfloat16 h = __float2bfloat16(v);
    __nv_bfloat16 l = __float2bfloat16(v - __bfloat162float(h));
    hi = *(unsigned short*)&h; lo = *(unsigned short*)&l;
}

// ================= prep kernels =================
__global__ void split_fp32(const float4* __restrict__ A,
                           __nv_bfloat16* __restrict__ Ah,
                           __nv_bfloat16* __restrict__ Al, int total4)
{
    int i = blockIdx.x * 256 + threadIdx.x;
    if (i < total4) {
        float4 v = A[i];
        ushort4 hh, ll;
        bsplit(v.x, hh.x, ll.x); bsplit(v.y, hh.y, ll.y);
        bsplit(v.z, hh.z, ll.z); bsplit(v.w, hh.w, ll.w);
        *(ushort4*)(Ah + 4 * (size_t)i) = hh;
        *(ushort4*)(Al + 4 * (size_t)i) = ll;
    }
}

__global__ void transpose_split(const float* __restrict__ W,
                                __nv_bfloat16* __restrict__ Th,
                                __nv_bfloat16* __restrict__ Tl, int K, int N)
{
    __shared__ float t[32][33];
    const int k0 = blockIdx.y * 32, n0 = blockIdx.x * 32;
    const int tx = threadIdx.x, ty = threadIdx.y;  // 32 x 8
    for (int i = ty; i < 32; i += 8) {
        int k = k0 + i, n = n0 + tx;
        t[i][tx] = (n < N && k < K) ? W[(size_t)k * N + n] : 0.f;
    }
    __syncthreads();
    for (int i = ty; i < 32; i += 8) {
        int n = n0 + i, k = k0 + tx;
        if (n < N && k < K) {
            unsigned short hi, lo;
            bsplit(t[tx][i], hi, lo);
            *(unsigned short*)(Th + (size_t)n * K + k) = hi;
            *(unsigned short*)(Tl + (size_t)n * K + k) = lo;
        }
    }
}

// K split + V transpose-split. grid (n/32, 2, 2), block (32,8)
__global__ void kv_prep(int ntok)
{
    __shared__ float t[32][33];
    const int n0 = blockIdx.x * 32, h = blockIdx.y, dh = blockIdx.z * 32;
    const int tx = threadIdx.x, ty = threadIdx.y;
    for (int i = ty; i < 32; i += 8) {
        const int n = n0 + i, d = dh + tx;
        float kv = g_kvg[n * 352 + h * 64 + d];
        unsigned short hi, lo;
        bsplit(kv, hi, lo);
        *(unsigned short*)(g_kbh + n * 128 + h * 64 + d) = hi;
        *(unsigned short*)(g_kbl + n * 128 + h * 64 + d) = lo;
        t[i][tx] = g_kvg[n * 352 + h * 64 + 128 + d];
    }
    __syncthreads();
    for (int i = ty; i < 32; i += 8) {
        const int d = dh + i, n = n0 + tx;
        unsigned short hi, lo;
        bsplit(t[tx][i], hi, lo);
        *(unsigned short*)(g_vth + (h * 64 + d) * TMAX + n) = hi;
        *(unsigned short*)(g_vtl + (h * 64 + d) * TMAX + n) = lo;
    }
}

// ================= split-bf16 GEMM on mma.sync, 128x128 tile, XOR-swizzled, 3-stage =================
#define SW_MAT 8192
#define SW_STAGE 32768
#define SMEM_SW (3 * SW_STAGE)

__global__ void __launch_bounds__(256, 2) mma_gemm_sw(
    const __nv_bfloat16* __restrict__ Ah, const __nv_bfloat16* __restrict__ Al,
    const __nv_bfloat16* __restrict__ Bth, const __nv_bfloat16* __restrict__ Btl,
    float* __restrict__ C, int M, int N, int K)
{
    extern __shared__ char smem[];
    const uint32_t sb = smem_u32(smem);
    const int tid = threadIdx.x;
    const int lane = tid & 31, wid = tid >> 5;
    const int warp_m = wid & 1, warp_n = wid >> 1;   // 2 x 4 warps
    const int row0 = blockIdx.y * 128, col0 = blockIdx.x * 128;
    const int nchunk = K >> 5;

    float acc[4][4][4];
#pragma unroll
    for (int a = 0; a < 4; a++)
#pragma unroll
        for (int b = 0; b < 4; b++)
#pragma unroll
            for (int c = 0; c < 4; c++) acc[a][b][c] = 0.f;

    const int mt = lane >> 3, rin = lane & 7;
    const int r3 = (rin >> 1) & 3;
    const uint32_t a_row = (uint32_t)((warp_m * 64 + (mt & 1) * 8 + rin) * 64);
    const int a_c0 = mt >> 1;
    const uint32_t a_swk0 = (uint32_t)(((0 + a_c0) ^ r3) * 16);
    const uint32_t a_swk1 = (uint32_t)(((2 + a_c0) ^ r3) * 16);
    const uint32_t b_row = (uint32_t)((warp_n * 32 + ((mt >= 2) ? 8 : 0) + rin) * 64);
    const int b_c0 = mt & 1;
    const uint32_t b_swk0 = (uint32_t)(((0 + b_c0) ^ r3) * 16);
    const uint32_t b_swk1 = (uint32_t)(((2 + b_c0) ^ r3) * 16);

    auto load_chunk = [&](int c, int stage) {
        const int k0 = c * 32;
        const uint32_t st = sb + (uint32_t)stage * SW_STAGE;
#pragma unroll
        for (int i = 0; i < 8; i++) {
            int v = tid + i * 256;
            int mat = v >> 9, idx = v & 511;
            int row = idx >> 2, c16 = idx & 3;
            uint32_t dst = st + mat * SW_MAT + row * 64
                         + (uint32_t)((c16 ^ ((row >> 1) & 3)) * 16);
            const __nv_bfloat16* srcp;
            int sz = 16;
            if (mat < 2) {
                srcp = (mat ? Al : Ah) + (size_t)(row0 + row) * K + k0 + c16 * 8;
            } else {
                int n = col0 + row;
                int nn = (n < N) ? n : 0;
                if (n >= N) sz = 0;
                srcp = (mat == 3 ? Btl : Bth) + (size_t)nn * K + k0 + c16 * 8;
            }
            asm volatile("cp.async.cg.shared.global [%0], [%1], 16, %2;"
                         :: "r"(dst), "l"(srcp), "r"(sz));
        }
        asm volatile("cp.async.commit_group;" ::: "memory");
    };

    int stage = 0;                         // stage of chunk c
    load_chunk(0, 0);
    if (nchunk > 1) load_chunk(1, 1);

    for (int c = 0; c < nchunk; c++) {
        if (c + 2 < nchunk) {
            load_chunk(c + 2, (stage + 2) % 3);
            asm volatile("cp.async.wait_group 2;" ::: "memory");
        } else if (c + 1 < nchunk) {
            asm volatile("cp.async.wait_group 1;" ::: "memory");
        } else {
            asm volatile("cp.async.wait_group 0;" ::: "memory");
        }
        __syncthreads();

        const uint32_t st = sb + (uint32_t)stage * SW_STAGE;
#pragma unroll
        for (int ks = 0; ks < 2; ks++) {
            const uint32_t a_sw = ks ? a_swk1 : a_swk0;
            const uint32_t b_sw = ks ? b_swk1 : b_swk0;
            uint32_t ah[4][4], al[4][4];
#pragma unroll
            for (int mi = 0; mi < 4; mi++) {
                uint32_t addr = st + a_row + mi * (16 * 64) + a_sw;
                LDSM4(ah[mi], addr);
                LDSM4(al[mi], addr + SW_MAT);
            }
#pragma unroll
            for (int b2 = 0; b2 < 2; b2++) {
                uint32_t bh[4], bl[4];
                uint32_t baddr = st + 2 * SW_MAT + b_row + b2 * (16 * 64) + b_sw;
                LDSM4(bh, baddr);
                LDSM4(bl, baddr + SW_MAT);
#pragma unroll
                for (int p = 0; p < 3; p++) {
#pragma unroll
                    for (int mi = 0; mi < 4; mi++) {
#pragma unroll
                        for (int hf = 0; hf < 2; hf++) {
                            const int nt = b2 * 2 + hf;
                            const uint32_t* A_ = (p == 2) ? al[mi] : ah[mi];
                            const uint32_t* B_ = (p == 1) ? bl : bh;
                            hmma(acc[mi][nt], A_, B_ + hf * 2);
                        }
                    }
                }
            }
        }
        __syncthreads();
        stage = (stage + 1) % 3;
    }

    const int g = lane >> 2, c2 = lane & 3;
#pragma unroll
    for (int mi = 0; mi < 4; mi++) {
        const int r = row0 + warp_m * 64 + mi * 16 + g;
#pragma unroll
        for (int nt = 0; nt < 4; nt++) {
            const int col = col0 + warp_n * 32 + nt * 8 + c2 * 2;
            if (col < N) {
                *(float2*)(C + (size_t)r * N + col)       = make_float2(acc[mi][nt][0], acc[mi][nt][1]);
                *(float2*)(C + (size_t)(r + 8) * N + col) = make_float2(acc[mi][nt][2], acc[mi][nt][3]);
            }
        }
    }
}

// ---------------- compressed tokens ----------------
__global__ void compress_kernel(const float* __restrict__ wck,
                                const float* __restrict__ wcv,
                                const float* __restrict__ pe)
{
    const int m = blockIdx.x, h = blockIdx.y, d = threadIdx.x;  // 64 threads
    float a = 0.f, b = 0.f;
    for (int t = 0; t < 64; t++) {
        const float wk = wck[h * 64 + t];
        const float wv = wcv[h * 64 + t];
        const int row = m * 64 + t;
        a = fmaf(g_kvg[row * 352 + h * 64 + d] + pe[(h * 64 + t) * 64 + d], wk, a);
        b = fmaf(g_kvg[row * 352 + 128 + h * 64 + d], wv, b);
    }
    g_ck[(m * 2 + h) * 64 + d] = a;
    g_cv[(m * 2 + h) * 64 + d] = b;
}

// ---------------- compressed attention + top-k, 8 tokens per CTA, dynamic smem ----------------
#define CSMEM (66816)
__global__ void __launch_bounds__(512) comp_attn_kernel(int ntok)
{
    extern __shared__ float csm[];
    float*  sq   = csm;                        // [8][1024] prescaled Q (log2 domain)
    float2* ckp  = (float2*)(csm + 8192);      // [32][33] d-pair ck
    float*  scv  = csm + 8192 + 2112;          // [32][64]
    float*  lg   = scv + 2048;                 // [8][512]
    float*  ssum = lg + 4096;                  // [8][32]

    const int n0 = blockIdx.x * 8, h = blockIdx.y;
    const int tid = threadIdx.x;
    const int tq = tid >> 6, ltid = tid & 63;
    const int M = ntok >> 6;

    for (int i = tid; i < 8192; i += 512) {
        int q = i >> 10;
        sq[i] = g_q[(n0 + q) * 2048 + h * 1024 + (i & 1023)] * QSCALE;
    }
    for (int i = tid; i < M * 32; i += 512) {
        int m = i >> 5, d2 = i & 31;
        ckp[d2 * 33 + m] = *(const float2*)&g_ck[(m * 2 + h) * 64 + 2 * d2];
    }
    for (int i = tid; i < M * 64; i += 512)
        scv[i] = g_cv[((i >> 6) * 2 + h) * 64 + (i & 63)];
    __syncthreads();

    const int n = n0 + tq;
    const int mvis = (n >= 63) ? (((n - 63) >> 6) + 1) : 0;

#pragma unroll
    for (int i = 0; i < 8; i++) {
        int e = ltid + i * 64;
        int g = e >> 5, m = e & 31;
        unsigned long long acc = 0ull;
#pragma unroll
        for (int d2 = 0; d2 < 32; d2++) {
            unsigned long long qp = pk2f2(*(const float2*)&sq[tq * 1024 + g * 64 + 2 * d2]);
            acc = fma2(qp, pk2f2(ckp[d2 * 33 + m]), acc);
        }
        float x, y; upk2(acc, x, y);
        lg[tq * 512 + g * 32 + m] = x + y;
    }
    __syncthreads();

    if (ltid < 16) {
        float* row = lg + tq * 512 + ltid * 32;
        if (mvis == 0) {
            for (int m = 0; m < M; m++) row[m] = 0.f;
        } else {
            float mx = -INFINITY;
            for (int m = 0; m < mvis; m++) mx = fmaxf(mx, row[m]);
            float s = 0.f;
            for (int m = 0; m < mvis; m++) {
                float p = exp2f(row[m] - mx);
                row[m] = p; s += p;
            }
            const float inv = 1.f / s;
            for (int m = 0; m < mvis; m++) row[m] *= inv;
            for (int m = mvis; m < M; m++) row[m] = 0.f;
        }
    }
    __syncthreads();

#pragma unroll
    for (int i = 0; i < 8; i++) {
        int e2 = ltid + i * 64;
        int g = e2 >> 5, d2 = e2 & 31;
        unsigned long long acc = 0ull;
        for (int m = 0; m < mvis; m++) {
            float p = lg[tq * 512 + g * 32 + m];
            acc = fma2(pk2(p, p), pk2f2(*(const float2*)&scv[m * 64 + 2 * d2]), acc);
        }
        float x, y; upk2(acc, x, y);
        *(float2*)&g_comp[n * 2048 + h * 1024 + g * 64 + 2 * d2] = make_float2(x, y);
    }

    if (ltid < 32) {
        float s = 0.f;
        if (ltid < M)
            for (int g = 0; g < 16; g++) s += lg[tq * 512 + g * 32 + ltid];
        ssum[tq * 32 + ltid] = s;
    }
    __syncthreads();

    if (ltid == 0) {
        const int qblk = n >> 6;
        unsigned sel = 0;
        if (qblk + 1 <= 16) {
            sel = (1u << (qblk + 1)) - 1u;
        } else {
            float sc[32];
            for (int m = 0; m < 32; m++) {
                if (m > qblk)                                  sc[m] = -INFINITY;
                else if (m == 0 || m == qblk || m == qblk - 1) sc[m] = INFINITY;
                else                                           sc[m] = ssum[tq * 32 + m];
            }
            for (int t = 0; t < 16; t++) {
                int best = 0; float bv = -INFINITY;
                for (int m = 0; m < 32; m++) {
                    if ((sel >> m) & 1u) continue;
                    if (sc[m] > bv) { bv = sc[m]; best = m; }
                }
                sel |= 1u << best;
            }
        }
        g_sel[n * 2 + h] = sel;
    }
}

// ---------------- main attention on tensor cores (K-prefetch pipelined, shared exp) ----------------
#define BST 72          // bf16 smem row stride (elements) = 144 bytes
#define SQH 0
#define SQL 9216
#define SKH 18432
#define SKL 27648
#define SVTH 36864
#define SVTL 46080
#define PSH 55296
#define PSL 64512
#define PWH 73728
#define PWL 82944
#define LG_OFF 92160    // float [64][66]
#define PM_OFF 109056   // float [512]
#define HMM_OFF 111104  // float [2][64]
#define HLL_OFF 111616
#define HRR_OFF 112128
#define ATTN_SMEM 112640

__global__ void __launch_bounds__(256, 2) main_attn_kernel(int ntok)
{
    extern __shared__ char dsm[];
    const uint32_t sb = smem_u32(dsm);
    float* lg  = (float*)(dsm + LG_OFF);
    float* pm  = (float*)(dsm + PM_OFF);
    float* hmm = (float*)(dsm + HMM_OFF);
    float* hll = (float*)(dsm + HLL_OFF);
    float* hrr = (float*)(dsm + HRR_OFF);

    // reversed CTA order: heaviest first for tail packing
    const int n0 = (gridDim.x - 1 - blockIdx.x) * 4, h = blockIdx.y;
    const int tid = threadIdx.x;
    const int lane = tid & 31, wid = tid >> 5;
    const int warp_m = wid & 1, warp_n = wid >> 1;
    const int g = lane >> 2, cq = lane & 3;

    const unsigned sel0 = g_sel[n0 * 2 + h],       sel1 = g_sel[(n0 + 1) * 2 + h],
                   sel2 = g_sel[(n0 + 2) * 2 + h], sel3 = g_sel[(n0 + 3) * 2 + h];
    const unsigned selU = sel0 | sel1 | sel2 | sel3;
    const int qblk = n0 >> 6;

    auto active = [&](int c) -> bool {
        return ((selU >> c) & 1u) || ((n0 - c * 64 - 512) <= 63);
    };

    auto loadK = [&](int c) {
#pragma unroll
        for (int i2 = 0; i2 < 4; i2++) {
            int i = tid + i2 * 256;
            int mat = i >> 9, idx = i & 511;
            int row = idx >> 3, c16 = idx & 7;
            const __nv_bfloat16* src = (mat == 0 ? g_kbh : g_kbl)
                                     + (size_t)(c * 64 + row) * 128 + h * 64 + c16 * 8;
            uint32_t dst = sb + SKH + (uint32_t)(mat * 9216 + row * 144 + c16 * 16);
            asm volatile("cp.async.cg.shared.global [%0], [%1], 16;" :: "r"(dst), "l"(src));
        }
        asm volatile("cp.async.commit_group;" ::: "memory");
    };
    auto loadV = [&](int c) {
#pragma unroll
        for (int i2 = 0; i2 < 4; i2++) {
            int i = tid + i2 * 256;
            int mat = i >> 9, idx = i & 511;
            int row = idx >> 3, c16 = idx & 7;
            const __nv_bfloat16* src = (mat == 0 ? g_vth : g_vtl)
                                     + (size_t)(h * 64 + row) * TMAX + c * 64 + c16 * 8;
            uint32_t dst = sb + SVTH + (uint32_t)(mat * 9216 + row * 144 + c16 * 16);
            asm volatile("cp.async.cg.shared.global [%0], [%1], 16;" :: "r"(dst), "l"(src));
        }
        asm volatile("cp.async.commit_group;" ::: "memory");
    };

    int c0 = 0;
    while (c0 <= qblk && !active(c0)) c0++;
    loadK(c0);
    loadV(c0);

    for (int i = tid; i < 4096; i += 256) {
        int r = i >> 6, d = i & 63;
        float v = g_q[(n0 + (r >> 4)) * 2048 + h * 1024 + (r & 15) * 64 + d] * QSCALE;
        unsigned short hi, lo;
        bsplit(v, hi, lo);
        *(unsigned short*)(dsm + SQH + (r * BST + d) * 2) = hi;
        *(unsigned short*)(dsm + SQL + (r * BST + d) * 2) = lo;
    }
    if (tid < 128) { hmm[tid] = -INFINITY; hll[tid] = 0.f; }

    const int mt = lane >> 3, rin = lane & 7;
    const uint32_t a_base = (uint32_t)(((mt & 1) * 8 + rin) * 144 + ((mt >> 1) * 8) * 2);
    const uint32_t b_base = (uint32_t)((warp_n * 16 + ((mt >= 2) ? 8 : 0) + rin) * 144 + ((mt & 1) * 8) * 2);

    float acc_s[2][2][4] = {}, acc_w[2][2][4] = {};

    for (int c = c0; c <= qblk;) {
        int cn = c + 1;
        while (cn <= qblk && !active(cn)) cn++;

        const int base = n0 - c * 64;
        const bool wact = (base - 512) <= 63;
        const bool sact = (selU >> c) & 1u;

        asm volatile("cp.async.wait_group 0;" ::: "memory");
        __syncthreads();

        // ---- S = Q K^T via HMMA (3-product) ----
        {
            float acc[2][2][4] = {};
#pragma unroll
            for (int ks = 0; ks < 4; ks++) {
                uint32_t kh[4], kl[4];
                LDSM4(kh, sb + SKH + b_base + ks * 32);
                LDSM4(kl, sb + SKL + b_base + ks * 32);
#pragma unroll
                for (int mi = 0; mi < 2; mi++) {
                    uint32_t qh[4], ql[4];
                    const uint32_t ao = (uint32_t)((warp_m * 32 + mi * 16) * 144) + a_base + ks * 32;
                    LDSM4(qh, sb + SQH + ao);
                    LDSM4(ql, sb + SQL + ao);
#pragma unroll
                    for (int hf = 0; hf < 2; hf++) {
                        hmma(acc[mi][hf], qh, kh + hf * 2);
                        hmma(acc[mi][hf], qh, kl + hf * 2);
                        hmma(acc[mi][hf], ql, kh + hf * 2);
                    }
                }
            }
#pragma unroll
            for (int mi = 0; mi < 2; mi++) {
                const int r0 = warp_m * 32 + mi * 16 + g;
#pragma unroll
                for (int hf = 0; hf < 2; hf++) {
                    const int col = warp_n * 16 + hf * 8 + cq * 2;
                    *(float2*)&lg[r0 * 66 + col]       = make_float2(acc[mi][hf][0], acc[mi][hf][1]);
                    *(float2*)&lg[(r0 + 8) * 66 + col] = make_float2(acc[mi][hf][2], acc[mi][hf][3]);
                }
            }
        }
        __syncthreads();

        if (cn <= qblk) loadK(cn);

        // ---- segmented max (branch-guarded) ----
        {
            const int r = tid >> 2, seg = tid & 3;
            const int q = r >> 4;
            const int jn = min(63, base + q);
            if (sact) {
                const unsigned selq = (q == 0) ? sel0 : (q == 1) ? sel1 : (q == 2) ? sel2 : sel3;
                float ms = -INFINITY;
                if ((selq >> c) & 1u) {
                    const int hi2 = min(seg * 16 + 15, jn);
                    for (int j = seg * 16; j <= hi2; j++) ms = fmaxf(ms, lg[r * 66 + j]);
                }
                pm[tid] = ms;
            }
            if (wact) {
                const int jw0 = base + q - 512;
                float mw = -INFINITY;
                if (jw0 <= 63) {
                    const int lo2 = max(seg * 16, jw0);
                    const int hi2 = min(seg * 16 + 15, jn);
                    for (int j = lo2; j <= hi2; j++) mw = fmaxf(mw, lg[r * 66 + j]);
                }
                pm[256 + tid] = mw;
            }
        }
        __syncthreads();
        if (tid < 128) {
            const int br = tid >> 6, r = tid & 63;
            const bool act = br ? wact : sact;
            if (act) {
                const float* p = pm + br * 256 + r * 4;
                const float cm = fmaxf(fmaxf(p[0], p[1]), fmaxf(p[2], p[3]));
                const float om = hmm[br * 64 + r];
                const float nm = fmaxf(om, cm);
                hmm[br * 64 + r] = nm;
                hrr[br * 64 + r] = (cm == -INFINITY) ? 1.f : exp2f(om - nm);
            } else {
                hrr[br * 64 + r] = 1.f;
            }
        }
        __syncthreads();

        // ---- exp (shared across branches) + partial sums + split-bf16 P store ----
        {
            const int r = tid >> 2, seg = tid & 3;
            const int q = r >> 4;
            const int jn = base + q;
            const int jw0 = base + q - 512;
            const uint32_t po = (uint32_t)((r * BST + seg * 16) * 2);
            const unsigned selq = (q == 0) ? sel0 : (q == 1) ? sel1 : (q == 2) ? sel2 : sel3;
            const bool srow = sact && ((selq >> c) & 1u);
            const bool wrow = wact && (jw0 <= 63);
            const float ms = hmm[r], mw = hmm[64 + r];

            float ev[16];
            if (sact) {
                float ss = 0.f;
                unsigned short eh[16], el[16];
                if (srow) {
#pragma unroll
                    for (int jj = 0; jj < 16; jj++) {
                        const int j = seg * 16 + jj;
                        float e = (j <= jn) ? exp2f(lg[r * 66 + j] - ms) : 0.f;
                        ev[jj] = e;
                        ss += e;
                        bsplit(e, eh[jj], el[jj]);
                    }
                } else {
#pragma unroll
                    for (int jj = 0; jj < 16; jj++) { ev[jj] = 0.f; eh[jj] = 0; el[jj] = 0; }
                }
                pm[tid] = ss;
#pragma unroll
                for (int v4 = 0; v4 < 4; v4++) {
                    *(ushort4*)(dsm + PSH + po + v4 * 8) = make_ushort4(eh[v4*4], eh[v4*4+1], eh[v4*4+2], eh[v4*4+3]);
                    *(ushort4*)(dsm + PSL + po + v4 * 8) = make_ushort4(el[v4*4], el[v4*4+1], el[v4*4+2], el[v4*4+3]);
                }
            }
            if (wact) {
                float sw = 0.f;
                unsigned short wh[16], wl[16];
                if (wrow) {
                    if (srow) {
                        const float sc = exp2f(ms - mw);
#pragma unroll
                        for (int jj = 0; jj < 16; jj++) {
                            const int j = seg * 16 + jj;
                            float ew = (j >= jw0) ? ev[jj] * sc : 0.f;
                            sw += ew;
                            bsplit(ew, wh[jj], wl[jj]);
                        }
                    } else {
#pragma unroll
                        for (int jj = 0; jj < 16; jj++) {
                            const int j = seg * 16 + jj;
                            float ew = (j <= jn && j >= jw0) ? exp2f(lg[r * 66 + j] - mw) : 0.f;
                            sw += ew;
                            bsplit(ew, wh[jj], wl[jj]);
                        }
                    }
                } else {
#pragma unroll
                    for (int jj = 0; jj < 16; jj++) { wh[jj] = 0; wl[jj] = 0; }
                }
                pm[256 + tid] = sw;
#pragma unroll
                for (int v4 = 0; v4 < 4; v4++) {
                    *(ushort4*)(dsm + PWH + po + v4 * 8) = make_ushort4(wh[v4*4], wh[v4*4+1], wh[v4*4+2], wh[v4*4+3]);
                    *(ushort4*)(dsm + PWL + po + v4 * 8) = make_ushort4(wl[v4*4], wl[v4*4+1], wl[v4*4+2], wl[v4*4+3]);
                }
            }
        }
        __syncthreads();
        if (tid < 128) {
            const int br = tid >> 6, r = tid & 63;
            const bool act = br ? wact : sact;
            if (act) {
                const float* p = pm + br * 256 + r * 4;
                hll[br * 64 + r] = hll[br * 64 + r] * hrr[br * 64 + r]
                                 + (p[0] + p[1]) + (p[2] + p[3]);
            }
        }

        // ---- PV via HMMA with flash rescale (branch-guarded) ----
        if (sact) {
#pragma unroll
            for (int mi = 0; mi < 2; mi++) {
                const int rb = warp_m * 32 + mi * 16 + g;
                const float rs0 = hrr[rb], rs1 = hrr[rb + 8];
#pragma unroll
                for (int hf = 0; hf < 2; hf++) {
                    acc_s[mi][hf][0] *= rs0; acc_s[mi][hf][1] *= rs0;
                    acc_s[mi][hf][2] *= rs1; acc_s[mi][hf][3] *= rs1;
                }
            }
        }
        if (wact) {
#pragma unroll
            for (int mi = 0; mi < 2; mi++) {
                const int rb = warp_m * 32 + mi * 16 + g;
                const float rw0 = hrr[64 + rb], rw1 = hrr[64 + rb + 8];
#pragma unroll
                for (int hf = 0; hf < 2; hf++) {
                    acc_w[mi][hf][0] *= rw0; acc_w[mi][hf][1] *= rw0;
                    acc_w[mi][hf][2] *= rw1; acc_w[mi][hf][3] *= rw1;
                }
            }
        }
#pragma unroll
        for (int ks = 0; ks < 4; ks++) {
            uint32_t vh[4], vl[4];
            LDSM4(vh, sb + SVTH + b_base + ks * 32);
            LDSM4(vl, sb + SVTL + b_base + ks * 32);
#pragma unroll
            for (int mi = 0; mi < 2; mi++) {
                const uint32_t ao = (uint32_t)((warp_m * 32 + mi * 16) * 144) + a_base + ks * 32;
                if (sact) {
                    uint32_t ph[4], pl[4];
                    LDSM4(ph, sb + PSH + ao);
                    LDSM4(pl, sb + PSL + ao);
#pragma unroll
                    for (int hf = 0; hf < 2; hf++) {
                        hmma(acc_s[mi][hf], ph, vh + hf * 2);
                        hmma(acc_s[mi][hf], ph, vl + hf * 2);
                        hmma(acc_s[mi][hf], pl, vh + hf * 2);
                    }
                }
                if (wact) {
                    uint32_t ph[4], pl[4];
                    LDSM4(ph, sb + PWH + ao);
                    LDSM4(pl, sb + PWL + ao);
#pragma unroll
                    for (int hf = 0; hf < 2; hf++) {
                        hmma(acc_w[mi][hf], ph, vh + hf * 2);
                        hmma(acc_w[mi][hf], ph, vl + hf * 2);
                        hmma(acc_w[mi][hf], pl, vh + hf * 2);
                    }
                }
            }
        }
        __syncthreads();
        if (cn <= qblk) loadV(cn);
        c = cn;
    }

    // ---- gated fusion epilogue ----
#pragma unroll
    for (int mi = 0; mi < 2; mi++) {
#pragma unroll
        for (int half = 0; half < 2; half++) {
            const int r = warp_m * 32 + mi * 16 + g + half * 8;
            const int nq = n0 + (r >> 4);
            const int head = r & 15;
            const int hq = h * 16 + head;
            const float gl0 = g_kvg[nq * 352 + 256 + hq * 3 + 0];
            const float gl1 = g_kvg[nq * 352 + 256 + hq * 3 + 1];
            const float gl2 = g_kvg[nq * 352 + 256 + hq * 3 + 2];
            const float g0 = 1.f / (1.f + __expf(-gl0));
            const float g1 = 1.f / (1.f + __expf(-gl1));
            const float g2 = 1.f / (1.f + __expf(-gl2));
            const float inv_s = 1.f / hll[r];
            const float inv_w = 1.f / hll[64 + r];
#pragma unroll
            for (int hf = 0; hf < 2; hf++) {
                const int col = warp_n * 16 + hf * 8 + cq * 2;
                const int oi = nq * 2048 + h * 1024 + head * 64 + col;
                const float2 cmp = *(const float2*)&g_comp[oi];
                const float o0 = g0 * cmp.x + g1 * acc_s[mi][hf][half * 2]     * inv_s
                                            + g2 * acc_w[mi][hf][half * 2]     * inv_w;
                const float o1 = g0 * cmp.y + g1 * acc_s[mi][hf][half * 2 + 1] * inv_s
                                            + g2 * acc_w[mi][hf][half * 2 + 1] * inv_w;
                ushort2 hh, ll;
                bsplit(o0, hh.x, ll.x);
                bsplit(o1, hh.y, ll.y);
                *(ushort2*)(g_fh + oi) = hh;
                *(ushort2*)(g_fl + oi) = ll;
            }
        }
    }
}

// ---------------- launch ----------------
extern "C" void kernel_launch(void* const* d_in, const int* in_sizes, int n_in,
                              void* d_out, int out_size)
{
    const float* x   = (const float*)d_in[0];
    const float* Wq  = (const float*)d_in[2];
    const float* Wk  = (const float*)d_in[3];
    const float* Wv  = (const float*)d_in[4];
    const float* Wo  = (const float*)d_in[5];
    const float* Wg  = (const float*)d_in[6];
    const float* wck = (const float*)d_in[7];
    const float* wcv = (const float*)d_in[8];
    const float* pe  = (const float*)d_in[9];
    float* out = (float*)d_out;

    const int ntok = in_sizes[0] / 2048;     // T = 2048
    const int M = ntok / 64;

    float *q, *kvg;
    cudaGetSymbolAddress((void**)&q,   g_q);
    cudaGetSymbolAddress((void**)&kvg, g_kvg);

    __nv_bfloat16 *xh, *xl, *fh, *fl, *wqh, *wql, *woh, *wol, *wkvgh, *wkvgl;
    cudaGetSymbolAddress((void**)&xh, g_xh);     cudaGetSymbolAddress((void**)&xl, g_xl);
    cudaGetSymbolAddress((void**)&fh, g_fh);     cudaGetSymbolAddress((void**)&fl, g_fl);
    cudaGetSymbolAddress((void**)&wqh, g_wqt_h); cudaGetSymbolAddress((void**)&wql, g_wqt_l);
    cudaGetSymbolAddress((void**)&woh, g_wot_h); cudaGetSymbolAddress((void**)&wol, g_wot_l);
    cudaGetSymbolAddress((void**)&wkvgh, g_wkvgt_h);
    cudaGetSymbolAddress((void**)&wkvgl, g_wkvgt_l);

    cudaFuncSetAttribute(mma_gemm_sw, cudaFuncAttributeMaxDynamicSharedMemorySize, SMEM_SW);
    cudaFuncSetAttribute(main_attn_kernel, cudaFuncAttributeMaxDynamicSharedMemorySize, ATTN_SMEM);
    cudaFuncSetAttribute(comp_attn_kernel, cudaFuncAttributeMaxDynamicSharedMemorySize, CSMEM);

    const int tot = ntok * 2048;
    dim3 tb(32, 8);

    split_fp32<<<(tot / 4 + 255) / 256, 256>>>((const float4*)x, xh, xl, tot / 4);                // 0
    transpose_split<<<dim3(64, 64), tb>>>(Wq, wqh, wql, 2048, 2048);                              // 1
    transpose_split<<<dim3(4,  64), tb>>>(Wk, wkvgh,              wkvgl,              2048, 128); // 2
    mma_gemm_sw<<<dim3(16, ntok / 128), 256, SMEM_SW>>>(xh, xl, wqh, wql, q, ntok, 2048, 2048);   // 3 <- ncu
    transpose_split<<<dim3(4,  64), tb>>>(Wv, wkvgh + 128 * 2048, wkvgl + 128 * 2048, 2048, 128); // 4
    transpose_split<<<dim3(3,  64), tb>>>(Wg, wkvgh + 256 * 2048, wkvgl + 256 * 2048, 2048, 96);  // 5
    mma_gemm_sw<<<dim3(3, ntok / 128), 256, SMEM_SW>>>(xh, xl, wkvgh, wkvgl, kvg, ntok, 352, 2048);

    kv_prep<<<dim3(ntok / 32, 2, 2), tb>>>(ntok);
    compress_kernel<<<dim3(M, 2), 64>>>(wck, wcv, pe);
    comp_attn_kernel<<<dim3(ntok / 8, 2), 512, CSMEM>>>(ntok);
    main_attn_kernel<<<dim3(ntok / 4, 2), 256, ATTN_SMEM>>>(ntok);

    transpose_split<<<dim3(64, 64), tb>>>(Wo, woh, wol, 2048, 2048);
    mma_gemm_sw<<<dim3(16, ntok / 128), 256, SMEM_SW>>>(fh, fl, woh, wol, out, ntok, 2048, 2048);
}